// round 10
// baseline (speedup 1.0000x reference)
#include <cuda_runtime.h>
#include <cstdint>

// Problem constants
#define BH   24
#define SEQ  4096
#define DD   128
#define FF   256
#define CHK  128
#define NC   32
#define ROWS (BH*SEQ)      // 98304
#define FD   (FF*DD)       // 32768
#define NBLK (ROWS/128)    // 768

// ---------------- scratch (device globals; no runtime allocation) ----------
__device__ float g_hq  [(size_t)ROWS * FF];
__device__ float g_hk  [(size_t)ROWS * FF];
__device__ float g_qphi[(size_t)ROWS * FF];
__device__ float g_kphi[(size_t)ROWS * FF];
__device__ float g_P   [(size_t)BH * (NC+1) * FD];   // TRANSPOSED slabs: [d][f]
__device__ float g_w1t [FF * DD];
__device__ float g_w2t [FF * FF];

#define GP  36
#define GPT 37
#define AP  132
#define VP  133
#define HP  260

__device__ __forceinline__ uint32_t f2tf32(float x) {
    uint32_t r; asm("cvt.rna.tf32.f32 %0, %1;" : "=r"(r) : "f"(x)); return r;
}
__device__ __forceinline__ void mma8(float* c, const uint32_t* a, const uint32_t* b) {
    asm volatile(
        "mma.sync.aligned.m16n8k8.row.col.f32.tf32.tf32.f32 "
        "{%0,%1,%2,%3}, {%4,%5,%6,%7}, {%8,%9}, {%0,%1,%2,%3};"
        : "+f"(c[0]), "+f"(c[1]), "+f"(c[2]), "+f"(c[3])
        : "r"(a[0]), "r"(a[1]), "r"(a[2]), "r"(a[3]), "r"(b[0]), "r"(b[1]));
}

// ---------------------------------------------------------------------------
// phiA: h = silu(X @ w1t^T + b1).  Grid 2*NBLK, 512 threads (16 warps, 4x4).
// Warp tile 32x32 (mt=2, nt=4); w1t fully resident; one sync.
// ---------------------------------------------------------------------------
#define PA_XS    0
#define PA_WS    (128*AP)
#define PA_BYTES ((128*AP + 256*AP) * 4)    // 202752

__global__ __launch_bounds__(512, 1) void phiA(
    const float* __restrict__ Xq, const float* __restrict__ Xk,
    const float* __restrict__ w1t, const float* __restrict__ b1,
    float* __restrict__ Hq, float* __restrict__ Hk)
{
    extern __shared__ uint32_t smx[];
    uint32_t* Xs = smx + PA_XS;
    uint32_t* Ws = smx + PA_WS;

    const int t    = threadIdx.x;
    const int lane = t & 31;
    const int wid  = t >> 5;
    const int wm   = wid >> 2;        // 0..3
    const int wn   = wid & 3;         // 0..3
    const int g    = lane >> 2;
    const int tig  = lane & 3;
    const int bx   = blockIdx.x;
    const bool isK = (bx >= NBLK);
    const int row0 = (isK ? bx - NBLK : bx) * 128;
    const float* X = isK ? Xk : Xq;
    float* H       = isK ? Hk : Hq;

    // stage X tile [128][128]: 4096 f4 slots
#pragma unroll
    for (int r = 0; r < 8; r++) {
        int slot = t + r * 512;
        int row  = slot >> 5;
        int c4   = (slot & 31) << 2;
        float4 v = *(const float4*)(X + (size_t)(row0 + row) * DD + c4);
        uint32_t* p = &Xs[row * AP + c4];
        p[0] = f2tf32(v.x); p[1] = f2tf32(v.y);
        p[2] = f2tf32(v.z); p[3] = f2tf32(v.w);
    }
    // stage w1t [256][128]: 8192 slots
#pragma unroll
    for (int r = 0; r < 16; r++) {
        int slot = t + r * 512;
        int row  = slot >> 5;
        int c4   = (slot & 31) << 2;
        float4 v = *(const float4*)(w1t + (size_t)row * DD + c4);
        uint32_t* p = &Ws[row * AP + c4];
        p[0] = f2tf32(v.x); p[1] = f2tf32(v.y);
        p[2] = f2tf32(v.z); p[3] = f2tf32(v.w);
    }
    __syncthreads();

#pragma unroll
    for (int np = 0; np < 2; np++) {
        float acc[2][4][4];
#pragma unroll
        for (int mt = 0; mt < 2; mt++)
#pragma unroll
            for (int nt = 0; nt < 4; nt++)
#pragma unroll
                for (int e = 0; e < 4; e++) acc[mt][nt][e] = 0.f;

#pragma unroll
        for (int ks = 0; ks < 16; ks++) {
            int kc = ks * 8 + tig;
            uint32_t af[2][4];
#pragma unroll
            for (int mt = 0; mt < 2; mt++) {
                int base = (wm * 32 + mt * 16 + g) * AP + kc;
                af[mt][0] = Xs[base];
                af[mt][1] = Xs[base + 8 * AP];
                af[mt][2] = Xs[base + 4];
                af[mt][3] = Xs[base + 8 * AP + 4];
            }
            uint32_t bf[4][2];
#pragma unroll
            for (int nt = 0; nt < 4; nt++) {
                int base = (np * 128 + wn * 32 + nt * 8 + g) * AP + kc;
                bf[nt][0] = Ws[base];
                bf[nt][1] = Ws[base + 4];
            }
#pragma unroll
            for (int mt = 0; mt < 2; mt++)
#pragma unroll
                for (int nt = 0; nt < 4; nt++)
                    mma8(acc[mt][nt], af[mt], bf[nt]);
        }
#pragma unroll
        for (int mt = 0; mt < 2; mt++) {
#pragma unroll
            for (int nt = 0; nt < 4; nt++) {
                int row = row0 + wm * 32 + mt * 16 + g;
                int col = np * 128 + wn * 32 + nt * 8 + tig * 2;
                float b0v = b1[col], b1v = b1[col + 1];
                float x0 = acc[mt][nt][0] + b0v;
                float x1 = acc[mt][nt][1] + b1v;
                float x2 = acc[mt][nt][2] + b0v;
                float x3 = acc[mt][nt][3] + b1v;
                x0 = x0 / (1.f + __expf(-x0));
                x1 = x1 / (1.f + __expf(-x1));
                x2 = x2 / (1.f + __expf(-x2));
                x3 = x3 / (1.f + __expf(-x3));
                float2 o01, o23;
                o01.x = x0; o01.y = x1;
                o23.x = x2; o23.y = x3;
                *(float2*)(H + (size_t)row * FF + col)       = o01;
                *(float2*)(H + (size_t)(row + 8) * FF + col) = o23;
            }
        }
    }
}

// ---------------------------------------------------------------------------
// phiB: phi = h @ w2t^T + b2.  Grid 2*NBLK, 512 threads.
// h tile (128x256) resident; w2t in 64-row slices; warp tile 32x16 (mt=2,nt=2).
// ---------------------------------------------------------------------------
#define PB_HS    0
#define PB_WS    (128*HP)
#define PB_BYTES ((128*HP + 64*HP) * 4)     // 199680

__global__ __launch_bounds__(512, 1) void phiB(
    const float* __restrict__ Hq, const float* __restrict__ Hk,
    const float* __restrict__ w2t, const float* __restrict__ b2,
    float* __restrict__ Cq, float* __restrict__ Ck)
{
    extern __shared__ uint32_t smx[];
    uint32_t* Hs = smx + PB_HS;
    uint32_t* Ws = smx + PB_WS;

    const int t    = threadIdx.x;
    const int lane = t & 31;
    const int wid  = t >> 5;
    const int wm   = wid >> 2;
    const int wn   = wid & 3;
    const int g    = lane >> 2;
    const int tig  = lane & 3;
    const int bx   = blockIdx.x;
    const bool isK = (bx >= NBLK);
    const int row0 = (isK ? bx - NBLK : bx) * 128;
    const float* H = isK ? Hk : Hq;
    float* C       = isK ? Ck : Cq;

    // stage h tile [128][256]: 8192 f4 slots
#pragma unroll
    for (int r = 0; r < 16; r++) {
        int slot = t + r * 512;
        int row  = slot >> 6;
        int c4   = (slot & 63) << 2;
        float4 v = *(const float4*)(H + (size_t)(row0 + row) * FF + c4);
        uint32_t* p = &Hs[row * HP + c4];
        p[0] = f2tf32(v.x); p[1] = f2tf32(v.y);
        p[2] = f2tf32(v.z); p[3] = f2tf32(v.w);
    }

#pragma unroll
    for (int np = 0; np < 4; np++) {
        __syncthreads();
        // stage w2t slice [64][256]: 4096 slots
#pragma unroll
        for (int r = 0; r < 8; r++) {
            int slot = t + r * 512;
            int row  = slot >> 6;
            int c4   = (slot & 63) << 2;
            float4 v = *(const float4*)(w2t + (size_t)(np * 64 + row) * FF + c4);
            uint32_t* p = &Ws[row * HP + c4];
            p[0] = f2tf32(v.x); p[1] = f2tf32(v.y);
            p[2] = f2tf32(v.z); p[3] = f2tf32(v.w);
        }
        __syncthreads();

        float acc[2][2][4];
#pragma unroll
        for (int mt = 0; mt < 2; mt++)
#pragma unroll
            for (int nt = 0; nt < 2; nt++)
#pragma unroll
                for (int e = 0; e < 4; e++) acc[mt][nt][e] = 0.f;

#pragma unroll
        for (int ks = 0; ks < 32; ks++) {
            int kc = ks * 8 + tig;
            uint32_t af[2][4];
#pragma unroll
            for (int mt = 0; mt < 2; mt++) {
                int base = (wm * 32 + mt * 16 + g) * HP + kc;
                af[mt][0] = Hs[base];
                af[mt][1] = Hs[base + 8 * HP];
                af[mt][2] = Hs[base + 4];
                af[mt][3] = Hs[base + 8 * HP + 4];
            }
            uint32_t bf[2][2];
#pragma unroll
            for (int nt = 0; nt < 2; nt++) {
                int base = (wn * 16 + nt * 8 + g) * HP + kc;
                bf[nt][0] = Ws[base];
                bf[nt][1] = Ws[base + 4];
            }
#pragma unroll
            for (int mt = 0; mt < 2; mt++)
#pragma unroll
                for (int nt = 0; nt < 2; nt++)
                    mma8(acc[mt][nt], af[mt], bf[nt]);
        }
#pragma unroll
        for (int mt = 0; mt < 2; mt++) {
#pragma unroll
            for (int nt = 0; nt < 2; nt++) {
                int row = row0 + wm * 32 + mt * 16 + g;
                int col = np * 64 + wn * 16 + nt * 8 + tig * 2;
                float b0v = b2[col], b1v = b2[col + 1];
                float2 o01, o23;
                o01.x = acc[mt][nt][0] + b0v;
                o01.y = acc[mt][nt][1] + b1v;
                o23.x = acc[mt][nt][2] + b0v;
                o23.y = acc[mt][nt][3] + b1v;
                *(float2*)(C + (size_t)row * FF + col)       = o01;
                *(float2*)(C + (size_t)(row + 8) * FF + col) = o23;
            }
        }
    }
}

// ---------------------------------------------------------------------------
// Transpose W [K,N] -> Wt [N,K]
// ---------------------------------------------------------------------------
__global__ void transpose_kernel(const float* __restrict__ W,
                                 float* __restrict__ Wt, int K, int N)
{
    int idx = blockIdx.x * blockDim.x + threadIdx.x;
    if (idx >= K * N) return;
    int kk = idx / N;
    int n  = idx - kk * N;
    Wt[(size_t)n * K + kk] = W[idx];
}

// ---------------------------------------------------------------------------
// chunk_state (tensor cores, 512 thr): S^T[d][f] = sum_m V[m][d]*Kphi[m][f]
// ---------------------------------------------------------------------------
__global__ __launch_bounds__(512, 1) void chunk_state_tc(
    const float* __restrict__ kphi, const float* __restrict__ vin,
    float* __restrict__ P)
{
    __shared__ uint32_t At[128 * GPT];
    __shared__ uint32_t Bt[128 * GPT];

    const int t    = threadIdx.x;
    const int lane = t & 31;
    const int wid  = t >> 5;
    const int wm   = wid >> 2;
    const int wn   = wid & 3;
    const int g    = lane >> 2;
    const int tig  = lane & 3;
    const int hc   = blockIdx.x;
    const int h    = hc >> 5;
    const int c    = hc & 31;
    const int f0   = blockIdx.y * 128;
    const int pos0 = h * SEQ + c * CHK;

    float acc[2][4][4];
#pragma unroll
    for (int mt = 0; mt < 2; mt++)
#pragma unroll
        for (int nt = 0; nt < 4; nt++)
#pragma unroll
            for (int e = 0; e < 4; e++) acc[mt][nt][e] = 0.f;

    for (int m0 = 0; m0 < CHK; m0 += 32) {
#pragma unroll
        for (int r = 0; r < 2; r++) {
            int slot = t + r * 512;
            int m    = slot >> 5;
            int x4   = (slot & 31) << 2;
            float4 vv = *(const float4*)(vin + (size_t)(pos0 + m0 + m) * DD + x4);
            At[(x4+0)*GPT + m] = f2tf32(vv.x);
            At[(x4+1)*GPT + m] = f2tf32(vv.y);
            At[(x4+2)*GPT + m] = f2tf32(vv.z);
            At[(x4+3)*GPT + m] = f2tf32(vv.w);
            float4 kk = *(const float4*)(kphi + (size_t)(pos0 + m0 + m) * FF + f0 + x4);
            Bt[(x4+0)*GPT + m] = f2tf32(kk.x);
            Bt[(x4+1)*GPT + m] = f2tf32(kk.y);
            Bt[(x4+2)*GPT + m] = f2tf32(kk.z);
            Bt[(x4+3)*GPT + m] = f2tf32(kk.w);
        }
        __syncthreads();
#pragma unroll
        for (int ks = 0; ks < 4; ks++) {
            int kc = ks * 8 + tig;
            uint32_t af[2][4];
#pragma unroll
            for (int mt = 0; mt < 2; mt++) {
                int base = (wm * 32 + mt * 16 + g) * GPT + kc;
                af[mt][0] = At[base];
                af[mt][1] = At[base + 8 * GPT];
                af[mt][2] = At[base + 4];
                af[mt][3] = At[base + 8 * GPT + 4];
            }
            uint32_t bf[4][2];
#pragma unroll
            for (int nt = 0; nt < 4; nt++) {
                int base = (wn * 32 + nt * 8 + g) * GPT + kc;
                bf[nt][0] = Bt[base];
                bf[nt][1] = Bt[base + 4];
            }
#pragma unroll
            for (int mt = 0; mt < 2; mt++)
#pragma unroll
                for (int nt = 0; nt < 4; nt++)
                    mma8(acc[mt][nt], af[mt], bf[nt]);
        }
        __syncthreads();
    }

    float* S = P + ((size_t)(h * (NC + 1)) + (c + 1)) * FD;
#pragma unroll
    for (int mt = 0; mt < 2; mt++) {
#pragma unroll
        for (int nt = 0; nt < 4; nt++) {
            int d   = wm * 32 + mt * 16 + g;
            int col = f0 + wn * 32 + nt * 8 + tig * 2;
            float2 o01; o01.x = acc[mt][nt][0]; o01.y = acc[mt][nt][1];
            float2 o23; o23.x = acc[mt][nt][2]; o23.y = acc[mt][nt][3];
            *(float2*)(S + (size_t)d * FF + col)       = o01;
            *(float2*)(S + (size_t)(d + 8) * FF + col) = o23;
        }
    }
}

// ---------------------------------------------------------------------------
// Inclusive prefix over chunk slabs.
// ---------------------------------------------------------------------------
__global__ void prefix_kernel(float* __restrict__ P)
{
    const int h = blockIdx.y;
    const int e = blockIdx.x * 256 + threadIdx.x;
    float* base = P + (size_t)h * (NC + 1) * FD;
    base[e] = 0.f;
    float acc = 0.f;
#pragma unroll
    for (int c = 1; c <= NC; c++) {
        acc += base[(size_t)c * FD + e];
        base[(size_t)c * FD + e] = acc;
    }
}

// ---------------------------------------------------------------------------
// output_tc (512 thr): per (head, chunk) block; warp tile 32x32 (mt=2,nt=4).
// ---------------------------------------------------------------------------
#define OSM_BYTES ((128*AP + 128*VP) * 4)   // 135680

__global__ __launch_bounds__(512, 1) void output_tc(
    const float* __restrict__ qphi, const float* __restrict__ kphi,
    const float* __restrict__ vin,  const float* __restrict__ P,
    float* __restrict__ out)
{
    extern __shared__ uint32_t smx[];
    uint32_t* Abuf = smx;
    uint32_t* Vt   = smx + 128 * AP;
    uint32_t* S1Q  = Vt;
    uint32_t* S1K  = Vt + 128 * GP;
    uint32_t* S3Q  = Abuf;
    uint32_t* S3B1 = Abuf + 128 * GP;
    uint32_t* S3B2 = Abuf + 2 * 128 * GP;

    const int t    = threadIdx.x;
    const int lane = t & 31;
    const int wid  = t >> 5;
    const int wm   = wid >> 2;
    const int wn   = wid & 3;
    const int g    = lane >> 2;
    const int tig  = lane & 3;
    const int hc   = blockIdx.x;
    const int h    = hc >> 5;
    const int c    = hc & 31;
    const int pos0 = h * SEQ + c * CHK;

    // ================= Stage 1: A = Qphi Kphi^T =================
    float accA[2][4][4];
#pragma unroll
    for (int mt = 0; mt < 2; mt++)
#pragma unroll
        for (int nt = 0; nt < 4; nt++)
#pragma unroll
            for (int e = 0; e < 4; e++) accA[mt][nt][e] = 0.f;

    for (int f0 = 0; f0 < FF; f0 += 32) {
        __syncthreads();
#pragma unroll
        for (int r = 0; r < 2; r++) {
            int slot = t + r * 512;
            int row  = slot >> 3;
            int c4   = (slot & 7) << 2;
            float4 qv = *(const float4*)(qphi + (size_t)(pos0 + row) * FF + f0 + c4);
            uint32_t* pq = &S1Q[row * GP + c4];
            pq[0] = f2tf32(qv.x); pq[1] = f2tf32(qv.y);
            pq[2] = f2tf32(qv.z); pq[3] = f2tf32(qv.w);
            float4 kv = *(const float4*)(kphi + (size_t)(pos0 + row) * FF + f0 + c4);
            uint32_t* pk = &S1K[row * GP + c4];
            pk[0] = f2tf32(kv.x); pk[1] = f2tf32(kv.y);
            pk[2] = f2tf32(kv.z); pk[3] = f2tf32(kv.w);
        }
        __syncthreads();
#pragma unroll
        for (int ks = 0; ks < 4; ks++) {
            int kc = ks * 8 + tig;
            uint32_t af[2][4];
#pragma unroll
            for (int mt = 0; mt < 2; mt++) {
                int base = (wm * 32 + mt * 16 + g) * GP + kc;
                af[mt][0] = S1Q[base];
                af[mt][1] = S1Q[base + 8 * GP];
                af[mt][2] = S1Q[base + 4];
                af[mt][3] = S1Q[base + 8 * GP + 4];
            }
            uint32_t bf[4][2];
#pragma unroll
            for (int nt = 0; nt < 4; nt++) {
                int base = (wn * 32 + nt * 8 + g) * GP + kc;
                bf[nt][0] = S1K[base];
                bf[nt][1] = S1K[base + 4];
            }
#pragma unroll
            for (int mt = 0; mt < 2; mt++)
#pragma unroll
                for (int nt = 0; nt < 4; nt++)
                    mma8(accA[mt][nt], af[mt], bf[nt]);
        }
    }
    __syncthreads();

    // write A (tf32) [n][m]; load V^T
#pragma unroll
    for (int mt = 0; mt < 2; mt++) {
#pragma unroll
        for (int nt = 0; nt < 4; nt++) {
            int n0 = wm * 32 + mt * 16 + g;
            int m0 = wn * 32 + nt * 8 + tig * 2;
            Abuf[n0 * AP + m0]           = f2tf32(accA[mt][nt][0]);
            Abuf[n0 * AP + m0 + 1]       = f2tf32(accA[mt][nt][1]);
            Abuf[(n0 + 8) * AP + m0]     = f2tf32(accA[mt][nt][2]);
            Abuf[(n0 + 8) * AP + m0 + 1] = f2tf32(accA[mt][nt][3]);
        }
    }
#pragma unroll
    for (int r = 0; r < 8; r++) {
        int slot = t + r * 512;
        int m    = slot >> 5;
        int d4   = (slot & 31) << 2;
        float4 vv = *(const float4*)(vin + (size_t)(pos0 + m) * DD + d4);
        Vt[(d4+0)*VP + m] = f2tf32(vv.x);
        Vt[(d4+1)*VP + m] = f2tf32(vv.y);
        Vt[(d4+2)*VP + m] = f2tf32(vv.z);
        Vt[(d4+3)*VP + m] = f2tf32(vv.w);
    }
    __syncthreads();

    // ================= Stage 2: masked A @ V =================
    float acc1[2][4][4], acc2[2][4][4];
#pragma unroll
    for (int mt = 0; mt < 2; mt++)
#pragma unroll
        for (int nt = 0; nt < 4; nt++)
#pragma unroll
            for (int e = 0; e < 4; e++) { acc1[mt][nt][e] = 0.f; acc2[mt][nt][e] = 0.f; }

#pragma unroll
    for (int kch = 0; kch < 4; kch++) {
#pragma unroll
        for (int ks = 0; ks < 4; ks++) {
            int kc = kch * 32 + ks * 8 + tig;
            uint32_t lo[2][4], up[2][4];
#pragma unroll
            for (int mt = 0; mt < 2; mt++) {
                int nA = wm * 32 + mt * 16 + g;
                int nB = nA + 8;
                uint32_t a0 = Abuf[nA * AP + kc];
                uint32_t a1 = Abuf[nB * AP + kc];
                uint32_t a2 = Abuf[nA * AP + kc + 4];
                uint32_t a3 = Abuf[nB * AP + kc + 4];
                lo[mt][0] = (kc     <= nA) ? a0 : 0u;
                lo[mt][1] = (kc     <= nB) ? a1 : 0u;
                lo[mt][2] = (kc + 4 <= nA) ? a2 : 0u;
                lo[mt][3] = (kc + 4 <= nB) ? a3 : 0u;
                up[mt][0] = (kc     >= nA) ? a0 : 0u;
                up[mt][1] = (kc     >= nB) ? a1 : 0u;
                up[mt][2] = (kc + 4 >= nA) ? a2 : 0u;
                up[mt][3] = (kc + 4 >= nB) ? a3 : 0u;
            }
            uint32_t bf[4][2];
#pragma unroll
            for (int nt = 0; nt < 4; nt++) {
                int base = (wn * 32 + nt * 8 + g) * VP + kc;
                bf[nt][0] = Vt[base];
                bf[nt][1] = Vt[base + 4];
            }
#pragma unroll
            for (int mt = 0; mt < 2; mt++)
#pragma unroll
                for (int nt = 0; nt < 4; nt++) {
                    mma8(acc1[mt][nt], lo[mt], bf[nt]);
                    mma8(acc2[mt][nt], up[mt], bf[nt]);
                }
        }
    }
    __syncthreads();

    // ================= Stage 3: Q @ Wexc / Q @ Wsuf =================
    const float* Pbase = P + (size_t)h * (NC + 1) * FD;
    const float* Pexc  = Pbase + (size_t)c * FD;
    const float* Pinc  = Pbase + (size_t)(c + 1) * FD;
    const float* Ptot  = Pbase + (size_t)NC * FD;

    for (int f0 = 0; f0 < FF; f0 += 32) {
#pragma unroll
        for (int r = 0; r < 2; r++) {
            int slot = t + r * 512;
            int row  = slot >> 3;
            int c4   = (slot & 7) << 2;
            float4 qv = *(const float4*)(qphi + (size_t)(pos0 + row) * FF + f0 + c4);
            uint32_t* pq = &S3Q[row * GP + c4];
            pq[0] = f2tf32(qv.x); pq[1] = f2tf32(qv.y);
            pq[2] = f2tf32(qv.z); pq[3] = f2tf32(qv.w);
            size_t go = (size_t)row * FF + f0 + c4;
            float4 ev = *(const float4*)(Pexc + go);
            uint32_t* p1 = &S3B1[row * GP + c4];
            p1[0] = f2tf32(ev.x); p1[1] = f2tf32(ev.y);
            p1[2] = f2tf32(ev.z); p1[3] = f2tf32(ev.w);
            float4 iv = *(const float4*)(Pinc + go);
            float4 tv = *(const float4*)(Ptot + go);
            uint32_t* p2 = &S3B2[row * GP + c4];
            p2[0] = f2tf32(tv.x - iv.x); p2[1] = f2tf32(tv.y - iv.y);
            p2[2] = f2tf32(tv.z - iv.z); p2[3] = f2tf32(tv.w - iv.w);
        }
        __syncthreads();
#pragma unroll
        for (int ks = 0; ks < 4; ks++) {
            int kc = ks * 8 + tig;
            uint32_t af[2][4];
#pragma unroll
            for (int mt = 0; mt < 2; mt++) {
                int base = (wm * 32 + mt * 16 + g) * GP + kc;
                af[mt][0] = S3Q[base];
                af[mt][1] = S3Q[base + 8 * GP];
                af[mt][2] = S3Q[base + 4];
                af[mt][3] = S3Q[base + 8 * GP + 4];
            }
            uint32_t b1[4][2], b2[4][2];
#pragma unroll
            for (int nt = 0; nt < 4; nt++) {
                int base = (wn * 32 + nt * 8 + g) * GP + kc;
                b1[nt][0] = S3B1[base];
                b1[nt][1] = S3B1[base + 4];
                b2[nt][0] = S3B2[base];
                b2[nt][1] = S3B2[base + 4];
            }
#pragma unroll
            for (int mt = 0; mt < 2; mt++)
#pragma unroll
                for (int nt = 0; nt < 4; nt++) {
                    mma8(acc1[mt][nt], af[mt], b1[nt]);
                    mma8(acc2[mt][nt], af[mt], b2[nt]);
                }
        }
        __syncthreads();
    }

    // ================= Epilogue =================
#pragma unroll
    for (int mt = 0; mt < 2; mt++) {
#pragma unroll
        for (int nt = 0; nt < 4; nt++) {
            int n0  = wm * 32 + mt * 16 + g;
            int d0  = wn * 32 + nt * 8 + tig * 2;
            int posA = c * CHK + n0;
            int posB = posA + 8;
            float s1a = 1.f / (float)(posA + 1);
            float s2a = 1.f / (float)(SEQ - posA);
            float s1b = 1.f / (float)(posB + 1);
            float s2b = 1.f / (float)(SEQ - posB);
            float2 oA, oB;
            oA.x = acc1[mt][nt][0] * s1a + acc2[mt][nt][0] * s2a;
            oA.y = acc1[mt][nt][1] * s1a + acc2[mt][nt][1] * s2a;
            oB.x = acc1[mt][nt][2] * s1b + acc2[mt][nt][2] * s2b;
            oB.y = acc1[mt][nt][3] * s1b + acc2[mt][nt][3] * s2b;
            *(float2*)(out + (size_t)(pos0 + n0) * DD + d0)     = oA;
            *(float2*)(out + (size_t)(pos0 + n0 + 8) * DD + d0) = oB;
        }
    }
}

// ---------------------------------------------------------------------------
extern "C" void kernel_launch(void* const* d_in, const int* in_sizes, int n_in,
                              void* d_out, int out_size)
{
    (void)out_size;
    int big[3] = {0, 1, 2}; int nbig = 0;
    int iw1 = -1, iw2 = -1, ibias[2] = {-1, -1}; int nb = 0;
    for (int i = 0; i < n_in; i++) {
        long long s = in_sizes[i];
        if ((s == 12582912LL || s == 50331648LL) && nbig < 3) big[nbig++] = i;
        else if (s == 32768LL  || s == 131072LL) iw1 = i;
        else if (s == 65536LL  || s == 262144LL) iw2 = i;
        else if ((s == 256LL   || s == 1024LL) && nb < 2) ibias[nb++] = i;
    }
    if (nbig != 3 || iw1 < 0 || iw2 < 0 || nb != 2) {
        big[0] = 0; big[1] = 1; big[2] = 2;
        iw1 = 3; ibias[0] = 4; iw2 = 5; ibias[1] = 6;
    }
    const float *q, *k;
    if (big[0] == 0) {
        q = (const float*)d_in[big[0]];
        k = (const float*)d_in[big[1]];
    } else {
        k = (const float*)d_in[big[0]];
        q = (const float*)d_in[big[1]];
    }
    const float* v  = (const float*)d_in[big[2]];
    const float* w1 = (const float*)d_in[iw1];
    const float* b1 = (const float*)d_in[ibias[0]];
    const float* w2 = (const float*)d_in[iw2];
    const float* b2 = (const float*)d_in[ibias[1]];
    float* out = (float*)d_out;

    float *hq, *hk, *qphi, *kphi, *P, *w1t, *w2t;
    cudaGetSymbolAddress((void**)&hq,   g_hq);
    cudaGetSymbolAddress((void**)&hk,   g_hk);
    cudaGetSymbolAddress((void**)&qphi, g_qphi);
    cudaGetSymbolAddress((void**)&kphi, g_kphi);
    cudaGetSymbolAddress((void**)&P,    g_P);
    cudaGetSymbolAddress((void**)&w1t,  g_w1t);
    cudaGetSymbolAddress((void**)&w2t,  g_w2t);

    cudaFuncSetAttribute(phiA,
                         cudaFuncAttributeMaxDynamicSharedMemorySize, PA_BYTES);
    cudaFuncSetAttribute(phiB,
                         cudaFuncAttributeMaxDynamicSharedMemorySize, PB_BYTES);
    cudaFuncSetAttribute(output_tc,
                         cudaFuncAttributeMaxDynamicSharedMemorySize, OSM_BYTES);

    transpose_kernel<<<(DD*FF + 255)/256, 256>>>(w1, w1t, DD, FF);
    transpose_kernel<<<(FF*FF + 255)/256, 256>>>(w2, w2t, FF, FF);

    phiA<<<2 * NBLK, 512, PA_BYTES>>>(q, k, w1t, b1, hq, hk);
    phiB<<<2 * NBLK, 512, PB_BYTES>>>(hq, hk, w2t, b2, qphi, kphi);

    chunk_state_tc<<<dim3(BH * NC, 2), 512>>>(kphi, v, P);
    prefix_kernel<<<dim3(FD / 256, BH), 256>>>(P);

    output_tc<<<BH * NC, 512, OSM_BYTES>>>(qphi, kphi, v, P, out);
}

// round 11
// speedup vs baseline: 1.0483x; 1.0483x over previous
#include <cuda_runtime.h>
#include <cstdint>

// Problem constants
#define BH   24
#define SEQ  4096
#define DD   128
#define FF   256
#define CHK  128
#define NC   32
#define ROWS (BH*SEQ)      // 98304
#define FD   (FF*DD)       // 32768
#define NBLK (ROWS/128)    // 768

// ---------------- scratch (device globals; no runtime allocation) ----------
__device__ float g_hq  [(size_t)ROWS * FF];
__device__ float g_hk  [(size_t)ROWS * FF];
__device__ float g_qphi[(size_t)ROWS * FF];
__device__ float g_kphi[(size_t)ROWS * FF];
__device__ float g_P   [(size_t)BH * (NC+1) * FD];   // TRANSPOSED slabs: [d][f]
__device__ float g_w1t [FF * DD];
__device__ float g_w2t [FF * FF];

#define GP  36
#define GPT 37
#define AP  132
#define VP  133

__device__ __forceinline__ uint32_t f2tf32(float x) {
    uint32_t r; asm("cvt.rna.tf32.f32 %0, %1;" : "=r"(r) : "f"(x)); return r;
}
__device__ __forceinline__ void mma8(float* c, const uint32_t* a, const uint32_t* b) {
    asm volatile(
        "mma.sync.aligned.m16n8k8.row.col.f32.tf32.tf32.f32 "
        "{%0,%1,%2,%3}, {%4,%5,%6,%7}, {%8,%9}, {%0,%1,%2,%3};"
        : "+f"(c[0]), "+f"(c[1]), "+f"(c[2]), "+f"(c[3])
        : "r"(a[0]), "r"(a[1]), "r"(a[2]), "r"(a[3]), "r"(b[0]), "r"(b[1]));
}

// ---------------------------------------------------------------------------
// phiA: h = silu(X @ w1t^T + b1).  Grid 2*NBLK, 256 thr, 8 warps (2m x 4n),
// warp tile 64x64 (mt=4, nt=8) -> block tile 128 x 256 (full FF).
// X tile + full w1t resident; ONE sync; 16 flop/smem-byte.
// ---------------------------------------------------------------------------
#define PA_XS    0
#define PA_WS    (128*AP)
#define PA_BYTES ((128*AP + 256*AP) * 4)    // 202752

__global__ __launch_bounds__(256, 1) void phiA(
    const float* __restrict__ Xq, const float* __restrict__ Xk,
    const float* __restrict__ w1t, const float* __restrict__ b1,
    float* __restrict__ Hq, float* __restrict__ Hk)
{
    extern __shared__ uint32_t smx[];
    uint32_t* Xs = smx + PA_XS;
    uint32_t* Ws = smx + PA_WS;

    const int t    = threadIdx.x;
    const int lane = t & 31;
    const int wid  = t >> 5;
    const int wm   = wid >> 2;        // 0..1
    const int wn   = wid & 3;         // 0..3
    const int g    = lane >> 2;
    const int tig  = lane & 3;
    const int bx   = blockIdx.x;
    const bool isK = (bx >= NBLK);
    const int row0 = (isK ? bx - NBLK : bx) * 128;
    const float* X = isK ? Xk : Xq;
    float* H       = isK ? Hk : Hq;

    // stage X tile [128][128]: 4096 f4 slots
#pragma unroll
    for (int r = 0; r < 16; r++) {
        int slot = t + r * 256;
        int row  = slot >> 5;
        int c4   = (slot & 31) << 2;
        float4 v = *(const float4*)(X + (size_t)(row0 + row) * DD + c4);
        uint32_t* p = &Xs[row * AP + c4];
        p[0] = f2tf32(v.x); p[1] = f2tf32(v.y);
        p[2] = f2tf32(v.z); p[3] = f2tf32(v.w);
    }
    // stage full w1t [256][128]: 8192 slots
#pragma unroll
    for (int r = 0; r < 32; r++) {
        int slot = t + r * 256;
        int row  = slot >> 5;           // 0..255
        int c4   = (slot & 31) << 2;
        float4 v = *(const float4*)(w1t + (size_t)row * DD + c4);
        uint32_t* p = &Ws[row * AP + c4];
        p[0] = f2tf32(v.x); p[1] = f2tf32(v.y);
        p[2] = f2tf32(v.z); p[3] = f2tf32(v.w);
    }
    __syncthreads();

    float acc[4][8][4];
#pragma unroll
    for (int mt = 0; mt < 4; mt++)
#pragma unroll
        for (int nt = 0; nt < 8; nt++)
#pragma unroll
            for (int e = 0; e < 4; e++) acc[mt][nt][e] = 0.f;

    for (int ks = 0; ks < 16; ks++) {
        int kc = ks * 8 + tig;
        uint32_t af[4][4];
#pragma unroll
        for (int mt = 0; mt < 4; mt++) {
            int base = (wm * 64 + mt * 16 + g) * AP + kc;
            af[mt][0] = Xs[base];
            af[mt][1] = Xs[base + 8 * AP];
            af[mt][2] = Xs[base + 4];
            af[mt][3] = Xs[base + 8 * AP + 4];
        }
        uint32_t bf[8][2];
#pragma unroll
        for (int nt = 0; nt < 8; nt++) {
            int base = (wn * 64 + nt * 8 + g) * AP + kc;
            bf[nt][0] = Ws[base];
            bf[nt][1] = Ws[base + 4];
        }
#pragma unroll
        for (int mt = 0; mt < 4; mt++)
#pragma unroll
            for (int nt = 0; nt < 8; nt++)
                mma8(acc[mt][nt], af[mt], bf[nt]);
    }

    // epilogue: bias + silu + store h
#pragma unroll
    for (int mt = 0; mt < 4; mt++) {
#pragma unroll
        for (int nt = 0; nt < 8; nt++) {
            int row = row0 + wm * 64 + mt * 16 + g;
            int col = wn * 64 + nt * 8 + tig * 2;
            float b0v = b1[col], b1v = b1[col + 1];
            float x0 = acc[mt][nt][0] + b0v;
            float x1 = acc[mt][nt][1] + b1v;
            float x2 = acc[mt][nt][2] + b0v;
            float x3 = acc[mt][nt][3] + b1v;
            x0 = x0 / (1.f + __expf(-x0));
            x1 = x1 / (1.f + __expf(-x1));
            x2 = x2 / (1.f + __expf(-x2));
            x3 = x3 / (1.f + __expf(-x3));
            float2 o01, o23;
            o01.x = x0; o01.y = x1;
            o23.x = x2; o23.y = x3;
            *(float2*)(H + (size_t)row * FF + col)       = o01;
            *(float2*)(H + (size_t)(row + 8) * FF + col) = o23;
        }
    }
}

// ---------------------------------------------------------------------------
// phiB: phi = h @ w2t^T + b2.  Grid 2*NBLK, 256 thr, 8 warps (2m x 4n),
// warp tile 64x64 -> block 128 x 256 (full n). K=256 via 2 k-passes of 128;
// acc persists in registers; Hs/Ws k-halves staged per pass.
// ---------------------------------------------------------------------------
#define PB_HS    0
#define PB_WS    (128*AP)
#define PB_BYTES ((128*AP + 256*AP) * 4)    // 202752

__global__ __launch_bounds__(256, 1) void phiB(
    const float* __restrict__ Hq, const float* __restrict__ Hk,
    const float* __restrict__ w2t, const float* __restrict__ b2,
    float* __restrict__ Cq, float* __restrict__ Ck)
{
    extern __shared__ uint32_t smx[];
    uint32_t* Hs = smx + PB_HS;      // [128 rows][128 k-local]
    uint32_t* Ws = smx + PB_WS;      // [256 n][128 k-local]

    const int t    = threadIdx.x;
    const int lane = t & 31;
    const int wid  = t >> 5;
    const int wm   = wid >> 2;
    const int wn   = wid & 3;
    const int g    = lane >> 2;
    const int tig  = lane & 3;
    const int bx   = blockIdx.x;
    const bool isK = (bx >= NBLK);
    const int row0 = (isK ? bx - NBLK : bx) * 128;
    const float* H = isK ? Hk : Hq;
    float* C       = isK ? Ck : Cq;

    float acc[4][8][4];
#pragma unroll
    for (int mt = 0; mt < 4; mt++)
#pragma unroll
        for (int nt = 0; nt < 8; nt++)
#pragma unroll
            for (int e = 0; e < 4; e++) acc[mt][nt][e] = 0.f;

#pragma unroll
    for (int kp = 0; kp < 2; kp++) {
        __syncthreads();   // previous pass done reading Hs/Ws
        // stage Hs k-half [128][128]: 4096 f4 slots
#pragma unroll
        for (int r = 0; r < 16; r++) {
            int slot = t + r * 256;
            int row  = slot >> 5;
            int c4   = (slot & 31) << 2;
            float4 v = *(const float4*)(H + (size_t)(row0 + row) * FF + kp * 128 + c4);
            uint32_t* p = &Hs[row * AP + c4];
            p[0] = f2tf32(v.x); p[1] = f2tf32(v.y);
            p[2] = f2tf32(v.z); p[3] = f2tf32(v.w);
        }
        // stage Ws k-half [256][128]: 8192 slots
#pragma unroll
        for (int r = 0; r < 32; r++) {
            int slot = t + r * 256;
            int row  = slot >> 5;       // 0..255
            int c4   = (slot & 31) << 2;
            float4 v = *(const float4*)(w2t + (size_t)row * FF + kp * 128 + c4);
            uint32_t* p = &Ws[row * AP + c4];
            p[0] = f2tf32(v.x); p[1] = f2tf32(v.y);
            p[2] = f2tf32(v.z); p[3] = f2tf32(v.w);
        }
        __syncthreads();

        for (int ks = 0; ks < 16; ks++) {
            int kc = ks * 8 + tig;
            uint32_t af[4][4];
#pragma unroll
            for (int mt = 0; mt < 4; mt++) {
                int base = (wm * 64 + mt * 16 + g) * AP + kc;
                af[mt][0] = Hs[base];
                af[mt][1] = Hs[base + 8 * AP];
                af[mt][2] = Hs[base + 4];
                af[mt][3] = Hs[base + 8 * AP + 4];
            }
            uint32_t bf[8][2];
#pragma unroll
            for (int nt = 0; nt < 8; nt++) {
                int base = (wn * 64 + nt * 8 + g) * AP + kc;
                bf[nt][0] = Ws[base];
                bf[nt][1] = Ws[base + 4];
            }
#pragma unroll
            for (int mt = 0; mt < 4; mt++)
#pragma unroll
                for (int nt = 0; nt < 8; nt++)
                    mma8(acc[mt][nt], af[mt], bf[nt]);
        }
    }

    // epilogue: bias + store
#pragma unroll
    for (int mt = 0; mt < 4; mt++) {
#pragma unroll
        for (int nt = 0; nt < 8; nt++) {
            int row = row0 + wm * 64 + mt * 16 + g;
            int col = wn * 64 + nt * 8 + tig * 2;
            float b0v = b2[col], b1v = b2[col + 1];
            float2 o01, o23;
            o01.x = acc[mt][nt][0] + b0v;
            o01.y = acc[mt][nt][1] + b1v;
            o23.x = acc[mt][nt][2] + b0v;
            o23.y = acc[mt][nt][3] + b1v;
            *(float2*)(C + (size_t)row * FF + col)       = o01;
            *(float2*)(C + (size_t)(row + 8) * FF + col) = o23;
        }
    }
}

// ---------------------------------------------------------------------------
// Transpose W [K,N] -> Wt [N,K]
// ---------------------------------------------------------------------------
__global__ void transpose_kernel(const float* __restrict__ W,
                                 float* __restrict__ Wt, int K, int N)
{
    int idx = blockIdx.x * blockDim.x + threadIdx.x;
    if (idx >= K * N) return;
    int kk = idx / N;
    int n  = idx - kk * N;
    Wt[(size_t)n * K + kk] = W[idx];
}

// ---------------------------------------------------------------------------
// chunk_state (tensor cores, 256 thr — verified R7): S^T[d][f]
// ---------------------------------------------------------------------------
__global__ __launch_bounds__(256) void chunk_state_tc(
    const float* __restrict__ kphi, const float* __restrict__ vin,
    float* __restrict__ P)
{
    __shared__ uint32_t At[128 * GPT];
    __shared__ uint32_t Bt[128 * GPT];

    const int t    = threadIdx.x;
    const int lane = t & 31;
    const int wid  = t >> 5;
    const int wm   = wid >> 2;
    const int wn   = wid & 3;
    const int g    = lane >> 2;
    const int tig  = lane & 3;
    const int hc   = blockIdx.x;
    const int h    = hc >> 5;
    const int c    = hc & 31;
    const int f0   = blockIdx.y * 128;
    const int pos0 = h * SEQ + c * CHK;

    float acc[4][4][4];
#pragma unroll
    for (int mt = 0; mt < 4; mt++)
#pragma unroll
        for (int nt = 0; nt < 4; nt++)
#pragma unroll
            for (int e = 0; e < 4; e++) acc[mt][nt][e] = 0.f;

    for (int m0 = 0; m0 < CHK; m0 += 32) {
#pragma unroll
        for (int r = 0; r < 4; r++) {
            int slot = t + r * 256;
            int m    = slot >> 5;
            int x4   = (slot & 31) << 2;
            float4 vv = *(const float4*)(vin + (size_t)(pos0 + m0 + m) * DD + x4);
            At[(x4+0)*GPT + m] = f2tf32(vv.x);
            At[(x4+1)*GPT + m] = f2tf32(vv.y);
            At[(x4+2)*GPT + m] = f2tf32(vv.z);
            At[(x4+3)*GPT + m] = f2tf32(vv.w);
            float4 kk = *(const float4*)(kphi + (size_t)(pos0 + m0 + m) * FF + f0 + x4);
            Bt[(x4+0)*GPT + m] = f2tf32(kk.x);
            Bt[(x4+1)*GPT + m] = f2tf32(kk.y);
            Bt[(x4+2)*GPT + m] = f2tf32(kk.z);
            Bt[(x4+3)*GPT + m] = f2tf32(kk.w);
        }
        __syncthreads();
#pragma unroll
        for (int ks = 0; ks < 4; ks++) {
            int kc = ks * 8 + tig;
            uint32_t af[4][4];
#pragma unroll
            for (int mt = 0; mt < 4; mt++) {
                int base = (wm * 64 + mt * 16 + g) * GPT + kc;
                af[mt][0] = At[base];
                af[mt][1] = At[base + 8 * GPT];
                af[mt][2] = At[base + 4];
                af[mt][3] = At[base + 8 * GPT + 4];
            }
            uint32_t bf[4][2];
#pragma unroll
            for (int nt = 0; nt < 4; nt++) {
                int base = (wn * 32 + nt * 8 + g) * GPT + kc;
                bf[nt][0] = Bt[base];
                bf[nt][1] = Bt[base + 4];
            }
#pragma unroll
            for (int mt = 0; mt < 4; mt++)
#pragma unroll
                for (int nt = 0; nt < 4; nt++)
                    mma8(acc[mt][nt], af[mt], bf[nt]);
        }
        __syncthreads();
    }

    float* S = P + ((size_t)(h * (NC + 1)) + (c + 1)) * FD;
#pragma unroll
    for (int mt = 0; mt < 4; mt++) {
#pragma unroll
        for (int nt = 0; nt < 4; nt++) {
            int d   = wm * 64 + mt * 16 + g;
            int col = f0 + wn * 32 + nt * 8 + tig * 2;
            float2 o01; o01.x = acc[mt][nt][0]; o01.y = acc[mt][nt][1];
            float2 o23; o23.x = acc[mt][nt][2]; o23.y = acc[mt][nt][3];
            *(float2*)(S + (size_t)d * FF + col)       = o01;
            *(float2*)(S + (size_t)(d + 8) * FF + col) = o23;
        }
    }
}

// ---------------------------------------------------------------------------
// Inclusive prefix over chunk slabs.
// ---------------------------------------------------------------------------
__global__ void prefix_kernel(float* __restrict__ P)
{
    const int h = blockIdx.y;
    const int e = blockIdx.x * 256 + threadIdx.x;
    float* base = P + (size_t)h * (NC + 1) * FD;
    base[e] = 0.f;
    float acc = 0.f;
#pragma unroll
    for (int c = 1; c <= NC; c++) {
        acc += base[(size_t)c * FD + e];
        base[(size_t)c * FD + e] = acc;
    }
}

// ---------------------------------------------------------------------------
// output_tc (verified R7, 256 thr): per (head, chunk) block, all-tensor-core.
// ---------------------------------------------------------------------------
#define OSM_BYTES ((128*AP + 128*VP) * 4)   // 135680

__global__ __launch_bounds__(256, 1) void output_tc(
    const float* __restrict__ qphi, const float* __restrict__ kphi,
    const float* __restrict__ vin,  const float* __restrict__ P,
    float* __restrict__ out)
{
    extern __shared__ uint32_t smx[];
    uint32_t* Abuf = smx;
    uint32_t* Vt   = smx + 128 * AP;
    uint32_t* S1Q  = Vt;
    uint32_t* S1K  = Vt + 128 * GP;
    uint32_t* S3Q  = Abuf;
    uint32_t* S3B1 = Abuf + 128 * GP;
    uint32_t* S3B2 = Abuf + 2 * 128 * GP;

    const int t    = threadIdx.x;
    const int lane = t & 31;
    const int wid  = t >> 5;
    const int wm   = wid >> 2;
    const int wn   = wid & 3;
    const int g    = lane >> 2;
    const int tig  = lane & 3;
    const int hc   = blockIdx.x;
    const int h    = hc >> 5;
    const int c    = hc & 31;
    const int pos0 = h * SEQ + c * CHK;

    float accA[4][4][4];
#pragma unroll
    for (int mt = 0; mt < 4; mt++)
#pragma unroll
        for (int nt = 0; nt < 4; nt++)
#pragma unroll
            for (int e = 0; e < 4; e++) accA[mt][nt][e] = 0.f;

    for (int f0 = 0; f0 < FF; f0 += 32) {
        __syncthreads();
#pragma unroll
        for (int r = 0; r < 4; r++) {
            int slot = t + r * 256;
            int row  = slot >> 3;
            int c4   = (slot & 7) << 2;
            float4 qv = *(const float4*)(qphi + (size_t)(pos0 + row) * FF + f0 + c4);
            uint32_t* pq = &S1Q[row * GP + c4];
            pq[0] = f2tf32(qv.x); pq[1] = f2tf32(qv.y);
            pq[2] = f2tf32(qv.z); pq[3] = f2tf32(qv.w);
            float4 kv = *(const float4*)(kphi + (size_t)(pos0 + row) * FF + f0 + c4);
            uint32_t* pk = &S1K[row * GP + c4];
            pk[0] = f2tf32(kv.x); pk[1] = f2tf32(kv.y);
            pk[2] = f2tf32(kv.z); pk[3] = f2tf32(kv.w);
        }
        __syncthreads();
#pragma unroll
        for (int ks = 0; ks < 4; ks++) {
            int kc = ks * 8 + tig;
            uint32_t af[4][4];
#pragma unroll
            for (int mt = 0; mt < 4; mt++) {
                int base = (wm * 64 + mt * 16 + g) * GP + kc;
                af[mt][0] = S1Q[base];
                af[mt][1] = S1Q[base + 8 * GP];
                af[mt][2] = S1Q[base + 4];
                af[mt][3] = S1Q[base + 8 * GP + 4];
            }
            uint32_t bf[4][2];
#pragma unroll
            for (int nt = 0; nt < 4; nt++) {
                int base = (wn * 32 + nt * 8 + g) * GP + kc;
                bf[nt][0] = S1K[base];
                bf[nt][1] = S1K[base + 4];
            }
#pragma unroll
            for (int mt = 0; mt < 4; mt++)
#pragma unroll
                for (int nt = 0; nt < 4; nt++)
                    mma8(accA[mt][nt], af[mt], bf[nt]);
        }
    }
    __syncthreads();

#pragma unroll
    for (int mt = 0; mt < 4; mt++) {
#pragma unroll
        for (int nt = 0; nt < 4; nt++) {
            int n0 = wm * 64 + mt * 16 + g;
            int m0 = wn * 32 + nt * 8 + tig * 2;
            Abuf[n0 * AP + m0]           = f2tf32(accA[mt][nt][0]);
            Abuf[n0 * AP + m0 + 1]       = f2tf32(accA[mt][nt][1]);
            Abuf[(n0 + 8) * AP + m0]     = f2tf32(accA[mt][nt][2]);
            Abuf[(n0 + 8) * AP + m0 + 1] = f2tf32(accA[mt][nt][3]);
        }
    }
#pragma unroll
    for (int r = 0; r < 16; r++) {
        int slot = t + r * 256;
        int m    = slot >> 5;
        int d4   = (slot & 31) << 2;
        float4 vv = *(const float4*)(vin + (size_t)(pos0 + m) * DD + d4);
        Vt[(d4+0)*VP + m] = f2tf32(vv.x);
        Vt[(d4+1)*VP + m] = f2tf32(vv.y);
        Vt[(d4+2)*VP + m] = f2tf32(vv.z);
        Vt[(d4+3)*VP + m] = f2tf32(vv.w);
    }
    __syncthreads();

    float acc1[4][4][4], acc2[4][4][4];
#pragma unroll
    for (int mt = 0; mt < 4; mt++)
#pragma unroll
        for (int nt = 0; nt < 4; nt++)
#pragma unroll
            for (int e = 0; e < 4; e++) { acc1[mt][nt][e] = 0.f; acc2[mt][nt][e] = 0.f; }

#pragma unroll
    for (int kch = 0; kch < 4; kch++) {
#pragma unroll
        for (int ks = 0; ks < 4; ks++) {
            int kc = kch * 32 + ks * 8 + tig;
            uint32_t lo[4][4], up[4][4];
#pragma unroll
            for (int mt = 0; mt < 4; mt++) {
                int nA = wm * 64 + mt * 16 + g;
                int nB = nA + 8;
                uint32_t a0 = Abuf[nA * AP + kc];
                uint32_t a1 = Abuf[nB * AP + kc];
                uint32_t a2 = Abuf[nA * AP + kc + 4];
                uint32_t a3 = Abuf[nB * AP + kc + 4];
                lo[mt][0] = (kc     <= nA) ? a0 : 0u;
                lo[mt][1] = (kc     <= nB) ? a1 : 0u;
                lo[mt][2] = (kc + 4 <= nA) ? a2 : 0u;
                lo[mt][3] = (kc + 4 <= nB) ? a3 : 0u;
                up[mt][0] = (kc     >= nA) ? a0 : 0u;
                up[mt][1] = (kc     >= nB) ? a1 : 0u;
                up[mt][2] = (kc + 4 >= nA) ? a2 : 0u;
                up[mt][3] = (kc + 4 >= nB) ? a3 : 0u;
            }
            uint32_t bf[4][2];
#pragma unroll
            for (int nt = 0; nt < 4; nt++) {
                int base = (wn * 32 + nt * 8 + g) * VP + kc;
                bf[nt][0] = Vt[base];
                bf[nt][1] = Vt[base + 4];
            }
#pragma unroll
            for (int mt = 0; mt < 4; mt++)
#pragma unroll
                for (int nt = 0; nt < 4; nt++) {
                    mma8(acc1[mt][nt], lo[mt], bf[nt]);
                    mma8(acc2[mt][nt], up[mt], bf[nt]);
                }
        }
    }
    __syncthreads();

    const float* Pbase = P + (size_t)h * (NC + 1) * FD;
    const float* Pexc  = Pbase + (size_t)c * FD;
    const float* Pinc  = Pbase + (size_t)(c + 1) * FD;
    const float* Ptot  = Pbase + (size_t)NC * FD;

    for (int f0 = 0; f0 < FF; f0 += 32) {
#pragma unroll
        for (int r = 0; r < 4; r++) {
            int slot = t + r * 256;
            int row  = slot >> 3;
            int c4   = (slot & 7) << 2;
            float4 qv = *(const float4*)(qphi + (size_t)(pos0 + row) * FF + f0 + c4);
            uint32_t* pq = &S3Q[row * GP + c4];
            pq[0] = f2tf32(qv.x); pq[1] = f2tf32(qv.y);
            pq[2] = f2tf32(qv.z); pq[3] = f2tf32(qv.w);
            size_t go = (size_t)row * FF + f0 + c4;
            float4 ev = *(const float4*)(Pexc + go);
            uint32_t* p1 = &S3B1[row * GP + c4];
            p1[0] = f2tf32(ev.x); p1[1] = f2tf32(ev.y);
            p1[2] = f2tf32(ev.z); p1[3] = f2tf32(ev.w);
            float4 iv = *(const float4*)(Pinc + go);
            float4 tv = *(const float4*)(Ptot + go);
            uint32_t* p2 = &S3B2[row * GP + c4];
            p2[0] = f2tf32(tv.x - iv.x); p2[1] = f2tf32(tv.y - iv.y);
            p2[2] = f2tf32(tv.z - iv.z); p2[3] = f2tf32(tv.w - iv.w);
        }
        __syncthreads();
#pragma unroll
        for (int ks = 0; ks < 4; ks++) {
            int kc = ks * 8 + tig;
            uint32_t af[4][4];
#pragma unroll
            for (int mt = 0; mt < 4; mt++) {
                int base = (wm * 64 + mt * 16 + g) * GP + kc;
                af[mt][0] = S3Q[base];
                af[mt][1] = S3Q[base + 8 * GP];
                af[mt][2] = S3Q[base + 4];
                af[mt][3] = S3Q[base + 8 * GP + 4];
            }
            uint32_t b1[4][2], b2[4][2];
#pragma unroll
            for (int nt = 0; nt < 4; nt++) {
                int base = (wn * 32 + nt * 8 + g) * GP + kc;
                b1[nt][0] = S3B1[base];
                b1[nt][1] = S3B1[base + 4];
                b2[nt][0] = S3B2[base];
                b2[nt][1] = S3B2[base + 4];
            }
#pragma unroll
            for (int mt = 0; mt < 4; mt++)
#pragma unroll
                for (int nt = 0; nt < 4; nt++) {
                    mma8(acc1[mt][nt], af[mt], b1[nt]);
                    mma8(acc2[mt][nt], af[mt], b2[nt]);
                }
        }
        __syncthreads();
    }

#pragma unroll
    for (int mt = 0; mt < 4; mt++) {
#pragma unroll
        for (int nt = 0; nt < 4; nt++) {
            int n0  = wm * 64 + mt * 16 + g;
            int d0  = wn * 32 + nt * 8 + tig * 2;
            int posA = c * CHK + n0;
            int posB = posA + 8;
            float s1a = 1.f / (float)(posA + 1);
            float s2a = 1.f / (float)(SEQ - posA);
            float s1b = 1.f / (float)(posB + 1);
            float s2b = 1.f / (float)(SEQ - posB);
            float2 oA, oB;
            oA.x = acc1[mt][nt][0] * s1a + acc2[mt][nt][0] * s2a;
            oA.y = acc1[mt][nt][1] * s1a + acc2[mt][nt][1] * s2a;
            oB.x = acc1[mt][nt][2] * s1b + acc2[mt][nt][2] * s2b;
            oB.y = acc1[mt][nt][3] * s1b + acc2[mt][nt][3] * s2b;
            *(float2*)(out + (size_t)(pos0 + n0) * DD + d0)     = oA;
            *(float2*)(out + (size_t)(pos0 + n0 + 8) * DD + d0) = oB;
        }
    }
}

// ---------------------------------------------------------------------------
extern "C" void kernel_launch(void* const* d_in, const int* in_sizes, int n_in,
                              void* d_out, int out_size)
{
    (void)out_size;
    int big[3] = {0, 1, 2}; int nbig = 0;
    int iw1 = -1, iw2 = -1, ibias[2] = {-1, -1}; int nb = 0;
    for (int i = 0; i < n_in; i++) {
        long long s = in_sizes[i];
        if ((s == 12582912LL || s == 50331648LL) && nbig < 3) big[nbig++] = i;
        else if (s == 32768LL  || s == 131072LL) iw1 = i;
        else if (s == 65536LL  || s == 262144LL) iw2 = i;
        else if ((s == 256LL   || s == 1024LL) && nb < 2) ibias[nb++] = i;
    }
    if (nbig != 3 || iw1 < 0 || iw2 < 0 || nb != 2) {
        big[0] = 0; big[1] = 1; big[2] = 2;
        iw1 = 3; ibias[0] = 4; iw2 = 5; ibias[1] = 6;
    }
    const float *q, *k;
    if (big[0] == 0) {
        q = (const float*)d_in[big[0]];
        k = (const float*)d_in[big[1]];
    } else {
        k = (const float*)d_in[big[0]];
        q = (const float*)d_in[big[1]];
    }
    const float* v  = (const float*)d_in[big[2]];
    const float* w1 = (const float*)d_in[iw1];
    const float* b1 = (const float*)d_in[ibias[0]];
    const float* w2 = (const float*)d_in[iw2];
    const float* b2 = (const float*)d_in[ibias[1]];
    float* out = (float*)d_out;

    float *hq, *hk, *qphi, *kphi, *P, *w1t, *w2t;
    cudaGetSymbolAddress((void**)&hq,   g_hq);
    cudaGetSymbolAddress((void**)&hk,   g_hk);
    cudaGetSymbolAddress((void**)&qphi, g_qphi);
    cudaGetSymbolAddress((void**)&kphi, g_kphi);
    cudaGetSymbolAddress((void**)&P,    g_P);
    cudaGetSymbolAddress((void**)&w1t,  g_w1t);
    cudaGetSymbolAddress((void**)&w2t,  g_w2t);

    cudaFuncSetAttribute(phiA,
                         cudaFuncAttributeMaxDynamicSharedMemorySize, PA_BYTES);
    cudaFuncSetAttribute(phiB,
                         cudaFuncAttributeMaxDynamicSharedMemorySize, PB_BYTES);
    cudaFuncSetAttribute(output_tc,
                         cudaFuncAttributeMaxDynamicSharedMemorySize, OSM_BYTES);

    transpose_kernel<<<(DD*FF + 255)/256, 256>>>(w1, w1t, DD, FF);
    transpose_kernel<<<(FF*FF + 255)/256, 256>>>(w2, w2t, FF, FF);

    phiA<<<2 * NBLK, 256, PA_BYTES>>>(q, k, w1t, b1, hq, hk);
    phiB<<<2 * NBLK, 256, PB_BYTES>>>(hq, hk, w2t, b2, qphi, kphi);

    chunk_state_tc<<<dim3(BH * NC, 2), 256>>>(kphi, v, P);
    prefix_kernel<<<dim3(FD / 256, BH), 256>>>(P);

    output_tc<<<BH * NC, 256, OSM_BYTES>>>(qphi, kphi, v, P, out);
}

// round 12
// speedup vs baseline: 1.3243x; 1.2633x over previous
#include <cuda_runtime.h>
#include <cuda_fp16.h>
#include <cstdint>

// Problem constants
#define BH   24
#define SEQ  4096
#define DD   128
#define FF   256
#define CHK  128
#define NC   32
#define ROWS (BH*SEQ)      // 98304
#define FD   (FF*DD)       // 32768
#define NBLK (ROWS/128)    // 768

// ---------------- scratch (device globals; no runtime allocation) ----------
__device__ float g_hq  [(size_t)ROWS * FF];
__device__ float g_hk  [(size_t)ROWS * FF];
__device__ float g_qphi[(size_t)ROWS * FF];
__device__ float g_kphi[(size_t)ROWS * FF];
__device__ float g_P   [(size_t)BH * (NC+1) * FD];   // TRANSPOSED slabs: [d][f]
__device__ float g_w1t [FF * DD];
__device__ float g_w2t [FF * FF];

// strides in u32 (fp16-pair) units; mod 32 == 4 -> conflict-free frag reads
#define KP64  68    // K=128 -> 64 pairs, stride 68
#define KP128 132   // K=256 -> 128 pairs, stride 132
#define GPT 37      // tf32 transposed tile stride (chunk_state)

__device__ __forceinline__ uint32_t f2tf32(float x) {
    uint32_t r; asm("cvt.rna.tf32.f32 %0, %1;" : "=r"(r) : "f"(x)); return r;
}
__device__ __forceinline__ uint32_t f2h2(float a, float b) {
    __half2 h = __floats2half2_rn(a, b);
    return *reinterpret_cast<uint32_t*>(&h);
}
// fp16 m16n8k16 mma, fp32 accumulate
__device__ __forceinline__ void mma16(float* c, const uint32_t* a, const uint32_t* b) {
    asm volatile(
        "mma.sync.aligned.m16n8k16.row.col.f32.f16.f16.f32 "
        "{%0,%1,%2,%3}, {%4,%5,%6,%7}, {%8,%9}, {%0,%1,%2,%3};"
        : "+f"(c[0]), "+f"(c[1]), "+f"(c[2]), "+f"(c[3])
        : "r"(a[0]), "r"(a[1]), "r"(a[2]), "r"(a[3]), "r"(b[0]), "r"(b[1]));
}
// tf32 m16n8k8 (chunk_state only)
__device__ __forceinline__ void mma8(float* c, const uint32_t* a, const uint32_t* b) {
    asm volatile(
        "mma.sync.aligned.m16n8k8.row.col.f32.tf32.tf32.f32 "
        "{%0,%1,%2,%3}, {%4,%5,%6,%7}, {%8,%9}, {%0,%1,%2,%3};"
        : "+f"(c[0]), "+f"(c[1]), "+f"(c[2]), "+f"(c[3])
        : "r"(a[0]), "r"(a[1]), "r"(a[2]), "r"(a[3]), "r"(b[0]), "r"(b[1]));
}
// keep fp16 halves of packed pair where (m <= n) / (m >= n); m0 = index of low half
__device__ __forceinline__ uint32_t maskLE(uint32_t v, int m0, int n) {
    uint32_t m = (m0 <= n ? 0xFFFFu : 0u) | (m0 + 1 <= n ? 0xFFFF0000u : 0u);
    return v & m;
}
__device__ __forceinline__ uint32_t maskGE(uint32_t v, int m0, int n) {
    uint32_t m = (m0 >= n ? 0xFFFFu : 0u) | (m0 + 1 >= n ? 0xFFFF0000u : 0u);
    return v & m;
}

// ---------------------------------------------------------------------------
// phiA: h = silu(X @ w1t^T + b1). fp16 mma. Grid 2*NBLK, 256 thr, 8 warps 2x4,
// warp tile 64x64. X tile + full w1t resident as fp16 pairs; one sync.
// ---------------------------------------------------------------------------
#define PA_XS    0
#define PA_WS    (128*KP64)
#define PA_BYTES ((128*KP64 + 256*KP64) * 4)   // 104448

__global__ __launch_bounds__(256, 1) void phiA(
    const float* __restrict__ Xq, const float* __restrict__ Xk,
    const float* __restrict__ w1t, const float* __restrict__ b1,
    float* __restrict__ Hq, float* __restrict__ Hk)
{
    extern __shared__ uint32_t smx[];
    uint32_t* Xs = smx + PA_XS;
    uint32_t* Ws = smx + PA_WS;

    const int t    = threadIdx.x;
    const int lane = t & 31;
    const int wid  = t >> 5;
    const int wm   = wid >> 2;
    const int wn   = wid & 3;
    const int g    = lane >> 2;
    const int tig  = lane & 3;
    const int bx   = blockIdx.x;
    const bool isK = (bx >= NBLK);
    const int row0 = (isK ? bx - NBLK : bx) * 128;
    const float* X = isK ? Xk : Xq;
    float* H       = isK ? Hk : Hq;

    // stage X [128 rows][64 pairs]
#pragma unroll
    for (int r = 0; r < 16; r++) {
        int slot = t + r * 256;          // 4096 f4 slots
        int row  = slot >> 5;
        int p2   = (slot & 31) << 1;     // pair index 0..62
        float4 v = *(const float4*)(X + (size_t)(row0 + row) * DD + (p2 << 1));
        Xs[row * KP64 + p2]     = f2h2(v.x, v.y);
        Xs[row * KP64 + p2 + 1] = f2h2(v.z, v.w);
    }
    // stage w1t [256 rows][64 pairs]
#pragma unroll
    for (int r = 0; r < 32; r++) {
        int slot = t + r * 256;
        int row  = slot >> 5;
        int p2   = (slot & 31) << 1;
        float4 v = *(const float4*)(w1t + (size_t)row * DD + (p2 << 1));
        Ws[row * KP64 + p2]     = f2h2(v.x, v.y);
        Ws[row * KP64 + p2 + 1] = f2h2(v.z, v.w);
    }
    __syncthreads();

    float acc[4][8][4];
#pragma unroll
    for (int mt = 0; mt < 4; mt++)
#pragma unroll
        for (int nt = 0; nt < 8; nt++)
#pragma unroll
            for (int e = 0; e < 4; e++) acc[mt][nt][e] = 0.f;

#pragma unroll
    for (int ks = 0; ks < 8; ks++) {     // K=128 -> 8 k-steps of 16
        int kb = ks * 8 + tig;           // pair index
        uint32_t af[4][4];
#pragma unroll
        for (int mt = 0; mt < 4; mt++) {
            int row = wm * 64 + mt * 16 + g;
            af[mt][0] = Xs[row * KP64 + kb];
            af[mt][1] = Xs[(row + 8) * KP64 + kb];
            af[mt][2] = Xs[row * KP64 + kb + 4];
            af[mt][3] = Xs[(row + 8) * KP64 + kb + 4];
        }
        uint32_t bf[8][2];
#pragma unroll
        for (int nt = 0; nt < 8; nt++) {
            int col = wn * 64 + nt * 8 + g;
            bf[nt][0] = Ws[col * KP64 + kb];
            bf[nt][1] = Ws[col * KP64 + kb + 4];
        }
#pragma unroll
        for (int mt = 0; mt < 4; mt++)
#pragma unroll
            for (int nt = 0; nt < 8; nt++)
                mma16(acc[mt][nt], af[mt], bf[nt]);
    }

#pragma unroll
    for (int mt = 0; mt < 4; mt++) {
#pragma unroll
        for (int nt = 0; nt < 8; nt++) {
            int row = row0 + wm * 64 + mt * 16 + g;
            int col = wn * 64 + nt * 8 + tig * 2;
            float b0v = b1[col], b1v = b1[col + 1];
            float x0 = acc[mt][nt][0] + b0v;
            float x1 = acc[mt][nt][1] + b1v;
            float x2 = acc[mt][nt][2] + b0v;
            float x3 = acc[mt][nt][3] + b1v;
            x0 = x0 / (1.f + __expf(-x0));
            x1 = x1 / (1.f + __expf(-x1));
            x2 = x2 / (1.f + __expf(-x2));
            x3 = x3 / (1.f + __expf(-x3));
            float2 o01, o23;
            o01.x = x0; o01.y = x1;
            o23.x = x2; o23.y = x3;
            *(float2*)(H + (size_t)row * FF + col)       = o01;
            *(float2*)(H + (size_t)(row + 8) * FF + col) = o23;
        }
    }
}

// ---------------------------------------------------------------------------
// phiB: phi = h @ w2t^T + b2. fp16 mma, full K=256 resident, one staging.
// Grid 2*NBLK, 256 thr, warp tile 64x64.
// ---------------------------------------------------------------------------
#define PB_HS    0
#define PB_WS    (128*KP128)
#define PB_BYTES ((128*KP128 + 256*KP128) * 4)   // 202752

__global__ __launch_bounds__(256, 1) void phiB(
    const float* __restrict__ Hq, const float* __restrict__ Hk,
    const float* __restrict__ w2t, const float* __restrict__ b2,
    float* __restrict__ Cq, float* __restrict__ Ck)
{
    extern __shared__ uint32_t smx[];
    uint32_t* Hs = smx + PB_HS;      // [128][128 pairs]
    uint32_t* Ws = smx + PB_WS;      // [256][128 pairs]

    const int t    = threadIdx.x;
    const int lane = t & 31;
    const int wid  = t >> 5;
    const int wm   = wid >> 2;
    const int wn   = wid & 3;
    const int g    = lane >> 2;
    const int tig  = lane & 3;
    const int bx   = blockIdx.x;
    const bool isK = (bx >= NBLK);
    const int row0 = (isK ? bx - NBLK : bx) * 128;
    const float* H = isK ? Hk : Hq;
    float* C       = isK ? Ck : Cq;

    // stage Hs [128][128 pairs] : 8192 f4 slots
#pragma unroll
    for (int r = 0; r < 32; r++) {
        int slot = t + r * 256;
        int row  = slot >> 6;
        int p2   = (slot & 63) << 1;
        float4 v = *(const float4*)(H + (size_t)(row0 + row) * FF + (p2 << 1));
        Hs[row * KP128 + p2]     = f2h2(v.x, v.y);
        Hs[row * KP128 + p2 + 1] = f2h2(v.z, v.w);
    }
    // stage Ws [256][128 pairs] : 16384 f4 slots
#pragma unroll
    for (int r = 0; r < 64; r++) {
        int slot = t + r * 256;
        int row  = slot >> 6;
        int p2   = (slot & 63) << 1;
        float4 v = *(const float4*)(w2t + (size_t)row * FF + (p2 << 1));
        Ws[row * KP128 + p2]     = f2h2(v.x, v.y);
        Ws[row * KP128 + p2 + 1] = f2h2(v.z, v.w);
    }
    __syncthreads();

    float acc[4][8][4];
#pragma unroll
    for (int mt = 0; mt < 4; mt++)
#pragma unroll
        for (int nt = 0; nt < 8; nt++)
#pragma unroll
            for (int e = 0; e < 4; e++) acc[mt][nt][e] = 0.f;

    for (int ks = 0; ks < 16; ks++) {    // K=256 -> 16 k-steps
        int kb = ks * 8 + tig;
        uint32_t af[4][4];
#pragma unroll
        for (int mt = 0; mt < 4; mt++) {
            int row = wm * 64 + mt * 16 + g;
            af[mt][0] = Hs[row * KP128 + kb];
            af[mt][1] = Hs[(row + 8) * KP128 + kb];
            af[mt][2] = Hs[row * KP128 + kb + 4];
            af[mt][3] = Hs[(row + 8) * KP128 + kb + 4];
        }
        uint32_t bf[8][2];
#pragma unroll
        for (int nt = 0; nt < 8; nt++) {
            int col = wn * 64 + nt * 8 + g;
            bf[nt][0] = Ws[col * KP128 + kb];
            bf[nt][1] = Ws[col * KP128 + kb + 4];
        }
#pragma unroll
        for (int mt = 0; mt < 4; mt++)
#pragma unroll
            for (int nt = 0; nt < 8; nt++)
                mma16(acc[mt][nt], af[mt], bf[nt]);
    }

#pragma unroll
    for (int mt = 0; mt < 4; mt++) {
#pragma unroll
        for (int nt = 0; nt < 8; nt++) {
            int row = row0 + wm * 64 + mt * 16 + g;
            int col = wn * 64 + nt * 8 + tig * 2;
            float b0v = b2[col], b1v = b2[col + 1];
            float2 o01, o23;
            o01.x = acc[mt][nt][0] + b0v;
            o01.y = acc[mt][nt][1] + b1v;
            o23.x = acc[mt][nt][2] + b0v;
            o23.y = acc[mt][nt][3] + b1v;
            *(float2*)(C + (size_t)row * FF + col)       = o01;
            *(float2*)(C + (size_t)(row + 8) * FF + col) = o23;
        }
    }
}

// ---------------------------------------------------------------------------
// Transpose W [K,N] -> Wt [N,K]
// ---------------------------------------------------------------------------
__global__ void transpose_kernel(const float* __restrict__ W,
                                 float* __restrict__ Wt, int K, int N)
{
    int idx = blockIdx.x * blockDim.x + threadIdx.x;
    if (idx >= K * N) return;
    int kk = idx / N;
    int n  = idx - kk * N;
    Wt[(size_t)n * K + kk] = W[idx];
}

// ---------------------------------------------------------------------------
// chunk_state (tf32, verified R7): S^T[d][f] = sum_m V[m][d] * Kphi[m][f]
// ---------------------------------------------------------------------------
__global__ __launch_bounds__(256) void chunk_state_tc(
    const float* __restrict__ kphi, const float* __restrict__ vin,
    float* __restrict__ P)
{
    __shared__ uint32_t At[128 * GPT];
    __shared__ uint32_t Bt[128 * GPT];

    const int t    = threadIdx.x;
    const int lane = t & 31;
    const int wid  = t >> 5;
    const int wm   = wid >> 2;
    const int wn   = wid & 3;
    const int g    = lane >> 2;
    const int tig  = lane & 3;
    const int hc   = blockIdx.x;
    const int h    = hc >> 5;
    const int c    = hc & 31;
    const int f0   = blockIdx.y * 128;
    const int pos0 = h * SEQ + c * CHK;

    float acc[4][4][4];
#pragma unroll
    for (int mt = 0; mt < 4; mt++)
#pragma unroll
        for (int nt = 0; nt < 4; nt++)
#pragma unroll
            for (int e = 0; e < 4; e++) acc[mt][nt][e] = 0.f;

    for (int m0 = 0; m0 < CHK; m0 += 32) {
#pragma unroll
        for (int r = 0; r < 4; r++) {
            int slot = t + r * 256;
            int m    = slot >> 5;
            int x4   = (slot & 31) << 2;
            float4 vv = *(const float4*)(vin + (size_t)(pos0 + m0 + m) * DD + x4);
            At[(x4+0)*GPT + m] = f2tf32(vv.x);
            At[(x4+1)*GPT + m] = f2tf32(vv.y);
            At[(x4+2)*GPT + m] = f2tf32(vv.z);
            At[(x4+3)*GPT + m] = f2tf32(vv.w);
            float4 kk = *(const float4*)(kphi + (size_t)(pos0 + m0 + m) * FF + f0 + x4);
            Bt[(x4+0)*GPT + m] = f2tf32(kk.x);
            Bt[(x4+1)*GPT + m] = f2tf32(kk.y);
            Bt[(x4+2)*GPT + m] = f2tf32(kk.z);
            Bt[(x4+3)*GPT + m] = f2tf32(kk.w);
        }
        __syncthreads();
#pragma unroll
        for (int ks = 0; ks < 4; ks++) {
            int kc = ks * 8 + tig;
            uint32_t af[4][4];
#pragma unroll
            for (int mt = 0; mt < 4; mt++) {
                int base = (wm * 64 + mt * 16 + g) * GPT + kc;
                af[mt][0] = At[base];
                af[mt][1] = At[base + 8 * GPT];
                af[mt][2] = At[base + 4];
                af[mt][3] = At[base + 8 * GPT + 4];
            }
            uint32_t bf[4][2];
#pragma unroll
            for (int nt = 0; nt < 4; nt++) {
                int base = (wn * 32 + nt * 8 + g) * GPT + kc;
                bf[nt][0] = Bt[base];
                bf[nt][1] = Bt[base + 4];
            }
#pragma unroll
            for (int mt = 0; mt < 4; mt++)
#pragma unroll
                for (int nt = 0; nt < 4; nt++)
                    mma8(acc[mt][nt], af[mt], bf[nt]);
        }
        __syncthreads();
    }

    float* S = P + ((size_t)(h * (NC + 1)) + (c + 1)) * FD;
#pragma unroll
    for (int mt = 0; mt < 4; mt++) {
#pragma unroll
        for (int nt = 0; nt < 4; nt++) {
            int d   = wm * 64 + mt * 16 + g;
            int col = f0 + wn * 32 + nt * 8 + tig * 2;
            float2 o01; o01.x = acc[mt][nt][0]; o01.y = acc[mt][nt][1];
            float2 o23; o23.x = acc[mt][nt][2]; o23.y = acc[mt][nt][3];
            *(float2*)(S + (size_t)d * FF + col)       = o01;
            *(float2*)(S + (size_t)(d + 8) * FF + col) = o23;
        }
    }
}

// ---------------------------------------------------------------------------
// Inclusive prefix over chunk slabs.
// ---------------------------------------------------------------------------
__global__ void prefix_kernel(float* __restrict__ P)
{
    const int h = blockIdx.y;
    const int e = blockIdx.x * 256 + threadIdx.x;
    float* base = P + (size_t)h * (NC + 1) * FD;
    base[e] = 0.f;
    float acc = 0.f;
#pragma unroll
    for (int c = 1; c <= NC; c++) {
        acc += base[(size_t)c * FD + e];
        base[(size_t)c * FD + e] = acc;
    }
}

// ---------------------------------------------------------------------------
// output_tc (fp16 mma): per (head, chunk) block, 256 thr, warp tile 64x32.
// Regions (u32): R0 = Qp[128][132] (persistent); R1 = Kp -> Vt -> B1;
//                R2 = Abuf -> B2.
// ---------------------------------------------------------------------------
#define OR0 0
#define OR1 (128*KP128)
#define OR2 (2*128*KP128)
#define OSM_BYTES (3*128*KP128*4)   // 202752

__global__ __launch_bounds__(256, 1) void output_tc(
    const float* __restrict__ qphi, const float* __restrict__ kphi,
    const float* __restrict__ vin,  const float* __restrict__ P,
    float* __restrict__ out)
{
    extern __shared__ uint32_t smx[];
    uint32_t* Qp   = smx + OR0;          // [128][KP128]
    uint32_t* Kp   = smx + OR1;          // stage1
    uint32_t* Vt   = smx + OR1;          // stage2 [128 d][KP64]
    uint32_t* B1   = smx + OR1;          // stage3 [128 d][KP128]
    uint32_t* Abuf = smx + OR2;          // stage2 [128 n][KP64]
    uint32_t* B2   = smx + OR2;          // stage3 [128 d][KP128]

    const int t    = threadIdx.x;
    const int lane = t & 31;
    const int wid  = t >> 5;
    const int wm   = wid >> 2;
    const int wn   = wid & 3;
    const int g    = lane >> 2;
    const int tig  = lane & 3;
    const int hc   = blockIdx.x;
    const int h    = hc >> 5;
    const int c    = hc & 31;
    const int pos0 = h * SEQ + c * CHK;

    // ---- stage Qp, Kp (full K=256 as pairs) ----
#pragma unroll
    for (int r = 0; r < 32; r++) {
        int slot = t + r * 256;
        int row  = slot >> 6;
        int p2   = (slot & 63) << 1;
        float4 qv = *(const float4*)(qphi + (size_t)(pos0 + row) * FF + (p2 << 1));
        Qp[row * KP128 + p2]     = f2h2(qv.x, qv.y);
        Qp[row * KP128 + p2 + 1] = f2h2(qv.z, qv.w);
        float4 kv = *(const float4*)(kphi + (size_t)(pos0 + row) * FF + (p2 << 1));
        Kp[row * KP128 + p2]     = f2h2(kv.x, kv.y);
        Kp[row * KP128 + p2 + 1] = f2h2(kv.z, kv.w);
    }
    __syncthreads();

    // ================= Stage 1: A = Qphi Kphi^T (K=256) =================
    float accA[4][4][4];
#pragma unroll
    for (int mt = 0; mt < 4; mt++)
#pragma unroll
        for (int nt = 0; nt < 4; nt++)
#pragma unroll
            for (int e = 0; e < 4; e++) accA[mt][nt][e] = 0.f;

    for (int ks = 0; ks < 16; ks++) {
        int kb = ks * 8 + tig;
        uint32_t af[4][4];
#pragma unroll
        for (int mt = 0; mt < 4; mt++) {
            int row = wm * 64 + mt * 16 + g;
            af[mt][0] = Qp[row * KP128 + kb];
            af[mt][1] = Qp[(row + 8) * KP128 + kb];
            af[mt][2] = Qp[row * KP128 + kb + 4];
            af[mt][3] = Qp[(row + 8) * KP128 + kb + 4];
        }
        uint32_t bf[4][2];
#pragma unroll
        for (int nt = 0; nt < 4; nt++) {
            int col = wn * 32 + nt * 8 + g;
            bf[nt][0] = Kp[col * KP128 + kb];
            bf[nt][1] = Kp[col * KP128 + kb + 4];
        }
#pragma unroll
        for (int mt = 0; mt < 4; mt++)
#pragma unroll
            for (int nt = 0; nt < 4; nt++)
                mma16(accA[mt][nt], af[mt], bf[nt]);
    }
    __syncthreads();   // Kp dead after this

    // ---- write A as fp16 pairs [n][m-pair]; pack V^T [d][m-pair] ----
#pragma unroll
    for (int mt = 0; mt < 4; mt++) {
#pragma unroll
        for (int nt = 0; nt < 4; nt++) {
            int n0 = wm * 64 + mt * 16 + g;
            int mp = wn * 16 + nt * 4 + tig;     // pair index (m0 = 2*mp)
            Abuf[n0 * KP64 + mp]       = f2h2(accA[mt][nt][0], accA[mt][nt][1]);
            Abuf[(n0 + 8) * KP64 + mp] = f2h2(accA[mt][nt][2], accA[mt][nt][3]);
        }
    }
#pragma unroll
    for (int r = 0; r < 8; r++) {
        int slot = t + r * 256;          // 2048 slots: 64 mp x 32 d4
        int mp   = slot >> 5;            // 0..63
        int d4   = (slot & 31) << 2;
        float4 va = *(const float4*)(vin + (size_t)(pos0 + 2 * mp) * DD + d4);
        float4 vb = *(const float4*)(vin + (size_t)(pos0 + 2 * mp + 1) * DD + d4);
        Vt[(d4+0) * KP64 + mp] = f2h2(va.x, vb.x);
        Vt[(d4+1) * KP64 + mp] = f2h2(va.y, vb.y);
        Vt[(d4+2) * KP64 + mp] = f2h2(va.z, vb.z);
        Vt[(d4+3) * KP64 + mp] = f2h2(va.w, vb.w);
    }
    __syncthreads();

    // ================= Stage 2: masked A @ V (K=m=128, 8 k-steps) =========
    float acc1[4][4][4], acc2[4][4][4];
#pragma unroll
    for (int mt = 0; mt < 4; mt++)
#pragma unroll
        for (int nt = 0; nt < 4; nt++)
#pragma unroll
            for (int e = 0; e < 4; e++) { acc1[mt][nt][e] = 0.f; acc2[mt][nt][e] = 0.f; }

#pragma unroll
    for (int ks = 0; ks < 8; ks++) {
        int kb = ks * 8 + tig;           // pair idx; m0 = 2*kb, m2 = 2*(kb+4)
        int m0 = kb * 2;
        int m2 = (kb + 4) * 2;
        uint32_t lo[4][4], up[4][4];
#pragma unroll
        for (int mt = 0; mt < 4; mt++) {
            int nA = wm * 64 + mt * 16 + g;
            int nB = nA + 8;
            uint32_t a0 = Abuf[nA * KP64 + kb];
            uint32_t a1 = Abuf[nB * KP64 + kb];
            uint32_t a2 = Abuf[nA * KP64 + kb + 4];
            uint32_t a3 = Abuf[nB * KP64 + kb + 4];
            lo[mt][0] = maskLE(a0, m0, nA);
            lo[mt][1] = maskLE(a1, m0, nB);
            lo[mt][2] = maskLE(a2, m2, nA);
            lo[mt][3] = maskLE(a3, m2, nB);
            up[mt][0] = maskGE(a0, m0, nA);
            up[mt][1] = maskGE(a1, m0, nB);
            up[mt][2] = maskGE(a2, m2, nA);
            up[mt][3] = maskGE(a3, m2, nB);
        }
        uint32_t bf[4][2];
#pragma unroll
        for (int nt = 0; nt < 4; nt++) {
            int col = wn * 32 + nt * 8 + g;
            bf[nt][0] = Vt[col * KP64 + kb];
            bf[nt][1] = Vt[col * KP64 + kb + 4];
        }
#pragma unroll
        for (int mt = 0; mt < 4; mt++)
#pragma unroll
            for (int nt = 0; nt < 4; nt++) {
                mma16(acc1[mt][nt], lo[mt], bf[nt]);
                mma16(acc2[mt][nt], up[mt], bf[nt]);
            }
    }
    __syncthreads();   // Vt/Abuf dead

    // ---- stage B1 = Wexc, B2 = Wtot - Winc as fp16 pairs [d][f-pair] ----
    const float* Pbase = P + (size_t)h * (NC + 1) * FD;
    const float* Pexc  = Pbase + (size_t)c * FD;
    const float* Pinc  = Pbase + (size_t)(c + 1) * FD;
    const float* Ptot  = Pbase + (size_t)NC * FD;

#pragma unroll
    for (int r = 0; r < 32; r++) {
        int slot = t + r * 256;
        int row  = slot >> 6;            // d
        int p2   = (slot & 63) << 1;     // f-pair
        size_t go = (size_t)row * FF + (p2 << 1);
        float4 ev = *(const float4*)(Pexc + go);
        B1[row * KP128 + p2]     = f2h2(ev.x, ev.y);
        B1[row * KP128 + p2 + 1] = f2h2(ev.z, ev.w);
        float4 iv = *(const float4*)(Pinc + go);
        float4 tv = *(const float4*)(Ptot + go);
        B2[row * KP128 + p2]     = f2h2(tv.x - iv.x, tv.y - iv.y);
        B2[row * KP128 + p2 + 1] = f2h2(tv.z - iv.z, tv.w - iv.w);
    }
    __syncthreads();

    // ================= Stage 3: Q @ Wexc / Q @ Wsuf (K=256) =================
    for (int ks = 0; ks < 16; ks++) {
        int kb = ks * 8 + tig;
        uint32_t af[4][4];
#pragma unroll
        for (int mt = 0; mt < 4; mt++) {
            int row = wm * 64 + mt * 16 + g;
            af[mt][0] = Qp[row * KP128 + kb];
            af[mt][1] = Qp[(row + 8) * KP128 + kb];
            af[mt][2] = Qp[row * KP128 + kb + 4];
            af[mt][3] = Qp[(row + 8) * KP128 + kb + 4];
        }
        uint32_t b1f[4][2], b2f[4][2];
#pragma unroll
        for (int nt = 0; nt < 4; nt++) {
            int col = wn * 32 + nt * 8 + g;
            b1f[nt][0] = B1[col * KP128 + kb];
            b1f[nt][1] = B1[col * KP128 + kb + 4];
            b2f[nt][0] = B2[col * KP128 + kb];
            b2f[nt][1] = B2[col * KP128 + kb + 4];
        }
#pragma unroll
        for (int mt = 0; mt < 4; mt++)
#pragma unroll
            for (int nt = 0; nt < 4; nt++) {
                mma16(acc1[mt][nt], af[mt], b1f[nt]);
                mma16(acc2[mt][nt], af[mt], b2f[nt]);
            }
    }

    // ================= Epilogue =================
#pragma unroll
    for (int mt = 0; mt < 4; mt++) {
#pragma unroll
        for (int nt = 0; nt < 4; nt++) {
            int n0  = wm * 64 + mt * 16 + g;
            int d0  = wn * 32 + nt * 8 + tig * 2;
            int posA = c * CHK + n0;
            int posB = posA + 8;
            float s1a = 1.f / (float)(posA + 1);
            float s2a = 1.f / (float)(SEQ - posA);
            float s1b = 1.f / (float)(posB + 1);
            float s2b = 1.f / (float)(SEQ - posB);
            float2 oA, oB;
            oA.x = acc1[mt][nt][0] * s1a + acc2[mt][nt][0] * s2a;
            oA.y = acc1[mt][nt][1] * s1a + acc2[mt][nt][1] * s2a;
            oB.x = acc1[mt][nt][2] * s1b + acc2[mt][nt][2] * s2b;
            oB.y = acc1[mt][nt][3] * s1b + acc2[mt][nt][3] * s2b;
            *(float2*)(out + (size_t)(pos0 + n0) * DD + d0)     = oA;
            *(float2*)(out + (size_t)(pos0 + n0 + 8) * DD + d0) = oB;
        }
    }
}

// ---------------------------------------------------------------------------
extern "C" void kernel_launch(void* const* d_in, const int* in_sizes, int n_in,
                              void* d_out, int out_size)
{
    (void)out_size;
    int big[3] = {0, 1, 2}; int nbig = 0;
    int iw1 = -1, iw2 = -1, ibias[2] = {-1, -1}; int nb = 0;
    for (int i = 0; i < n_in; i++) {
        long long s = in_sizes[i];
        if ((s == 12582912LL || s == 50331648LL) && nbig < 3) big[nbig++] = i;
        else if (s == 32768LL  || s == 131072LL) iw1 = i;
        else if (s == 65536LL  || s == 262144LL) iw2 = i;
        else if ((s == 256LL   || s == 1024LL) && nb < 2) ibias[nb++] = i;
    }
    if (nbig != 3 || iw1 < 0 || iw2 < 0 || nb != 2) {
        big[0] = 0; big[1] = 1; big[2] = 2;
        iw1 = 3; ibias[0] = 4; iw2 = 5; ibias[1] = 6;
    }
    const float *q, *k;
    if (big[0] == 0) {
        q = (const float*)d_in[big[0]];
        k = (const float*)d_in[big[1]];
    } else {
        k = (const float*)d_in[big[0]];
        q = (const float*)d_in[big[1]];
    }
    const float* v  = (const float*)d_in[big[2]];
    const float* w1 = (const float*)d_in[iw1];
    const float* b1 = (const float*)d_in[ibias[0]];
    const float* w2 = (const float*)d_in[iw2];
    const float* b2 = (const float*)d_in[ibias[1]];
    float* out = (float*)d_out;

    float *hq, *hk, *qphi, *kphi, *P, *w1t, *w2t;
    cudaGetSymbolAddress((void**)&hq,   g_hq);
    cudaGetSymbolAddress((void**)&hk,   g_hk);
    cudaGetSymbolAddress((void**)&qphi, g_qphi);
    cudaGetSymbolAddress((void**)&kphi, g_kphi);
    cudaGetSymbolAddress((void**)&P,    g_P);
    cudaGetSymbolAddress((void**)&w1t,  g_w1t);
    cudaGetSymbolAddress((void**)&w2t,  g_w2t);

    cudaFuncSetAttribute(phiA,
                         cudaFuncAttributeMaxDynamicSharedMemorySize, PA_BYTES);
    cudaFuncSetAttribute(phiB,
                         cudaFuncAttributeMaxDynamicSharedMemorySize, PB_BYTES);
    cudaFuncSetAttribute(output_tc,
                         cudaFuncAttributeMaxDynamicSharedMemorySize, OSM_BYTES);

    transpose_kernel<<<(DD*FF + 255)/256, 256>>>(w1, w1t, DD, FF);
    transpose_kernel<<<(FF*FF + 255)/256, 256>>>(w2, w2t, FF, FF);

    phiA<<<2 * NBLK, 256, PA_BYTES>>>(q, k, w1t, b1, hq, hk);
    phiB<<<2 * NBLK, 256, PB_BYTES>>>(hq, hk, w2t, b2, qphi, kphi);

    chunk_state_tc<<<dim3(BH * NC, 2), 256>>>(kphi, v, P);
    prefix_kernel<<<dim3(FD / 256, BH), 256>>>(P);

    output_tc<<<BH * NC, 256, OSM_BYTES>>>(qphi, kphi, v, P, out);
}

// round 14
// speedup vs baseline: 1.4618x; 1.1038x over previous
#include <cuda_runtime.h>
#include <cuda_fp16.h>
#include <cstdint>

// Problem constants
#define BH   24
#define SEQ  4096
#define DD   128
#define FF   256
#define FP   128   // FF/2 pairs
#define CHK  128
#define NC   32
#define ROWS (BH*SEQ)      // 98304
#define FD   (FF*DD)       // 32768
#define NBLK (ROWS/128)    // 768

// ---------------- scratch (device globals; no runtime allocation) ----------
// h / qphi / kphi stored as fp16 pairs (one u32 = 2 halfs along f)
__device__ uint32_t g_hq  [(size_t)ROWS * FP];
__device__ uint32_t g_hk  [(size_t)ROWS * FP];
__device__ uint32_t g_qphi[(size_t)ROWS * FP];
__device__ uint32_t g_kphi[(size_t)ROWS * FP];
__device__ float    g_P   [(size_t)BH * (NC+1) * FD];   // TRANSPOSED slabs [d][f], fp32
__device__ float    g_w1t [FF * DD];
__device__ float    g_w2t [FF * FF];

// strides in u32 (pair) units; mod 32 == 4 -> conflict-free frag reads
#define KP64  68
#define KP128 132
#define GPT 37

__device__ __forceinline__ uint32_t f2tf32(float x) {
    uint32_t r; asm("cvt.rna.tf32.f32 %0, %1;" : "=r"(r) : "f"(x)); return r;
}
__device__ __forceinline__ uint32_t f2h2(float a, float b) {
    __half2 h = __floats2half2_rn(a, b);
    return *reinterpret_cast<uint32_t*>(&h);
}
__device__ __forceinline__ void mma16(float* c, const uint32_t* a, const uint32_t* b) {
    asm volatile(
        "mma.sync.aligned.m16n8k16.row.col.f32.f16.f16.f32 "
        "{%0,%1,%2,%3}, {%4,%5,%6,%7}, {%8,%9}, {%0,%1,%2,%3};"
        : "+f"(c[0]), "+f"(c[1]), "+f"(c[2]), "+f"(c[3])
        : "r"(a[0]), "r"(a[1]), "r"(a[2]), "r"(a[3]), "r"(b[0]), "r"(b[1]));
}
__device__ __forceinline__ void mma8(float* c, const uint32_t* a, const uint32_t* b) {
    asm volatile(
        "mma.sync.aligned.m16n8k8.row.col.f32.tf32.tf32.f32 "
        "{%0,%1,%2,%3}, {%4,%5,%6,%7}, {%8,%9}, {%0,%1,%2,%3};"
        : "+f"(c[0]), "+f"(c[1]), "+f"(c[2]), "+f"(c[3])
        : "r"(a[0]), "r"(a[1]), "r"(a[2]), "r"(a[3]), "r"(b[0]), "r"(b[1]));
}
__device__ __forceinline__ uint32_t maskLE(uint32_t v, int m0, int n) {
    uint32_t m = (m0 <= n ? 0xFFFFu : 0u) | (m0 + 1 <= n ? 0xFFFF0000u : 0u);
    return v & m;
}
__device__ __forceinline__ uint32_t maskGE(uint32_t v, int m0, int n) {
    uint32_t m = (m0 >= n ? 0xFFFFu : 0u) | (m0 + 1 >= n ? 0xFFFF0000u : 0u);
    return v & m;
}

// ---------------------------------------------------------------------------
// phiA: h = silu(X @ w1t^T + b1), h stored fp16. 256 thr, warp tile 64x32,
// two n-passes. X tile + full w1t resident; one sync.
// ---------------------------------------------------------------------------
#define PA_XS    0
#define PA_WS    (128*KP64)
#define PA_BYTES ((128*KP64 + 256*KP64) * 4)   // 104448

__global__ __launch_bounds__(256, 1) void phiA(
    const float* __restrict__ Xq, const float* __restrict__ Xk,
    const float* __restrict__ w1t, const float* __restrict__ b1,
    uint32_t* __restrict__ Hq, uint32_t* __restrict__ Hk)
{
    extern __shared__ uint32_t smx[];
    uint32_t* Xs = smx + PA_XS;
    uint32_t* Ws = smx + PA_WS;

    const int t    = threadIdx.x;
    const int lane = t & 31;
    const int wid  = t >> 5;
    const int wm   = wid >> 2;
    const int wn   = wid & 3;
    const int g    = lane >> 2;
    const int tig  = lane & 3;
    const int bx   = blockIdx.x;
    const bool isK = (bx >= NBLK);
    const int row0 = (isK ? bx - NBLK : bx) * 128;
    const float* X = isK ? Xk : Xq;
    uint32_t* H    = isK ? Hk : Hq;

    // Xs: 128 rows x 64 pairs -> 4096 float4 slots (2 pairs each)
#pragma unroll
    for (int r = 0; r < 16; r++) {
        int slot = t + r * 256;
        int row  = slot >> 5;
        int p2   = (slot & 31) << 1;
        float4 v = *(const float4*)(X + (size_t)(row0 + row) * DD + (p2 << 1));
        Xs[row * KP64 + p2]     = f2h2(v.x, v.y);
        Xs[row * KP64 + p2 + 1] = f2h2(v.z, v.w);
    }
    // Ws: 256 rows x 64 pairs -> 8192 float4 slots
#pragma unroll
    for (int r = 0; r < 32; r++) {
        int slot = t + r * 256;
        int row  = slot >> 5;
        int p2   = (slot & 31) << 1;
        float4 v = *(const float4*)(w1t + (size_t)row * DD + (p2 << 1));
        Ws[row * KP64 + p2]     = f2h2(v.x, v.y);
        Ws[row * KP64 + p2 + 1] = f2h2(v.z, v.w);
    }
    __syncthreads();

#pragma unroll
    for (int np = 0; np < 2; np++) {
        float acc[4][4][4];
#pragma unroll
        for (int mt = 0; mt < 4; mt++)
#pragma unroll
            for (int nt = 0; nt < 4; nt++)
#pragma unroll
                for (int e = 0; e < 4; e++) acc[mt][nt][e] = 0.f;

#pragma unroll
        for (int ks = 0; ks < 8; ks++) {
            int kb = ks * 8 + tig;
            uint32_t af[4][4];
#pragma unroll
            for (int mt = 0; mt < 4; mt++) {
                int row = wm * 64 + mt * 16 + g;
                af[mt][0] = Xs[row * KP64 + kb];
                af[mt][1] = Xs[(row + 8) * KP64 + kb];
                af[mt][2] = Xs[row * KP64 + kb + 4];
                af[mt][3] = Xs[(row + 8) * KP64 + kb + 4];
            }
            uint32_t bf[4][2];
#pragma unroll
            for (int nt = 0; nt < 4; nt++) {
                int col = np * 128 + wn * 32 + nt * 8 + g;
                bf[nt][0] = Ws[col * KP64 + kb];
                bf[nt][1] = Ws[col * KP64 + kb + 4];
            }
#pragma unroll
            for (int mt = 0; mt < 4; mt++)
#pragma unroll
                for (int nt = 0; nt < 4; nt++)
                    mma16(acc[mt][nt], af[mt], bf[nt]);
        }
#pragma unroll
        for (int mt = 0; mt < 4; mt++) {
#pragma unroll
            for (int nt = 0; nt < 4; nt++) {
                int row  = row0 + wm * 64 + mt * 16 + g;
                int col  = np * 128 + wn * 32 + nt * 8 + tig * 2;
                int pcol = col >> 1;
                float b0v = b1[col], b1v = b1[col + 1];
                float x0 = acc[mt][nt][0] + b0v;
                float x1 = acc[mt][nt][1] + b1v;
                float x2 = acc[mt][nt][2] + b0v;
                float x3 = acc[mt][nt][3] + b1v;
                x0 = x0 / (1.f + __expf(-x0));
                x1 = x1 / (1.f + __expf(-x1));
                x2 = x2 / (1.f + __expf(-x2));
                x3 = x3 / (1.f + __expf(-x3));
                H[(size_t)row * FP + pcol]       = f2h2(x0, x1);
                H[(size_t)(row + 8) * FP + pcol] = f2h2(x2, x3);
            }
        }
    }
}

// ---------------------------------------------------------------------------
// phiB: phi = h @ w2t^T + b2, fp16 in/out. 256 thr, warp tile 64x32,
// two n-passes, full K=256 resident.
// ---------------------------------------------------------------------------
#define PB_HS    0
#define PB_WS    (128*KP128)
#define PB_BYTES ((128*KP128 + 256*KP128) * 4)   // 202752

__global__ __launch_bounds__(256, 1) void phiB(
    const uint32_t* __restrict__ Hq, const uint32_t* __restrict__ Hk,
    const float* __restrict__ w2t, const float* __restrict__ b2,
    uint32_t* __restrict__ Cq, uint32_t* __restrict__ Ck)
{
    extern __shared__ uint32_t smx[];
    uint32_t* Hs = smx + PB_HS;
    uint32_t* Ws = smx + PB_WS;

    const int t    = threadIdx.x;
    const int lane = t & 31;
    const int wid  = t >> 5;
    const int wm   = wid >> 2;
    const int wn   = wid & 3;
    const int g    = lane >> 2;
    const int tig  = lane & 3;
    const int bx   = blockIdx.x;
    const bool isK = (bx >= NBLK);
    const int row0 = (isK ? bx - NBLK : bx) * 128;
    const uint32_t* H = isK ? Hk : Hq;
    uint32_t* C       = isK ? Ck : Cq;

    // stage Hs [128 rows][128 pairs] direct copy: 4096 uint4 slots (4 pairs)
#pragma unroll
    for (int r = 0; r < 16; r++) {
        int slot = t + r * 256;
        int row  = slot >> 5;
        int p4   = (slot & 31) << 2;
        uint4 v = *(const uint4*)(H + (size_t)(row0 + row) * FP + p4);
        Hs[row * KP128 + p4]     = v.x;
        Hs[row * KP128 + p4 + 1] = v.y;
        Hs[row * KP128 + p4 + 2] = v.z;
        Hs[row * KP128 + p4 + 3] = v.w;
    }
    // stage Ws [256 rows][128 pairs] from fp32 w2t:
    // 256*128 = 32768 pairs -> 16384 float4 loads (2 pairs each) -> r<64
    // (FIXED from R13: was r<32 with wrong row mapping -> half tile garbage)
#pragma unroll
    for (int r = 0; r < 64; r++) {
        int slot = t + r * 256;          // 0..16383
        int row  = slot >> 6;            // 0..255
        int p2   = (slot & 63) << 1;     // 0..126
        float4 v = *(const float4*)(w2t + (size_t)row * FF + (p2 << 1));
        Ws[row * KP128 + p2]     = f2h2(v.x, v.y);
        Ws[row * KP128 + p2 + 1] = f2h2(v.z, v.w);
    }
    __syncthreads();

#pragma unroll
    for (int np = 0; np < 2; np++) {
        float acc[4][4][4];
#pragma unroll
        for (int mt = 0; mt < 4; mt++)
#pragma unroll
            for (int nt = 0; nt < 4; nt++)
#pragma unroll
                for (int e = 0; e < 4; e++) acc[mt][nt][e] = 0.f;

        for (int ks = 0; ks < 16; ks++) {
            int kb = ks * 8 + tig;
            uint32_t af[4][4];
#pragma unroll
            for (int mt = 0; mt < 4; mt++) {
                int row = wm * 64 + mt * 16 + g;
                af[mt][0] = Hs[row * KP128 + kb];
                af[mt][1] = Hs[(row + 8) * KP128 + kb];
                af[mt][2] = Hs[row * KP128 + kb + 4];
                af[mt][3] = Hs[(row + 8) * KP128 + kb + 4];
            }
            uint32_t bf[4][2];
#pragma unroll
            for (int nt = 0; nt < 4; nt++) {
                int col = np * 128 + wn * 32 + nt * 8 + g;
                bf[nt][0] = Ws[col * KP128 + kb];
                bf[nt][1] = Ws[col * KP128 + kb + 4];
            }
#pragma unroll
            for (int mt = 0; mt < 4; mt++)
#pragma unroll
                for (int nt = 0; nt < 4; nt++)
                    mma16(acc[mt][nt], af[mt], bf[nt]);
        }
#pragma unroll
        for (int mt = 0; mt < 4; mt++) {
#pragma unroll
            for (int nt = 0; nt < 4; nt++) {
                int row  = row0 + wm * 64 + mt * 16 + g;
                int col  = np * 128 + wn * 32 + nt * 8 + tig * 2;
                int pcol = col >> 1;
                float b0v = b2[col], b1v = b2[col + 1];
                C[(size_t)row * FP + pcol] =
                    f2h2(acc[mt][nt][0] + b0v, acc[mt][nt][1] + b1v);
                C[(size_t)(row + 8) * FP + pcol] =
                    f2h2(acc[mt][nt][2] + b0v, acc[mt][nt][3] + b1v);
            }
        }
    }
}

// ---------------------------------------------------------------------------
__global__ void transpose_kernel(const float* __restrict__ W,
                                 float* __restrict__ Wt, int K, int N)
{
    int idx = blockIdx.x * blockDim.x + threadIdx.x;
    if (idx >= K * N) return;
    int kk = idx / N;
    int n  = idx - kk * N;
    Wt[(size_t)n * K + kk] = W[idx];
}

// ---------------------------------------------------------------------------
// chunk_state (tf32): S^T[d][f] = sum_m V[m][d] * Kphi[m][f]; kphi fp16 in.
// ---------------------------------------------------------------------------
__global__ __launch_bounds__(256) void chunk_state_tc(
    const uint32_t* __restrict__ kphi, const float* __restrict__ vin,
    float* __restrict__ P)
{
    __shared__ uint32_t At[128 * GPT];
    __shared__ uint32_t Bt[128 * GPT];

    const int t    = threadIdx.x;
    const int lane = t & 31;
    const int wid  = t >> 5;
    const int wm   = wid >> 2;
    const int wn   = wid & 3;
    const int g    = lane >> 2;
    const int tig  = lane & 3;
    const int hc   = blockIdx.x;
    const int h    = hc >> 5;
    const int c    = hc & 31;
    const int f0   = blockIdx.y * 128;
    const int fp0  = f0 >> 1;
    const int pos0 = h * SEQ + c * CHK;

    float acc[4][4][4];
#pragma unroll
    for (int mt = 0; mt < 4; mt++)
#pragma unroll
        for (int nt = 0; nt < 4; nt++)
#pragma unroll
            for (int e = 0; e < 4; e++) acc[mt][nt][e] = 0.f;

    for (int m0 = 0; m0 < CHK; m0 += 32) {
        // V: 32 rows x 128 d fp32 -> At[d][m], 1024 f4 slots
#pragma unroll
        for (int r = 0; r < 4; r++) {
            int slot = t + r * 256;
            int m    = slot >> 5;
            int x4   = (slot & 31) << 2;
            float4 vv = *(const float4*)(vin + (size_t)(pos0 + m0 + m) * DD + x4);
            At[(x4+0)*GPT + m] = f2tf32(vv.x);
            At[(x4+1)*GPT + m] = f2tf32(vv.y);
            At[(x4+2)*GPT + m] = f2tf32(vv.z);
            At[(x4+3)*GPT + m] = f2tf32(vv.w);
        }
        // K: 32 rows x 64 pairs fp16 -> Bt[f][m], 512 uint4 slots (4 pairs)
#pragma unroll
        for (int r = 0; r < 2; r++) {
            int slot = t + r * 256;
            int m    = slot >> 4;            // 0..31
            int p4   = (slot & 15) << 2;     // 0..60
            uint4 kv = *(const uint4*)(kphi + (size_t)(pos0 + m0 + m) * FP + fp0 + p4);
            uint32_t pk[4] = {kv.x, kv.y, kv.z, kv.w};
#pragma unroll
            for (int j = 0; j < 4; j++) {
                __half2 hp = *reinterpret_cast<__half2*>(&pk[j]);
                float lo = __low2float(hp), hi = __high2float(hp);
                int f = (p4 + j) * 2;
                Bt[(f)   * GPT + m] = f2tf32(lo);
                Bt[(f+1) * GPT + m] = f2tf32(hi);
            }
        }
        __syncthreads();
#pragma unroll
        for (int ks = 0; ks < 4; ks++) {
            int kc = ks * 8 + tig;
            uint32_t af[4][4];
#pragma unroll
            for (int mt = 0; mt < 4; mt++) {
                int base = (wm * 64 + mt * 16 + g) * GPT + kc;
                af[mt][0] = At[base];
                af[mt][1] = At[base + 8 * GPT];
                af[mt][2] = At[base + 4];
                af[mt][3] = At[base + 8 * GPT + 4];
            }
            uint32_t bf[4][2];
#pragma unroll
            for (int nt = 0; nt < 4; nt++) {
                int base = (wn * 32 + nt * 8 + g) * GPT + kc;
                bf[nt][0] = Bt[base];
                bf[nt][1] = Bt[base + 4];
            }
#pragma unroll
            for (int mt = 0; mt < 4; mt++)
#pragma unroll
                for (int nt = 0; nt < 4; nt++)
                    mma8(acc[mt][nt], af[mt], bf[nt]);
        }
        __syncthreads();
    }

    float* S = P + ((size_t)(h * (NC + 1)) + (c + 1)) * FD;
#pragma unroll
    for (int mt = 0; mt < 4; mt++) {
#pragma unroll
        for (int nt = 0; nt < 4; nt++) {
            int d   = wm * 64 + mt * 16 + g;
            int col = f0 + wn * 32 + nt * 8 + tig * 2;
            float2 o01; o01.x = acc[mt][nt][0]; o01.y = acc[mt][nt][1];
            float2 o23; o23.x = acc[mt][nt][2]; o23.y = acc[mt][nt][3];
            *(float2*)(S + (size_t)d * FF + col)       = o01;
            *(float2*)(S + (size_t)(d + 8) * FF + col) = o23;
        }
    }
}

// ---------------------------------------------------------------------------
__global__ void prefix_kernel(float* __restrict__ P)
{
    const int h = blockIdx.y;
    const int e = blockIdx.x * 256 + threadIdx.x;
    float* base = P + (size_t)h * (NC + 1) * FD;
    base[e] = 0.f;
    float acc = 0.f;
#pragma unroll
    for (int c = 1; c <= NC; c++) {
        acc += base[(size_t)c * FD + e];
        base[(size_t)c * FD + e] = acc;
    }
}

// ---------------------------------------------------------------------------
// output_tc (fp16 mma): qphi/kphi fp16 pairs in gmem.
// ---------------------------------------------------------------------------
#define OR0 0
#define OR1 (128*KP128)
#define OR2 (2*128*KP128)
#define OSM_BYTES (3*128*KP128*4)   // 202752

__global__ __launch_bounds__(256, 1) void output_tc(
    const uint32_t* __restrict__ qphi, const uint32_t* __restrict__ kphi,
    const float* __restrict__ vin,  const float* __restrict__ P,
    float* __restrict__ out)
{
    extern __shared__ uint32_t smx[];
    uint32_t* Qp   = smx + OR0;
    uint32_t* Kp   = smx + OR1;
    uint32_t* Vt   = smx + OR1;
    uint32_t* B1   = smx + OR1;
    uint32_t* Abuf = smx + OR2;
    uint32_t* B2   = smx + OR2;

    const int t    = threadIdx.x;
    const int lane = t & 31;
    const int wid  = t >> 5;
    const int wm   = wid >> 2;
    const int wn   = wid & 3;
    const int g    = lane >> 2;
    const int tig  = lane & 3;
    const int hc   = blockIdx.x;
    const int h    = hc >> 5;
    const int c    = hc & 31;
    const int pos0 = h * SEQ + c * CHK;

    // ---- stage Qp, Kp: 128 rows x 128 pairs = 4096 uint4 slots each ----
#pragma unroll
    for (int r = 0; r < 16; r++) {
        int slot = t + r * 256;
        int row  = slot >> 5;
        int p4   = (slot & 31) << 2;
        uint4 qv = *(const uint4*)(qphi + (size_t)(pos0 + row) * FP + p4);
        Qp[row * KP128 + p4]     = qv.x;
        Qp[row * KP128 + p4 + 1] = qv.y;
        Qp[row * KP128 + p4 + 2] = qv.z;
        Qp[row * KP128 + p4 + 3] = qv.w;
        uint4 kv = *(const uint4*)(kphi + (size_t)(pos0 + row) * FP + p4);
        Kp[row * KP128 + p4]     = kv.x;
        Kp[row * KP128 + p4 + 1] = kv.y;
        Kp[row * KP128 + p4 + 2] = kv.z;
        Kp[row * KP128 + p4 + 3] = kv.w;
    }
    __syncthreads();

    // ================= Stage 1: A = Qphi Kphi^T (K=256) =================
    float accA[4][4][4];
#pragma unroll
    for (int mt = 0; mt < 4; mt++)
#pragma unroll
        for (int nt = 0; nt < 4; nt++)
#pragma unroll
            for (int e = 0; e < 4; e++) accA[mt][nt][e] = 0.f;

    for (int ks = 0; ks < 16; ks++) {
        int kb = ks * 8 + tig;
        uint32_t af[4][4];
#pragma unroll
        for (int mt = 0; mt < 4; mt++) {
            int row = wm * 64 + mt * 16 + g;
            af[mt][0] = Qp[row * KP128 + kb];
            af[mt][1] = Qp[(row + 8) * KP128 + kb];
            af[mt][2] = Qp[row * KP128 + kb + 4];
            af[mt][3] = Qp[(row + 8) * KP128 + kb + 4];
        }
        uint32_t bf[4][2];
#pragma unroll
        for (int nt = 0; nt < 4; nt++) {
            int col = wn * 32 + nt * 8 + g;
            bf[nt][0] = Kp[col * KP128 + kb];
            bf[nt][1] = Kp[col * KP128 + kb + 4];
        }
#pragma unroll
        for (int mt = 0; mt < 4; mt++)
#pragma unroll
            for (int nt = 0; nt < 4; nt++)
                mma16(accA[mt][nt], af[mt], bf[nt]);
    }
    __syncthreads();

    // ---- write A as fp16 pairs [n][m-pair]; pack V^T [d][m-pair] ----
#pragma unroll
    for (int mt = 0; mt < 4; mt++) {
#pragma unroll
        for (int nt = 0; nt < 4; nt++) {
            int n0 = wm * 64 + mt * 16 + g;
            int mp = wn * 16 + nt * 4 + tig;
            Abuf[n0 * KP64 + mp]       = f2h2(accA[mt][nt][0], accA[mt][nt][1]);
            Abuf[(n0 + 8) * KP64 + mp] = f2h2(accA[mt][nt][2], accA[mt][nt][3]);
        }
    }
#pragma unroll
    for (int r = 0; r < 8; r++) {
        int slot = t + r * 256;
        int mp   = slot >> 5;
        int d4   = (slot & 31) << 2;
        float4 va = *(const float4*)(vin + (size_t)(pos0 + 2 * mp) * DD + d4);
        float4 vb = *(const float4*)(vin + (size_t)(pos0 + 2 * mp + 1) * DD + d4);
        Vt[(d4+0) * KP64 + mp] = f2h2(va.x, vb.x);
        Vt[(d4+1) * KP64 + mp] = f2h2(va.y, vb.y);
        Vt[(d4+2) * KP64 + mp] = f2h2(va.z, vb.z);
        Vt[(d4+3) * KP64 + mp] = f2h2(va.w, vb.w);
    }
    __syncthreads();

    // ================= Stage 2: masked A @ V =================
    float acc1[4][4][4], acc2[4][4][4];
#pragma unroll
    for (int mt = 0; mt < 4; mt++)
#pragma unroll
        for (int nt = 0; nt < 4; nt++)
#pragma unroll
            for (int e = 0; e < 4; e++) { acc1[mt][nt][e] = 0.f; acc2[mt][nt][e] = 0.f; }

#pragma unroll
    for (int ks = 0; ks < 8; ks++) {
        int kb = ks * 8 + tig;
        int m0 = kb * 2;
        int m2 = (kb + 4) * 2;
        uint32_t lo[4][4], up[4][4];
#pragma unroll
        for (int mt = 0; mt < 4; mt++) {
            int nA = wm * 64 + mt * 16 + g;
            int nB = nA + 8;
            uint32_t a0 = Abuf[nA * KP64 + kb];
            uint32_t a1 = Abuf[nB * KP64 + kb];
            uint32_t a2 = Abuf[nA * KP64 + kb + 4];
            uint32_t a3 = Abuf[nB * KP64 + kb + 4];
            lo[mt][0] = maskLE(a0, m0, nA);
            lo[mt][1] = maskLE(a1, m0, nB);
            lo[mt][2] = maskLE(a2, m2, nA);
            lo[mt][3] = maskLE(a3, m2, nB);
            up[mt][0] = maskGE(a0, m0, nA);
            up[mt][1] = maskGE(a1, m0, nB);
            up[mt][2] = maskGE(a2, m2, nA);
            up[mt][3] = maskGE(a3, m2, nB);
        }
        uint32_t bf[4][2];
#pragma unroll
        for (int nt = 0; nt < 4; nt++) {
            int col = wn * 32 + nt * 8 + g;
            bf[nt][0] = Vt[col * KP64 + kb];
            bf[nt][1] = Vt[col * KP64 + kb + 4];
        }
#pragma unroll
        for (int mt = 0; mt < 4; mt++)
#pragma unroll
            for (int nt = 0; nt < 4; nt++) {
                mma16(acc1[mt][nt], lo[mt], bf[nt]);
                mma16(acc2[mt][nt], up[mt], bf[nt]);
            }
    }
    __syncthreads();

    // ---- stage B1 = Wexc, B2 = Wtot - Winc as fp16 pairs [d][f-pair] ----
    const float* Pbase = P + (size_t)h * (NC + 1) * FD;
    const float* Pexc  = Pbase + (size_t)c * FD;
    const float* Pinc  = Pbase + (size_t)(c + 1) * FD;
    const float* Ptot  = Pbase + (size_t)NC * FD;

#pragma unroll
    for (int r = 0; r < 32; r++) {
        int slot = t + r * 256;          // 8192 slots: 128 rows x 64 f4 loads
        int row  = slot >> 6;
        int p2   = (slot & 63) << 1;
        size_t go = (size_t)row * FF + (p2 << 1);
        float4 ev = *(const float4*)(Pexc + go);
        B1[row * KP128 + p2]     = f2h2(ev.x, ev.y);
        B1[row * KP128 + p2 + 1] = f2h2(ev.z, ev.w);
        float4 iv = *(const float4*)(Pinc + go);
        float4 tv = *(const float4*)(Ptot + go);
        B2[row * KP128 + p2]     = f2h2(tv.x - iv.x, tv.y - iv.y);
        B2[row * KP128 + p2 + 1] = f2h2(tv.z - iv.z, tv.w - iv.w);
    }
    __syncthreads();

    // ================= Stage 3: Q @ Wexc / Q @ Wsuf (K=256) =================
    for (int ks = 0; ks < 16; ks++) {
        int kb = ks * 8 + tig;
        uint32_t af[4][4];
#pragma unroll
        for (int mt = 0; mt < 4; mt++) {
            int row = wm * 64 + mt * 16 + g;
            af[mt][0] = Qp[row * KP128 + kb];
            af[mt][1] = Qp[(row + 8) * KP128 + kb];
            af[mt][2] = Qp[row * KP128 + kb + 4];
            af[mt][3] = Qp[(row + 8) * KP128 + kb + 4];
        }
        uint32_t b1f[4][2], b2f[4][2];
#pragma unroll
        for (int nt = 0; nt < 4; nt++) {
            int col = wn * 32 + nt * 8 + g;
            b1f[nt][0] = B1[col * KP128 + kb];
            b1f[nt][1] = B1[col * KP128 + kb + 4];
            b2f[nt][0] = B2[col * KP128 + kb];
            b2f[nt][1] = B2[col * KP128 + kb + 4];
        }
#pragma unroll
        for (int mt = 0; mt < 4; mt++)
#pragma unroll
            for (int nt = 0; nt < 4; nt++) {
                mma16(acc1[mt][nt], af[mt], b1f[nt]);
                mma16(acc2[mt][nt], af[mt], b2f[nt]);
            }
    }

    // ================= Epilogue =================
#pragma unroll
    for (int mt = 0; mt < 4; mt++) {
#pragma unroll
        for (int nt = 0; nt < 4; nt++) {
            int n0  = wm * 64 + mt * 16 + g;
            int d0  = wn * 32 + nt * 8 + tig * 2;
            int posA = c * CHK + n0;
            int posB = posA + 8;
            float s1a = 1.f / (float)(posA + 1);
            float s2a = 1.f / (float)(SEQ - posA);
            float s1b = 1.f / (float)(posB + 1);
            float s2b = 1.f / (float)(SEQ - posB);
            float2 oA, oB;
            oA.x = acc1[mt][nt][0] * s1a + acc2[mt][nt][0] * s2a;
            oA.y = acc1[mt][nt][1] * s1a + acc2[mt][nt][1] * s2a;
            oB.x = acc1[mt][nt][2] * s1b + acc2[mt][nt][2] * s2b;
            oB.y = acc1[mt][nt][3] * s1b + acc2[mt][nt][3] * s2b;
            *(float2*)(out + (size_t)(pos0 + n0) * DD + d0)     = oA;
            *(float2*)(out + (size_t)(pos0 + n0 + 8) * DD + d0) = oB;
        }
    }
}

// ---------------------------------------------------------------------------
extern "C" void kernel_launch(void* const* d_in, const int* in_sizes, int n_in,
                              void* d_out, int out_size)
{
    (void)out_size;
    int big[3] = {0, 1, 2}; int nbig = 0;
    int iw1 = -1, iw2 = -1, ibias[2] = {-1, -1}; int nb = 0;
    for (int i = 0; i < n_in; i++) {
        long long s = in_sizes[i];
        if ((s == 12582912LL || s == 50331648LL) && nbig < 3) big[nbig++] = i;
        else if (s == 32768LL  || s == 131072LL) iw1 = i;
        else if (s == 65536LL  || s == 262144LL) iw2 = i;
        else if ((s == 256LL   || s == 1024LL) && nb < 2) ibias[nb++] = i;
    }
    if (nbig != 3 || iw1 < 0 || iw2 < 0 || nb != 2) {
        big[0] = 0; big[1] = 1; big[2] = 2;
        iw1 = 3; ibias[0] = 4; iw2 = 5; ibias[1] = 6;
    }
    const float *q, *k;
    if (big[0] == 0) {
        q = (const float*)d_in[big[0]];
        k = (const float*)d_in[big[1]];
    } else {
        k = (const float*)d_in[big[0]];
        q = (const float*)d_in[big[1]];
    }
    const float* v  = (const float*)d_in[big[2]];
    const float* w1 = (const float*)d_in[iw1];
    const float* b1 = (const float*)d_in[ibias[0]];
    const float* w2 = (const float*)d_in[iw2];
    const float* b2 = (const float*)d_in[ibias[1]];
    float* out = (float*)d_out;

    uint32_t *hq, *hk, *qphi, *kphi;
    float *P, *w1t, *w2t;
    cudaGetSymbolAddress((void**)&hq,   g_hq);
    cudaGetSymbolAddress((void**)&hk,   g_hk);
    cudaGetSymbolAddress((void**)&qphi, g_qphi);
    cudaGetSymbolAddress((void**)&kphi, g_kphi);
    cudaGetSymbolAddress((void**)&P,    g_P);
    cudaGetSymbolAddress((void**)&w1t,  g_w1t);
    cudaGetSymbolAddress((void**)&w2t,  g_w2t);

    cudaFuncSetAttribute(phiA,
                         cudaFuncAttributeMaxDynamicSharedMemorySize, PA_BYTES);
    cudaFuncSetAttribute(phiB,
                         cudaFuncAttributeMaxDynamicSharedMemorySize, PB_BYTES);
    cudaFuncSetAttribute(output_tc,
                         cudaFuncAttributeMaxDynamicSharedMemorySize, OSM_BYTES);

    transpose_kernel<<<(DD*FF + 255)/256, 256>>>(w1, w1t, DD, FF);
    transpose_kernel<<<(FF*FF + 255)/256, 256>>>(w2, w2t, FF, FF);

    phiA<<<2 * NBLK, 256, PA_BYTES>>>(q, k, w1t, b1, hq, hk);
    phiB<<<2 * NBLK, 256, PB_BYTES>>>(hq, hk, w2t, b2, qphi, kphi);

    chunk_state_tc<<<dim3(BH * NC, 2), 256>>>(kphi, v, P);
    prefix_kernel<<<dim3(FD / 256, BH), 256>>>(P);

    output_tc<<<BH * NC, 256, OSM_BYTES>>>(qphi, kphi, v, P, out);
}

// round 15
// speedup vs baseline: 1.5892x; 1.0872x over previous
#include <cuda_runtime.h>
#include <cuda_fp16.h>
#include <cstdint>

// Problem constants
#define BH   24
#define SEQ  4096
#define DD   128
#define FF   256
#define FP   128   // FF/2 pairs
#define CHK  128
#define NC   32
#define FD   (FF*DD)       // 32768
#define FDP  (FD/2)        // 16384 pairs per slab
#define FPP  128           // pairs per d-row in a slab
#define ROWS (BH*SEQ)      // 98304
#define NBLK (ROWS/128)    // 768

// ---------------- scratch (device globals; no runtime allocation) ----------
__device__ uint32_t g_hq  [(size_t)ROWS * FP];
__device__ uint32_t g_hk  [(size_t)ROWS * FP];
__device__ uint32_t g_qphi[(size_t)ROWS * FP];
__device__ uint32_t g_kphi[(size_t)ROWS * FP];
__device__ uint32_t g_P   [(size_t)BH * (NC+1) * FDP];  // fp16-pair slabs [d][f-pair]
__device__ float    g_w1t [FF * DD];
__device__ float    g_w2t [FF * FF];

// strides in u32 (pair) units; mod 32 == 4 -> conflict-free frag reads
#define KP64  68
#define KP128 132

__device__ __forceinline__ uint32_t f2h2(float a, float b) {
    __half2 h = __floats2half2_rn(a, b);
    return *reinterpret_cast<uint32_t*>(&h);
}
__device__ __forceinline__ uint32_t hsub2u(uint32_t a, uint32_t b) {
    __half2 r = __hsub2(*reinterpret_cast<__half2*>(&a),
                        *reinterpret_cast<__half2*>(&b));
    return *reinterpret_cast<uint32_t*>(&r);
}
__device__ __forceinline__ void mma16(float* c, const uint32_t* a, const uint32_t* b) {
    asm volatile(
        "mma.sync.aligned.m16n8k16.row.col.f32.f16.f16.f32 "
        "{%0,%1,%2,%3}, {%4,%5,%6,%7}, {%8,%9}, {%0,%1,%2,%3};"
        : "+f"(c[0]), "+f"(c[1]), "+f"(c[2]), "+f"(c[3])
        : "r"(a[0]), "r"(a[1]), "r"(a[2]), "r"(a[3]), "r"(b[0]), "r"(b[1]));
}
__device__ __forceinline__ uint32_t maskLE(uint32_t v, int m0, int n) {
    uint32_t m = (m0 <= n ? 0xFFFFu : 0u) | (m0 + 1 <= n ? 0xFFFF0000u : 0u);
    return v & m;
}
__device__ __forceinline__ uint32_t maskGE(uint32_t v, int m0, int n) {
    uint32_t m = (m0 >= n ? 0xFFFFu : 0u) | (m0 + 1 >= n ? 0xFFFF0000u : 0u);
    return v & m;
}

// ---------------------------------------------------------------------------
// phiA (verified R14): h = silu(X @ w1t^T + b1), fp16 out.
// ---------------------------------------------------------------------------
#define PA_XS    0
#define PA_WS    (128*KP64)
#define PA_BYTES ((128*KP64 + 256*KP64) * 4)   // 104448

__global__ __launch_bounds__(256, 1) void phiA(
    const float* __restrict__ Xq, const float* __restrict__ Xk,
    const float* __restrict__ w1t, const float* __restrict__ b1,
    uint32_t* __restrict__ Hq, uint32_t* __restrict__ Hk)
{
    extern __shared__ uint32_t smx[];
    uint32_t* Xs = smx + PA_XS;
    uint32_t* Ws = smx + PA_WS;

    const int t    = threadIdx.x;
    const int lane = t & 31;
    const int wid  = t >> 5;
    const int wm   = wid >> 2;
    const int wn   = wid & 3;
    const int g    = lane >> 2;
    const int tig  = lane & 3;
    const int bx   = blockIdx.x;
    const bool isK = (bx >= NBLK);
    const int row0 = (isK ? bx - NBLK : bx) * 128;
    const float* X = isK ? Xk : Xq;
    uint32_t* H    = isK ? Hk : Hq;

#pragma unroll
    for (int r = 0; r < 16; r++) {
        int slot = t + r * 256;
        int row  = slot >> 5;
        int p2   = (slot & 31) << 1;
        float4 v = *(const float4*)(X + (size_t)(row0 + row) * DD + (p2 << 1));
        Xs[row * KP64 + p2]     = f2h2(v.x, v.y);
        Xs[row * KP64 + p2 + 1] = f2h2(v.z, v.w);
    }
#pragma unroll
    for (int r = 0; r < 32; r++) {
        int slot = t + r * 256;
        int row  = slot >> 5;
        int p2   = (slot & 31) << 1;
        float4 v = *(const float4*)(w1t + (size_t)row * DD + (p2 << 1));
        Ws[row * KP64 + p2]     = f2h2(v.x, v.y);
        Ws[row * KP64 + p2 + 1] = f2h2(v.z, v.w);
    }
    __syncthreads();

#pragma unroll
    for (int np = 0; np < 2; np++) {
        float acc[4][4][4];
#pragma unroll
        for (int mt = 0; mt < 4; mt++)
#pragma unroll
            for (int nt = 0; nt < 4; nt++)
#pragma unroll
                for (int e = 0; e < 4; e++) acc[mt][nt][e] = 0.f;

#pragma unroll
        for (int ks = 0; ks < 8; ks++) {
            int kb = ks * 8 + tig;
            uint32_t af[4][4];
#pragma unroll
            for (int mt = 0; mt < 4; mt++) {
                int row = wm * 64 + mt * 16 + g;
                af[mt][0] = Xs[row * KP64 + kb];
                af[mt][1] = Xs[(row + 8) * KP64 + kb];
                af[mt][2] = Xs[row * KP64 + kb + 4];
                af[mt][3] = Xs[(row + 8) * KP64 + kb + 4];
            }
            uint32_t bf[4][2];
#pragma unroll
            for (int nt = 0; nt < 4; nt++) {
                int col = np * 128 + wn * 32 + nt * 8 + g;
                bf[nt][0] = Ws[col * KP64 + kb];
                bf[nt][1] = Ws[col * KP64 + kb + 4];
            }
#pragma unroll
            for (int mt = 0; mt < 4; mt++)
#pragma unroll
                for (int nt = 0; nt < 4; nt++)
                    mma16(acc[mt][nt], af[mt], bf[nt]);
        }
#pragma unroll
        for (int mt = 0; mt < 4; mt++) {
#pragma unroll
            for (int nt = 0; nt < 4; nt++) {
                int row  = row0 + wm * 64 + mt * 16 + g;
                int col  = np * 128 + wn * 32 + nt * 8 + tig * 2;
                int pcol = col >> 1;
                float b0v = b1[col], b1v = b1[col + 1];
                float x0 = acc[mt][nt][0] + b0v;
                float x1 = acc[mt][nt][1] + b1v;
                float x2 = acc[mt][nt][2] + b0v;
                float x3 = acc[mt][nt][3] + b1v;
                x0 = x0 / (1.f + __expf(-x0));
                x1 = x1 / (1.f + __expf(-x1));
                x2 = x2 / (1.f + __expf(-x2));
                x3 = x3 / (1.f + __expf(-x3));
                H[(size_t)row * FP + pcol]       = f2h2(x0, x1);
                H[(size_t)(row + 8) * FP + pcol] = f2h2(x2, x3);
            }
        }
    }
}

// ---------------------------------------------------------------------------
// phiB (verified R14): phi = h @ w2t^T + b2, fp16 in/out.
// ---------------------------------------------------------------------------
#define PB_HS    0
#define PB_WS    (128*KP128)
#define PB_BYTES ((128*KP128 + 256*KP128) * 4)   // 202752

__global__ __launch_bounds__(256, 1) void phiB(
    const uint32_t* __restrict__ Hq, const uint32_t* __restrict__ Hk,
    const float* __restrict__ w2t, const float* __restrict__ b2,
    uint32_t* __restrict__ Cq, uint32_t* __restrict__ Ck)
{
    extern __shared__ uint32_t smx[];
    uint32_t* Hs = smx + PB_HS;
    uint32_t* Ws = smx + PB_WS;

    const int t    = threadIdx.x;
    const int lane = t & 31;
    const int wid  = t >> 5;
    const int wm   = wid >> 2;
    const int wn   = wid & 3;
    const int g    = lane >> 2;
    const int tig  = lane & 3;
    const int bx   = blockIdx.x;
    const bool isK = (bx >= NBLK);
    const int row0 = (isK ? bx - NBLK : bx) * 128;
    const uint32_t* H = isK ? Hk : Hq;
    uint32_t* C       = isK ? Ck : Cq;

#pragma unroll
    for (int r = 0; r < 16; r++) {
        int slot = t + r * 256;
        int row  = slot >> 5;
        int p4   = (slot & 31) << 2;
        uint4 v = *(const uint4*)(H + (size_t)(row0 + row) * FP + p4);
        Hs[row * KP128 + p4]     = v.x;
        Hs[row * KP128 + p4 + 1] = v.y;
        Hs[row * KP128 + p4 + 2] = v.z;
        Hs[row * KP128 + p4 + 3] = v.w;
    }
#pragma unroll
    for (int r = 0; r < 64; r++) {
        int slot = t + r * 256;
        int row  = slot >> 6;
        int p2   = (slot & 63) << 1;
        float4 v = *(const float4*)(w2t + (size_t)row * FF + (p2 << 1));
        Ws[row * KP128 + p2]     = f2h2(v.x, v.y);
        Ws[row * KP128 + p2 + 1] = f2h2(v.z, v.w);
    }
    __syncthreads();

#pragma unroll
    for (int np = 0; np < 2; np++) {
        float acc[4][4][4];
#pragma unroll
        for (int mt = 0; mt < 4; mt++)
#pragma unroll
            for (int nt = 0; nt < 4; nt++)
#pragma unroll
                for (int e = 0; e < 4; e++) acc[mt][nt][e] = 0.f;

        for (int ks = 0; ks < 16; ks++) {
            int kb = ks * 8 + tig;
            uint32_t af[4][4];
#pragma unroll
            for (int mt = 0; mt < 4; mt++) {
                int row = wm * 64 + mt * 16 + g;
                af[mt][0] = Hs[row * KP128 + kb];
                af[mt][1] = Hs[(row + 8) * KP128 + kb];
                af[mt][2] = Hs[row * KP128 + kb + 4];
                af[mt][3] = Hs[(row + 8) * KP128 + kb + 4];
            }
            uint32_t bf[4][2];
#pragma unroll
            for (int nt = 0; nt < 4; nt++) {
                int col = np * 128 + wn * 32 + nt * 8 + g;
                bf[nt][0] = Ws[col * KP128 + kb];
                bf[nt][1] = Ws[col * KP128 + kb + 4];
            }
#pragma unroll
            for (int mt = 0; mt < 4; mt++)
#pragma unroll
                for (int nt = 0; nt < 4; nt++)
                    mma16(acc[mt][nt], af[mt], bf[nt]);
        }
#pragma unroll
        for (int mt = 0; mt < 4; mt++) {
#pragma unroll
            for (int nt = 0; nt < 4; nt++) {
                int row  = row0 + wm * 64 + mt * 16 + g;
                int col  = np * 128 + wn * 32 + nt * 8 + tig * 2;
                int pcol = col >> 1;
                float b0v = b2[col], b1v = b2[col + 1];
                C[(size_t)row * FP + pcol] =
                    f2h2(acc[mt][nt][0] + b0v, acc[mt][nt][1] + b1v);
                C[(size_t)(row + 8) * FP + pcol] =
                    f2h2(acc[mt][nt][2] + b0v, acc[mt][nt][3] + b1v);
            }
        }
    }
}

// ---------------------------------------------------------------------------
__global__ void transpose_kernel(const float* __restrict__ W,
                                 float* __restrict__ Wt, int K, int N)
{
    int idx = blockIdx.x * blockDim.x + threadIdx.x;
    if (idx >= K * N) return;
    int kk = idx / N;
    int n  = idx - kk * N;
    Wt[(size_t)n * K + kk] = W[idx];
}

// ---------------------------------------------------------------------------
// chunk_state (fp16 mma): S^T[d][f] = sum_m V[m][d] * Kphi[m][f].
// Whole m=128 resident (64 m-pairs); one sync; fp16 slab write.
// grid (BH*NC, 2): blockIdx.y = f-block of 128. Warp tile 64(d) x 32(f).
// ---------------------------------------------------------------------------
#define CS_AT    0
#define CS_BT    (128*KP64)
#define CS_BYTES (2*128*KP64*4)   // 69632

__global__ __launch_bounds__(256, 1) void chunk_state_fp16(
    const uint32_t* __restrict__ kphi, const float* __restrict__ vin,
    uint32_t* __restrict__ P)
{
    extern __shared__ uint32_t smx[];
    uint32_t* At = smx + CS_AT;    // [128 d][64 m-pairs]
    uint32_t* Bt = smx + CS_BT;    // [128 f-local][64 m-pairs]

    const int t    = threadIdx.x;
    const int lane = t & 31;
    const int wid  = t >> 5;
    const int wm   = wid >> 2;
    const int wn   = wid & 3;
    const int g    = lane >> 2;
    const int tig  = lane & 3;
    const int hc   = blockIdx.x;
    const int h    = hc >> 5;
    const int c    = hc & 31;
    const int f0   = blockIdx.y * 128;
    const int fp0p = blockIdx.y * 64;      // pair offset in kphi row
    const int pos0 = h * SEQ + c * CHK;

    // At: V^T packed along m-pairs: 64 mp x 32 d4-slots = 2048 slots
#pragma unroll
    for (int r = 0; r < 8; r++) {
        int slot = t + r * 256;
        int mp   = slot >> 5;
        int d4   = (slot & 31) << 2;
        float4 va = *(const float4*)(vin + (size_t)(pos0 + 2 * mp) * DD + d4);
        float4 vb = *(const float4*)(vin + (size_t)(pos0 + 2 * mp + 1) * DD + d4);
        At[(d4+0) * KP64 + mp] = f2h2(va.x, vb.x);
        At[(d4+1) * KP64 + mp] = f2h2(va.y, vb.y);
        At[(d4+2) * KP64 + mp] = f2h2(va.z, vb.z);
        At[(d4+3) * KP64 + mp] = f2h2(va.w, vb.w);
    }
    // Bt: K^T packed along m-pairs: 64 mp x 64 f-pairs = 4096 slots
#pragma unroll
    for (int r = 0; r < 16; r++) {
        int slot = t + r * 256;
        int mp   = slot >> 6;            // 0..63
        int fp   = slot & 63;            // f-pair within block
        uint32_t ua = kphi[(size_t)(pos0 + 2 * mp) * FP + fp0p + fp];
        uint32_t ub = kphi[(size_t)(pos0 + 2 * mp + 1) * FP + fp0p + fp];
        __half2 ha = *reinterpret_cast<__half2*>(&ua);
        __half2 hb = *reinterpret_cast<__half2*>(&ub);
        __half2 lo = __halves2half2(__low2half(ha),  __low2half(hb));
        __half2 hi = __halves2half2(__high2half(ha), __high2half(hb));
        Bt[(2*fp)   * KP64 + mp] = *reinterpret_cast<uint32_t*>(&lo);
        Bt[(2*fp+1) * KP64 + mp] = *reinterpret_cast<uint32_t*>(&hi);
    }
    __syncthreads();

    float acc[4][4][4];
#pragma unroll
    for (int mt = 0; mt < 4; mt++)
#pragma unroll
        for (int nt = 0; nt < 4; nt++)
#pragma unroll
            for (int e = 0; e < 4; e++) acc[mt][nt][e] = 0.f;

#pragma unroll
    for (int ks = 0; ks < 8; ks++) {
        int kb = ks * 8 + tig;
        uint32_t af[4][4];
#pragma unroll
        for (int mt = 0; mt < 4; mt++) {
            int row = wm * 64 + mt * 16 + g;     // d
            af[mt][0] = At[row * KP64 + kb];
            af[mt][1] = At[(row + 8) * KP64 + kb];
            af[mt][2] = At[row * KP64 + kb + 4];
            af[mt][3] = At[(row + 8) * KP64 + kb + 4];
        }
        uint32_t bf[4][2];
#pragma unroll
        for (int nt = 0; nt < 4; nt++) {
            int col = wn * 32 + nt * 8 + g;      // f local
            bf[nt][0] = Bt[col * KP64 + kb];
            bf[nt][1] = Bt[col * KP64 + kb + 4];
        }
#pragma unroll
        for (int mt = 0; mt < 4; mt++)
#pragma unroll
            for (int nt = 0; nt < 4; nt++)
                mma16(acc[mt][nt], af[mt], bf[nt]);
    }

    uint32_t* S = P + ((size_t)(h * (NC + 1)) + (c + 1)) * FDP;
#pragma unroll
    for (int mt = 0; mt < 4; mt++) {
#pragma unroll
        for (int nt = 0; nt < 4; nt++) {
            int d    = wm * 64 + mt * 16 + g;
            int col  = f0 + wn * 32 + nt * 8 + tig * 2;
            int pcol = col >> 1;
            S[(size_t)d * FPP + pcol]       = f2h2(acc[mt][nt][0], acc[mt][nt][1]);
            S[(size_t)(d + 8) * FPP + pcol] = f2h2(acc[mt][nt][2], acc[mt][nt][3]);
        }
    }
}

// ---------------------------------------------------------------------------
// prefix over fp16 slabs; fp32 accumulation per element-pair.
// ---------------------------------------------------------------------------
__global__ void prefix_kernel(uint32_t* __restrict__ P)
{
    const int h = blockIdx.y;
    const int e = blockIdx.x * 256 + threadIdx.x;   // < FDP
    uint32_t* base = P + (size_t)h * (NC + 1) * FDP;
    base[e] = 0u;
    float a0 = 0.f, a1 = 0.f;
#pragma unroll
    for (int c = 1; c <= NC; c++) {
        uint32_t u = base[(size_t)c * FDP + e];
        __half2 hv = *reinterpret_cast<__half2*>(&u);
        a0 += __low2float(hv);
        a1 += __high2float(hv);
        base[(size_t)c * FDP + e] = f2h2(a0, a1);
    }
}

// ---------------------------------------------------------------------------
// output_tc (fp16 mma, verified R14 structure; P now fp16 pairs).
// ---------------------------------------------------------------------------
#define OR0 0
#define OR1 (128*KP128)
#define OR2 (2*128*KP128)
#define OSM_BYTES (3*128*KP128*4)   // 202752

__global__ __launch_bounds__(256, 1) void output_tc(
    const uint32_t* __restrict__ qphi, const uint32_t* __restrict__ kphi,
    const float* __restrict__ vin,  const uint32_t* __restrict__ P,
    float* __restrict__ out)
{
    extern __shared__ uint32_t smx[];
    uint32_t* Qp   = smx + OR0;
    uint32_t* Kp   = smx + OR1;
    uint32_t* Vt   = smx + OR1;
    uint32_t* B1   = smx + OR1;
    uint32_t* Abuf = smx + OR2;
    uint32_t* B2   = smx + OR2;

    const int t    = threadIdx.x;
    const int lane = t & 31;
    const int wid  = t >> 5;
    const int wm   = wid >> 2;
    const int wn   = wid & 3;
    const int g    = lane >> 2;
    const int tig  = lane & 3;
    const int hc   = blockIdx.x;
    const int h    = hc >> 5;
    const int c    = hc & 31;
    const int pos0 = h * SEQ + c * CHK;

#pragma unroll
    for (int r = 0; r < 16; r++) {
        int slot = t + r * 256;
        int row  = slot >> 5;
        int p4   = (slot & 31) << 2;
        uint4 qv = *(const uint4*)(qphi + (size_t)(pos0 + row) * FP + p4);
        Qp[row * KP128 + p4]     = qv.x;
        Qp[row * KP128 + p4 + 1] = qv.y;
        Qp[row * KP128 + p4 + 2] = qv.z;
        Qp[row * KP128 + p4 + 3] = qv.w;
        uint4 kv = *(const uint4*)(kphi + (size_t)(pos0 + row) * FP + p4);
        Kp[row * KP128 + p4]     = kv.x;
        Kp[row * KP128 + p4 + 1] = kv.y;
        Kp[row * KP128 + p4 + 2] = kv.z;
        Kp[row * KP128 + p4 + 3] = kv.w;
    }
    __syncthreads();

    // ================= Stage 1: A = Qphi Kphi^T (K=256) =================
    float accA[4][4][4];
#pragma unroll
    for (int mt = 0; mt < 4; mt++)
#pragma unroll
        for (int nt = 0; nt < 4; nt++)
#pragma unroll
            for (int e = 0; e < 4; e++) accA[mt][nt][e] = 0.f;

    for (int ks = 0; ks < 16; ks++) {
        int kb = ks * 8 + tig;
        uint32_t af[4][4];
#pragma unroll
        for (int mt = 0; mt < 4; mt++) {
            int row = wm * 64 + mt * 16 + g;
            af[mt][0] = Qp[row * KP128 + kb];
            af[mt][1] = Qp[(row + 8) * KP128 + kb];
            af[mt][2] = Qp[row * KP128 + kb + 4];
            af[mt][3] = Qp[(row + 8) * KP128 + kb + 4];
        }
        uint32_t bf[4][2];
#pragma unroll
        for (int nt = 0; nt < 4; nt++) {
            int col = wn * 32 + nt * 8 + g;
            bf[nt][0] = Kp[col * KP128 + kb];
            bf[nt][1] = Kp[col * KP128 + kb + 4];
        }
#pragma unroll
        for (int mt = 0; mt < 4; mt++)
#pragma unroll
            for (int nt = 0; nt < 4; nt++)
                mma16(accA[mt][nt], af[mt], bf[nt]);
    }
    __syncthreads();

    // ---- write A as fp16 pairs [n][m-pair]; pack V^T [d][m-pair] ----
#pragma unroll
    for (int mt = 0; mt < 4; mt++) {
#pragma unroll
        for (int nt = 0; nt < 4; nt++) {
            int n0 = wm * 64 + mt * 16 + g;
            int mp = wn * 16 + nt * 4 + tig;
            Abuf[n0 * KP64 + mp]       = f2h2(accA[mt][nt][0], accA[mt][nt][1]);
            Abuf[(n0 + 8) * KP64 + mp] = f2h2(accA[mt][nt][2], accA[mt][nt][3]);
        }
    }
#pragma unroll
    for (int r = 0; r < 8; r++) {
        int slot = t + r * 256;
        int mp   = slot >> 5;
        int d4   = (slot & 31) << 2;
        float4 va = *(const float4*)(vin + (size_t)(pos0 + 2 * mp) * DD + d4);
        float4 vb = *(const float4*)(vin + (size_t)(pos0 + 2 * mp + 1) * DD + d4);
        Vt[(d4+0) * KP64 + mp] = f2h2(va.x, vb.x);
        Vt[(d4+1) * KP64 + mp] = f2h2(va.y, vb.y);
        Vt[(d4+2) * KP64 + mp] = f2h2(va.z, vb.z);
        Vt[(d4+3) * KP64 + mp] = f2h2(va.w, vb.w);
    }
    __syncthreads();

    // ================= Stage 2: masked A @ V =================
    float acc1[4][4][4], acc2[4][4][4];
#pragma unroll
    for (int mt = 0; mt < 4; mt++)
#pragma unroll
        for (int nt = 0; nt < 4; nt++)
#pragma unroll
            for (int e = 0; e < 4; e++) { acc1[mt][nt][e] = 0.f; acc2[mt][nt][e] = 0.f; }

#pragma unroll
    for (int ks = 0; ks < 8; ks++) {
        int kb = ks * 8 + tig;
        int m0 = kb * 2;
        int m2 = (kb + 4) * 2;
        uint32_t lo[4][4], up[4][4];
#pragma unroll
        for (int mt = 0; mt < 4; mt++) {
            int nA = wm * 64 + mt * 16 + g;
            int nB = nA + 8;
            uint32_t a0 = Abuf[nA * KP64 + kb];
            uint32_t a1 = Abuf[nB * KP64 + kb];
            uint32_t a2 = Abuf[nA * KP64 + kb + 4];
            uint32_t a3 = Abuf[nB * KP64 + kb + 4];
            lo[mt][0] = maskLE(a0, m0, nA);
            lo[mt][1] = maskLE(a1, m0, nB);
            lo[mt][2] = maskLE(a2, m2, nA);
            lo[mt][3] = maskLE(a3, m2, nB);
            up[mt][0] = maskGE(a0, m0, nA);
            up[mt][1] = maskGE(a1, m0, nB);
            up[mt][2] = maskGE(a2, m2, nA);
            up[mt][3] = maskGE(a3, m2, nB);
        }
        uint32_t bf[4][2];
#pragma unroll
        for (int nt = 0; nt < 4; nt++) {
            int col = wn * 32 + nt * 8 + g;
            bf[nt][0] = Vt[col * KP64 + kb];
            bf[nt][1] = Vt[col * KP64 + kb + 4];
        }
#pragma unroll
        for (int mt = 0; mt < 4; mt++)
#pragma unroll
            for (int nt = 0; nt < 4; nt++) {
                mma16(acc1[mt][nt], lo[mt], bf[nt]);
                mma16(acc2[mt][nt], up[mt], bf[nt]);
            }
    }
    __syncthreads();

    // ---- stage B1 = Wexc, B2 = Wtot - Winc (fp16 pairs, direct) ----
    const uint32_t* Pbase = P + (size_t)h * (NC + 1) * FDP;
    const uint32_t* Pexc  = Pbase + (size_t)c * FDP;
    const uint32_t* Pinc  = Pbase + (size_t)(c + 1) * FDP;
    const uint32_t* Ptot  = Pbase + (size_t)NC * FDP;

#pragma unroll
    for (int r = 0; r < 16; r++) {
        int slot = t + r * 256;          // 4096 uint4 slots: 128 d x 32
        int row  = slot >> 5;
        int p4   = (slot & 31) << 2;
        size_t go = (size_t)row * FPP + p4;
        uint4 ev = *(const uint4*)(Pexc + go);
        B1[row * KP128 + p4]     = ev.x;
        B1[row * KP128 + p4 + 1] = ev.y;
        B1[row * KP128 + p4 + 2] = ev.z;
        B1[row * KP128 + p4 + 3] = ev.w;
        uint4 iv = *(const uint4*)(Pinc + go);
        uint4 tv = *(const uint4*)(Ptot + go);
        B2[row * KP128 + p4]     = hsub2u(tv.x, iv.x);
        B2[row * KP128 + p4 + 1] = hsub2u(tv.y, iv.y);
        B2[row * KP128 + p4 + 2] = hsub2u(tv.z, iv.z);
        B2[row * KP128 + p4 + 3] = hsub2u(tv.w, iv.w);
    }
    __syncthreads();

    // ================= Stage 3: Q @ Wexc / Q @ Wsuf (K=256) =================
    for (int ks = 0; ks < 16; ks++) {
        int kb = ks * 8 + tig;
        uint32_t af[4][4];
#pragma unroll
        for (int mt = 0; mt < 4; mt++) {
            int row = wm * 64 + mt * 16 + g;
            af[mt][0] = Qp[row * KP128 + kb];
            af[mt][1] = Qp[(row + 8) * KP128 + kb];
            af[mt][2] = Qp[row * KP128 + kb + 4];
            af[mt][3] = Qp[(row + 8) * KP128 + kb + 4];
        }
        uint32_t b1f[4][2], b2f[4][2];
#pragma unroll
        for (int nt = 0; nt < 4; nt++) {
            int col = wn * 32 + nt * 8 + g;
            b1f[nt][0] = B1[col * KP128 + kb];
            b1f[nt][1] = B1[col * KP128 + kb + 4];
            b2f[nt][0] = B2[col * KP128 + kb];
            b2f[nt][1] = B2[col * KP128 + kb + 4];
        }
#pragma unroll
        for (int mt = 0; mt < 4; mt++)
#pragma unroll
            for (int nt = 0; nt < 4; nt++) {
                mma16(acc1[mt][nt], af[mt], b1f[nt]);
                mma16(acc2[mt][nt], af[mt], b2f[nt]);
            }
    }

    // ================= Epilogue =================
#pragma unroll
    for (int mt = 0; mt < 4; mt++) {
#pragma unroll
        for (int nt = 0; nt < 4; nt++) {
            int n0  = wm * 64 + mt * 16 + g;
            int d0  = wn * 32 + nt * 8 + tig * 2;
            int posA = c * CHK + n0;
            int posB = posA + 8;
            float s1a = 1.f / (float)(posA + 1);
            float s2a = 1.f / (float)(SEQ - posA);
            float s1b = 1.f / (float)(posB + 1);
            float s2b = 1.f / (float)(SEQ - posB);
            float2 oA, oB;
            oA.x = acc1[mt][nt][0] * s1a + acc2[mt][nt][0] * s2a;
            oA.y = acc1[mt][nt][1] * s1a + acc2[mt][nt][1] * s2a;
            oB.x = acc1[mt][nt][2] * s1b + acc2[mt][nt][2] * s2b;
            oB.y = acc1[mt][nt][3] * s1b + acc2[mt][nt][3] * s2b;
            *(float2*)(out + (size_t)(pos0 + n0) * DD + d0)     = oA;
            *(float2*)(out + (size_t)(pos0 + n0 + 8) * DD + d0) = oB;
        }
    }
}

// ---------------------------------------------------------------------------
extern "C" void kernel_launch(void* const* d_in, const int* in_sizes, int n_in,
                              void* d_out, int out_size)
{
    (void)out_size;
    int big[3] = {0, 1, 2}; int nbig = 0;
    int iw1 = -1, iw2 = -1, ibias[2] = {-1, -1}; int nb = 0;
    for (int i = 0; i < n_in; i++) {
        long long s = in_sizes[i];
        if ((s == 12582912LL || s == 50331648LL) && nbig < 3) big[nbig++] = i;
        else if (s == 32768LL  || s == 131072LL) iw1 = i;
        else if (s == 65536LL  || s == 262144LL) iw2 = i;
        else if ((s == 256LL   || s == 1024LL) && nb < 2) ibias[nb++] = i;
    }
    if (nbig != 3 || iw1 < 0 || iw2 < 0 || nb != 2) {
        big[0] = 0; big[1] = 1; big[2] = 2;
        iw1 = 3; ibias[0] = 4; iw2 = 5; ibias[1] = 6;
    }
    const float *q, *k;
    if (big[0] == 0) {
        q = (const float*)d_in[big[0]];
        k = (const float*)d_in[big[1]];
    } else {
        k = (const float*)d_in[big[0]];
        q = (const float*)d_in[big[1]];
    }
    const float* v  = (const float*)d_in[big[2]];
    const float* w1 = (const float*)d_in[iw1];
    const float* b1 = (const float*)d_in[ibias[0]];
    const float* w2 = (const float*)d_in[iw2];
    const float* b2 = (const float*)d_in[ibias[1]];
    float* out = (float*)d_out;

    uint32_t *hq, *hk, *qphi, *kphi, *P;
    float *w1t, *w2t;
    cudaGetSymbolAddress((void**)&hq,   g_hq);
    cudaGetSymbolAddress((void**)&hk,   g_hk);
    cudaGetSymbolAddress((void**)&qphi, g_qphi);
    cudaGetSymbolAddress((void**)&kphi, g_kphi);
    cudaGetSymbolAddress((void**)&P,    g_P);
    cudaGetSymbolAddress((void**)&w1t,  g_w1t);
    cudaGetSymbolAddress((void**)&w2t,  g_w2t);

    cudaFuncSetAttribute(phiA,
                         cudaFuncAttributeMaxDynamicSharedMemorySize, PA_BYTES);
    cudaFuncSetAttribute(phiB,
                         cudaFuncAttributeMaxDynamicSharedMemorySize, PB_BYTES);
    cudaFuncSetAttribute(chunk_state_fp16,
                         cudaFuncAttributeMaxDynamicSharedMemorySize, CS_BYTES);
    cudaFuncSetAttribute(output_tc,
                         cudaFuncAttributeMaxDynamicSharedMemorySize, OSM_BYTES);

    transpose_kernel<<<(DD*FF + 255)/256, 256>>>(w1, w1t, DD, FF);
    transpose_kernel<<<(FF*FF + 255)/256, 256>>>(w2, w2t, FF, FF);

    phiA<<<2 * NBLK, 256, PA_BYTES>>>(q, k, w1t, b1, hq, hk);
    phiB<<<2 * NBLK, 256, PB_BYTES>>>(hq, hk, w2t, b2, qphi, kphi);

    chunk_state_fp16<<<dim3(BH * NC, 2), 256, CS_BYTES>>>(kphi, v, P);
    prefix_kernel<<<dim3(FDP / 256, BH), 256>>>(P);

    output_tc<<<BH * NC, 256, OSM_BYTES>>>(qphi, kphi, v, P, out);
}

// round 16
// speedup vs baseline: 1.7767x; 1.1180x over previous
#include <cuda_runtime.h>
#include <cuda_fp16.h>
#include <cstdint>

// Problem constants
#define BH   24
#define SEQ  4096
#define DD   128
#define FF   256
#define FP   128   // FF/2 pairs
#define CHK  128
#define NC   32
#define FD   (FF*DD)       // 32768
#define FDP  (FD/2)        // 16384 pairs per slab
#define FPP  128           // pairs per d-row in a slab
#define ROWS (BH*SEQ)      // 98304
#define NBLK (ROWS/128)    // 768

// ---------------- scratch (device globals; no runtime allocation) ----------
__device__ uint32_t g_hq  [(size_t)ROWS * FP];
__device__ uint32_t g_hk  [(size_t)ROWS * FP];
__device__ uint32_t g_qphi[(size_t)ROWS * FP];
__device__ uint32_t g_kphi[(size_t)ROWS * FP];
__device__ uint32_t g_P   [(size_t)BH * (NC+1) * FDP];  // fp16-pair slabs [d][f-pair]
__device__ float    g_w1t [FF * DD];
__device__ float    g_w2t [FF * FF];

#define KP64  68
#define KP128 132

__device__ __forceinline__ uint32_t f2h2(float a, float b) {
    __half2 h = __floats2half2_rn(a, b);
    return *reinterpret_cast<uint32_t*>(&h);
}
__device__ __forceinline__ uint32_t hsub2u(uint32_t a, uint32_t b) {
    __half2 r = __hsub2(*reinterpret_cast<__half2*>(&a),
                        *reinterpret_cast<__half2*>(&b));
    return *reinterpret_cast<uint32_t*>(&r);
}
__device__ __forceinline__ void mma16(float* c, const uint32_t* a, const uint32_t* b) {
    asm volatile(
        "mma.sync.aligned.m16n8k16.row.col.f32.f16.f16.f32 "
        "{%0,%1,%2,%3}, {%4,%5,%6,%7}, {%8,%9}, {%0,%1,%2,%3};"
        : "+f"(c[0]), "+f"(c[1]), "+f"(c[2]), "+f"(c[3])
        : "r"(a[0]), "r"(a[1]), "r"(a[2]), "r"(a[3]), "r"(b[0]), "r"(b[1]));
}
__device__ __forceinline__ uint32_t maskLE(uint32_t v, int m0, int n) {
    uint32_t m = (m0 <= n ? 0xFFFFu : 0u) | (m0 + 1 <= n ? 0xFFFF0000u : 0u);
    return v & m;
}
__device__ __forceinline__ uint32_t maskGE(uint32_t v, int m0, int n) {
    uint32_t m = (m0 >= n ? 0xFFFFu : 0u) | (m0 + 1 >= n ? 0xFFFF0000u : 0u);
    return v & m;
}

// ---------------------------------------------------------------------------
// phiA: h = silu(X @ w1t^T + b1), fp16 out. 104.4 KB smem -> 2 CTAs/SM.
// ---------------------------------------------------------------------------
#define PA_XS    0
#define PA_WS    (128*KP64)
#define PA_BYTES ((128*KP64 + 256*KP64) * 4)   // 104448

__global__ __launch_bounds__(256, 2) void phiA(
    const float* __restrict__ Xq, const float* __restrict__ Xk,
    const float* __restrict__ w1t, const float* __restrict__ b1,
    uint32_t* __restrict__ Hq, uint32_t* __restrict__ Hk)
{
    extern __shared__ uint32_t smx[];
    uint32_t* Xs = smx + PA_XS;
    uint32_t* Ws = smx + PA_WS;

    const int t    = threadIdx.x;
    const int lane = t & 31;
    const int wid  = t >> 5;
    const int wm   = wid >> 2;
    const int wn   = wid & 3;
    const int g    = lane >> 2;
    const int tig  = lane & 3;
    const int bx   = blockIdx.x;
    const bool isK = (bx >= NBLK);
    const int row0 = (isK ? bx - NBLK : bx) * 128;
    const float* X = isK ? Xk : Xq;
    uint32_t* H    = isK ? Hk : Hq;

#pragma unroll
    for (int r = 0; r < 16; r++) {
        int slot = t + r * 256;
        int row  = slot >> 5;
        int p2   = (slot & 31) << 1;
        float4 v = *(const float4*)(X + (size_t)(row0 + row) * DD + (p2 << 1));
        Xs[row * KP64 + p2]     = f2h2(v.x, v.y);
        Xs[row * KP64 + p2 + 1] = f2h2(v.z, v.w);
    }
#pragma unroll
    for (int r = 0; r < 32; r++) {
        int slot = t + r * 256;
        int row  = slot >> 5;
        int p2   = (slot & 31) << 1;
        float4 v = *(const float4*)(w1t + (size_t)row * DD + (p2 << 1));
        Ws[row * KP64 + p2]     = f2h2(v.x, v.y);
        Ws[row * KP64 + p2 + 1] = f2h2(v.z, v.w);
    }
    __syncthreads();

#pragma unroll
    for (int np = 0; np < 2; np++) {
        float acc[4][4][4];
#pragma unroll
        for (int mt = 0; mt < 4; mt++)
#pragma unroll
            for (int nt = 0; nt < 4; nt++)
#pragma unroll
                for (int e = 0; e < 4; e++) acc[mt][nt][e] = 0.f;

#pragma unroll 4
        for (int ks = 0; ks < 8; ks++) {
            int kb = ks * 8 + tig;
            uint32_t af[4][4];
#pragma unroll
            for (int mt = 0; mt < 4; mt++) {
                int row = wm * 64 + mt * 16 + g;
                af[mt][0] = Xs[row * KP64 + kb];
                af[mt][1] = Xs[(row + 8) * KP64 + kb];
                af[mt][2] = Xs[row * KP64 + kb + 4];
                af[mt][3] = Xs[(row + 8) * KP64 + kb + 4];
            }
            uint32_t bf[4][2];
#pragma unroll
            for (int nt = 0; nt < 4; nt++) {
                int col = np * 128 + wn * 32 + nt * 8 + g;
                bf[nt][0] = Ws[col * KP64 + kb];
                bf[nt][1] = Ws[col * KP64 + kb + 4];
            }
#pragma unroll
            for (int mt = 0; mt < 4; mt++)
#pragma unroll
                for (int nt = 0; nt < 4; nt++)
                    mma16(acc[mt][nt], af[mt], bf[nt]);
        }
#pragma unroll
        for (int mt = 0; mt < 4; mt++) {
#pragma unroll
            for (int nt = 0; nt < 4; nt++) {
                int row  = row0 + wm * 64 + mt * 16 + g;
                int col  = np * 128 + wn * 32 + nt * 8 + tig * 2;
                int pcol = col >> 1;
                float b0v = b1[col], b1v = b1[col + 1];
                float x0 = acc[mt][nt][0] + b0v;
                float x1 = acc[mt][nt][1] + b1v;
                float x2 = acc[mt][nt][2] + b0v;
                float x3 = acc[mt][nt][3] + b1v;
                x0 = x0 / (1.f + __expf(-x0));
                x1 = x1 / (1.f + __expf(-x1));
                x2 = x2 / (1.f + __expf(-x2));
                x3 = x3 / (1.f + __expf(-x3));
                H[(size_t)row * FP + pcol]       = f2h2(x0, x1);
                H[(size_t)(row + 8) * FP + pcol] = f2h2(x2, x3);
            }
        }
    }
}

// ---------------------------------------------------------------------------
// phiB (restructured): phi = h @ w2t^T + b2.
// Hs split into two K-halves + one 128-col Ws slice -> 104.4 KB, 2 CTAs/SM.
// Loops: np (out cols) x kp (K half); acc persists across kp.
// ---------------------------------------------------------------------------
#define PB_H0    0
#define PB_H1    (128*KP64)
#define PB_WS    (2*128*KP64)
#define PB_BYTES (3*128*KP64*4)   // 104448

__global__ __launch_bounds__(256, 2) void phiB(
    const uint32_t* __restrict__ Hq, const uint32_t* __restrict__ Hk,
    const float* __restrict__ w2t, const float* __restrict__ b2,
    uint32_t* __restrict__ Cq, uint32_t* __restrict__ Ck)
{
    extern __shared__ uint32_t smx[];
    uint32_t* Hs0 = smx + PB_H0;
    uint32_t* Hs1 = smx + PB_H1;
    uint32_t* Ws  = smx + PB_WS;

    const int t    = threadIdx.x;
    const int lane = t & 31;
    const int wid  = t >> 5;
    const int wm   = wid >> 2;
    const int wn   = wid & 3;
    const int g    = lane >> 2;
    const int tig  = lane & 3;
    const int bx   = blockIdx.x;
    const bool isK = (bx >= NBLK);
    const int row0 = (isK ? bx - NBLK : bx) * 128;
    const uint32_t* H = isK ? Hk : Hq;
    uint32_t* C       = isK ? Ck : Cq;

    // stage Hs (both K-halves): 128 rows x 128 pairs = 4096 uint4 slots
#pragma unroll
    for (int r = 0; r < 16; r++) {
        int slot = t + r * 256;
        int row  = slot >> 5;
        int p4   = (slot & 31) << 2;     // 0..124, multiple of 4
        uint4 v  = *(const uint4*)(H + (size_t)(row0 + row) * FP + p4);
        uint32_t* dst = ((p4 & 64) ? Hs1 : Hs0) + row * KP64 + (p4 & 63);
        dst[0] = v.x; dst[1] = v.y; dst[2] = v.z; dst[3] = v.w;
    }

#pragma unroll
    for (int np = 0; np < 2; np++) {
        float acc[4][4][4];
#pragma unroll
        for (int mt = 0; mt < 4; mt++)
#pragma unroll
            for (int nt = 0; nt < 4; nt++)
#pragma unroll
                for (int e = 0; e < 4; e++) acc[mt][nt][e] = 0.f;

#pragma unroll
        for (int kp = 0; kp < 2; kp++) {
            __syncthreads();   // prev Ws readers done (also orders Hs staging, 1st iter)
            // stage Ws slice: rows [np*128, +128) of w2t, f-pairs [kp*64, +64)
            // 128 rows x 32 float4 loads (2 pairs each) = 4096 slots
#pragma unroll
            for (int r = 0; r < 16; r++) {
                int slot = t + r * 256;
                int row  = slot >> 5;            // 0..127
                int p2   = (slot & 31) << 1;     // 0..62
                float4 v = *(const float4*)(
                    w2t + (size_t)(np * 128 + row) * FF + (kp * 64 + p2) * 2);
                Ws[row * KP64 + p2]     = f2h2(v.x, v.y);
                Ws[row * KP64 + p2 + 1] = f2h2(v.z, v.w);
            }
            __syncthreads();

            const uint32_t* Hh = kp ? Hs1 : Hs0;
#pragma unroll 4
            for (int ks = 0; ks < 8; ks++) {
                int kb = ks * 8 + tig;
                uint32_t af[4][4];
#pragma unroll
                for (int mt = 0; mt < 4; mt++) {
                    int row = wm * 64 + mt * 16 + g;
                    af[mt][0] = Hh[row * KP64 + kb];
                    af[mt][1] = Hh[(row + 8) * KP64 + kb];
                    af[mt][2] = Hh[row * KP64 + kb + 4];
                    af[mt][3] = Hh[(row + 8) * KP64 + kb + 4];
                }
                uint32_t bf[4][2];
#pragma unroll
                for (int nt = 0; nt < 4; nt++) {
                    int col = wn * 32 + nt * 8 + g;
                    bf[nt][0] = Ws[col * KP64 + kb];
                    bf[nt][1] = Ws[col * KP64 + kb + 4];
                }
#pragma unroll
                for (int mt = 0; mt < 4; mt++)
#pragma unroll
                    for (int nt = 0; nt < 4; nt++)
                        mma16(acc[mt][nt], af[mt], bf[nt]);
            }
        }
        // epilogue for this np
#pragma unroll
        for (int mt = 0; mt < 4; mt++) {
#pragma unroll
            for (int nt = 0; nt < 4; nt++) {
                int row  = row0 + wm * 64 + mt * 16 + g;
                int col  = np * 128 + wn * 32 + nt * 8 + tig * 2;
                int pcol = col >> 1;
                float b0v = b2[col], b1v = b2[col + 1];
                C[(size_t)row * FP + pcol] =
                    f2h2(acc[mt][nt][0] + b0v, acc[mt][nt][1] + b1v);
                C[(size_t)(row + 8) * FP + pcol] =
                    f2h2(acc[mt][nt][2] + b0v, acc[mt][nt][3] + b1v);
            }
        }
    }
}

// ---------------------------------------------------------------------------
__global__ void transpose_kernel(const float* __restrict__ W,
                                 float* __restrict__ Wt, int K, int N)
{
    int idx = blockIdx.x * blockDim.x + threadIdx.x;
    if (idx >= K * N) return;
    int kk = idx / N;
    int n  = idx - kk * N;
    Wt[(size_t)n * K + kk] = W[idx];
}

// ---------------------------------------------------------------------------
// chunk_state (fp16 mma, verified R15): 69.6 KB smem -> 2 CTAs/SM.
// ---------------------------------------------------------------------------
#define CS_AT    0
#define CS_BT    (128*KP64)
#define CS_BYTES (2*128*KP64*4)   // 69632

__global__ __launch_bounds__(256, 2) void chunk_state_fp16(
    const uint32_t* __restrict__ kphi, const float* __restrict__ vin,
    uint32_t* __restrict__ P)
{
    extern __shared__ uint32_t smx[];
    uint32_t* At = smx + CS_AT;
    uint32_t* Bt = smx + CS_BT;

    const int t    = threadIdx.x;
    const int lane = t & 31;
    const int wid  = t >> 5;
    const int wm   = wid >> 2;
    const int wn   = wid & 3;
    const int g    = lane >> 2;
    const int tig  = lane & 3;
    const int hc   = blockIdx.x;
    const int h    = hc >> 5;
    const int c    = hc & 31;
    const int f0   = blockIdx.y * 128;
    const int fp0p = blockIdx.y * 64;
    const int pos0 = h * SEQ + c * CHK;

#pragma unroll
    for (int r = 0; r < 8; r++) {
        int slot = t + r * 256;
        int mp   = slot >> 5;
        int d4   = (slot & 31) << 2;
        float4 va = *(const float4*)(vin + (size_t)(pos0 + 2 * mp) * DD + d4);
        float4 vb = *(const float4*)(vin + (size_t)(pos0 + 2 * mp + 1) * DD + d4);
        At[(d4+0) * KP64 + mp] = f2h2(va.x, vb.x);
        At[(d4+1) * KP64 + mp] = f2h2(va.y, vb.y);
        At[(d4+2) * KP64 + mp] = f2h2(va.z, vb.z);
        At[(d4+3) * KP64 + mp] = f2h2(va.w, vb.w);
    }
#pragma unroll
    for (int r = 0; r < 16; r++) {
        int slot = t + r * 256;
        int mp   = slot >> 6;
        int fp   = slot & 63;
        uint32_t ua = kphi[(size_t)(pos0 + 2 * mp) * FP + fp0p + fp];
        uint32_t ub = kphi[(size_t)(pos0 + 2 * mp + 1) * FP + fp0p + fp];
        __half2 ha = *reinterpret_cast<__half2*>(&ua);
        __half2 hb = *reinterpret_cast<__half2*>(&ub);
        __half2 lo = __halves2half2(__low2half(ha),  __low2half(hb));
        __half2 hi = __halves2half2(__high2half(ha), __high2half(hb));
        Bt[(2*fp)   * KP64 + mp] = *reinterpret_cast<uint32_t*>(&lo);
        Bt[(2*fp+1) * KP64 + mp] = *reinterpret_cast<uint32_t*>(&hi);
    }
    __syncthreads();

    float acc[4][4][4];
#pragma unroll
    for (int mt = 0; mt < 4; mt++)
#pragma unroll
        for (int nt = 0; nt < 4; nt++)
#pragma unroll
            for (int e = 0; e < 4; e++) acc[mt][nt][e] = 0.f;

#pragma unroll 4
    for (int ks = 0; ks < 8; ks++) {
        int kb = ks * 8 + tig;
        uint32_t af[4][4];
#pragma unroll
        for (int mt = 0; mt < 4; mt++) {
            int row = wm * 64 + mt * 16 + g;
            af[mt][0] = At[row * KP64 + kb];
            af[mt][1] = At[(row + 8) * KP64 + kb];
            af[mt][2] = At[row * KP64 + kb + 4];
            af[mt][3] = At[(row + 8) * KP64 + kb + 4];
        }
        uint32_t bf[4][2];
#pragma unroll
        for (int nt = 0; nt < 4; nt++) {
            int col = wn * 32 + nt * 8 + g;
            bf[nt][0] = Bt[col * KP64 + kb];
            bf[nt][1] = Bt[col * KP64 + kb + 4];
        }
#pragma unroll
        for (int mt = 0; mt < 4; mt++)
#pragma unroll
            for (int nt = 0; nt < 4; nt++)
                mma16(acc[mt][nt], af[mt], bf[nt]);
    }

    uint32_t* S = P + ((size_t)(h * (NC + 1)) + (c + 1)) * FDP;
#pragma unroll
    for (int mt = 0; mt < 4; mt++) {
#pragma unroll
        for (int nt = 0; nt < 4; nt++) {
            int d    = wm * 64 + mt * 16 + g;
            int col  = f0 + wn * 32 + nt * 8 + tig * 2;
            int pcol = col >> 1;
            S[(size_t)d * FPP + pcol]       = f2h2(acc[mt][nt][0], acc[mt][nt][1]);
            S[(size_t)(d + 8) * FPP + pcol] = f2h2(acc[mt][nt][2], acc[mt][nt][3]);
        }
    }
}

// ---------------------------------------------------------------------------
// prefix over fp16 slabs; fp32 accumulation per element-pair.
// ---------------------------------------------------------------------------
__global__ void prefix_kernel(uint32_t* __restrict__ P)
{
    const int h = blockIdx.y;
    const int e = blockIdx.x * 256 + threadIdx.x;
    uint32_t* base = P + (size_t)h * (NC + 1) * FDP;
    base[e] = 0u;
    float a0 = 0.f, a1 = 0.f;
#pragma unroll
    for (int c = 1; c <= NC; c++) {
        uint32_t u = base[(size_t)c * FDP + e];
        __half2 hv = *reinterpret_cast<__half2*>(&u);
        a0 += __low2float(hv);
        a1 += __high2float(hv);
        base[(size_t)c * FDP + e] = f2h2(a0, a1);
    }
}

// ---------------------------------------------------------------------------
// output_tc (fp16 mma, verified R15; unroll-4 on long mma loops).
// ---------------------------------------------------------------------------
#define OR0 0
#define OR1 (128*KP128)
#define OR2 (2*128*KP128)
#define OSM_BYTES (3*128*KP128*4)   // 202752

__global__ __launch_bounds__(256, 1) void output_tc(
    const uint32_t* __restrict__ qphi, const uint32_t* __restrict__ kphi,
    const float* __restrict__ vin,  const uint32_t* __restrict__ P,
    float* __restrict__ out)
{
    extern __shared__ uint32_t smx[];
    uint32_t* Qp   = smx + OR0;
    uint32_t* Kp   = smx + OR1;
    uint32_t* Vt   = smx + OR1;
    uint32_t* B1   = smx + OR1;
    uint32_t* Abuf = smx + OR2;
    uint32_t* B2   = smx + OR2;

    const int t    = threadIdx.x;
    const int lane = t & 31;
    const int wid  = t >> 5;
    const int wm   = wid >> 2;
    const int wn   = wid & 3;
    const int g    = lane >> 2;
    const int tig  = lane & 3;
    const int hc   = blockIdx.x;
    const int h    = hc >> 5;
    const int c    = hc & 31;
    const int pos0 = h * SEQ + c * CHK;

#pragma unroll
    for (int r = 0; r < 16; r++) {
        int slot = t + r * 256;
        int row  = slot >> 5;
        int p4   = (slot & 31) << 2;
        uint4 qv = *(const uint4*)(qphi + (size_t)(pos0 + row) * FP + p4);
        Qp[row * KP128 + p4]     = qv.x;
        Qp[row * KP128 + p4 + 1] = qv.y;
        Qp[row * KP128 + p4 + 2] = qv.z;
        Qp[row * KP128 + p4 + 3] = qv.w;
        uint4 kv = *(const uint4*)(kphi + (size_t)(pos0 + row) * FP + p4);
        Kp[row * KP128 + p4]     = kv.x;
        Kp[row * KP128 + p4 + 1] = kv.y;
        Kp[row * KP128 + p4 + 2] = kv.z;
        Kp[row * KP128 + p4 + 3] = kv.w;
    }
    __syncthreads();

    // ================= Stage 1: A = Qphi Kphi^T (K=256) =================
    float accA[4][4][4];
#pragma unroll
    for (int mt = 0; mt < 4; mt++)
#pragma unroll
        for (int nt = 0; nt < 4; nt++)
#pragma unroll
            for (int e = 0; e < 4; e++) accA[mt][nt][e] = 0.f;

#pragma unroll 4
    for (int ks = 0; ks < 16; ks++) {
        int kb = ks * 8 + tig;
        uint32_t af[4][4];
#pragma unroll
        for (int mt = 0; mt < 4; mt++) {
            int row = wm * 64 + mt * 16 + g;
            af[mt][0] = Qp[row * KP128 + kb];
            af[mt][1] = Qp[(row + 8) * KP128 + kb];
            af[mt][2] = Qp[row * KP128 + kb + 4];
            af[mt][3] = Qp[(row + 8) * KP128 + kb + 4];
        }
        uint32_t bf[4][2];
#pragma unroll
        for (int nt = 0; nt < 4; nt++) {
            int col = wn * 32 + nt * 8 + g;
            bf[nt][0] = Kp[col * KP128 + kb];
            bf[nt][1] = Kp[col * KP128 + kb + 4];
        }
#pragma unroll
        for (int mt = 0; mt < 4; mt++)
#pragma unroll
            for (int nt = 0; nt < 4; nt++)
                mma16(accA[mt][nt], af[mt], bf[nt]);
    }
    __syncthreads();

    // ---- write A as fp16 pairs [n][m-pair]; pack V^T [d][m-pair] ----
#pragma unroll
    for (int mt = 0; mt < 4; mt++) {
#pragma unroll
        for (int nt = 0; nt < 4; nt++) {
            int n0 = wm * 64 + mt * 16 + g;
            int mp = wn * 16 + nt * 4 + tig;
            Abuf[n0 * KP64 + mp]       = f2h2(accA[mt][nt][0], accA[mt][nt][1]);
            Abuf[(n0 + 8) * KP64 + mp] = f2h2(accA[mt][nt][2], accA[mt][nt][3]);
        }
    }
#pragma unroll
    for (int r = 0; r < 8; r++) {
        int slot = t + r * 256;
        int mp   = slot >> 5;
        int d4   = (slot & 31) << 2;
        float4 va = *(const float4*)(vin + (size_t)(pos0 + 2 * mp) * DD + d4);
        float4 vb = *(const float4*)(vin + (size_t)(pos0 + 2 * mp + 1) * DD + d4);
        Vt[(d4+0) * KP64 + mp] = f2h2(va.x, vb.x);
        Vt[(d4+1) * KP64 + mp] = f2h2(va.y, vb.y);
        Vt[(d4+2) * KP64 + mp] = f2h2(va.z, vb.z);
        Vt[(d4+3) * KP64 + mp] = f2h2(va.w, vb.w);
    }
    __syncthreads();

    // ================= Stage 2: masked A @ V =================
    float acc1[4][4][4], acc2[4][4][4];
#pragma unroll
    for (int mt = 0; mt < 4; mt++)
#pragma unroll
        for (int nt = 0; nt < 4; nt++)
#pragma unroll
            for (int e = 0; e < 4; e++) { acc1[mt][nt][e] = 0.f; acc2[mt][nt][e] = 0.f; }

#pragma unroll 4
    for (int ks = 0; ks < 8; ks++) {
        int kb = ks * 8 + tig;
        int m0 = kb * 2;
        int m2 = (kb + 4) * 2;
        uint32_t lo[4][4], up[4][4];
#pragma unroll
        for (int mt = 0; mt < 4; mt++) {
            int nA = wm * 64 + mt * 16 + g;
            int nB = nA + 8;
            uint32_t a0 = Abuf[nA * KP64 + kb];
            uint32_t a1 = Abuf[nB * KP64 + kb];
            uint32_t a2 = Abuf[nA * KP64 + kb + 4];
            uint32_t a3 = Abuf[nB * KP64 + kb + 4];
            lo[mt][0] = maskLE(a0, m0, nA);
            lo[mt][1] = maskLE(a1, m0, nB);
            lo[mt][2] = maskLE(a2, m2, nA);
            lo[mt][3] = maskLE(a3, m2, nB);
            up[mt][0] = maskGE(a0, m0, nA);
            up[mt][1] = maskGE(a1, m0, nB);
            up[mt][2] = maskGE(a2, m2, nA);
            up[mt][3] = maskGE(a3, m2, nB);
        }
        uint32_t bf[4][2];
#pragma unroll
        for (int nt = 0; nt < 4; nt++) {
            int col = wn * 32 + nt * 8 + g;
            bf[nt][0] = Vt[col * KP64 + kb];
            bf[nt][1] = Vt[col * KP64 + kb + 4];
        }
#pragma unroll
        for (int mt = 0; mt < 4; mt++)
#pragma unroll
            for (int nt = 0; nt < 4; nt++) {
                mma16(acc1[mt][nt], lo[mt], bf[nt]);
                mma16(acc2[mt][nt], up[mt], bf[nt]);
            }
    }
    __syncthreads();

    // ---- stage B1 = Wexc, B2 = Wtot - Winc (fp16 pairs, direct) ----
    const uint32_t* Pbase = P + (size_t)h * (NC + 1) * FDP;
    const uint32_t* Pexc  = Pbase + (size_t)c * FDP;
    const uint32_t* Pinc  = Pbase + (size_t)(c + 1) * FDP;
    const uint32_t* Ptot  = Pbase + (size_t)NC * FDP;

#pragma unroll
    for (int r = 0; r < 16; r++) {
        int slot = t + r * 256;
        int row  = slot >> 5;
        int p4   = (slot & 31) << 2;
        size_t go = (size_t)row * FPP + p4;
        uint4 ev = *(const uint4*)(Pexc + go);
        B1[row * KP128 + p4]     = ev.x;
        B1[row * KP128 + p4 + 1] = ev.y;
        B1[row * KP128 + p4 + 2] = ev.z;
        B1[row * KP128 + p4 + 3] = ev.w;
        uint4 iv = *(const uint4*)(Pinc + go);
        uint4 tv = *(const uint4*)(Ptot + go);
        B2[row * KP128 + p4]     = hsub2u(tv.x, iv.x);
        B2[row * KP128 + p4 + 1] = hsub2u(tv.y, iv.y);
        B2[row * KP128 + p4 + 2] = hsub2u(tv.z, iv.z);
        B2[row * KP128 + p4 + 3] = hsub2u(tv.w, iv.w);
    }
    __syncthreads();

    // ================= Stage 3: Q @ Wexc / Q @ Wsuf (K=256) =================
#pragma unroll 4
    for (int ks = 0; ks < 16; ks++) {
        int kb = ks * 8 + tig;
        uint32_t af[4][4];
#pragma unroll
        for (int mt = 0; mt < 4; mt++) {
            int row = wm * 64 + mt * 16 + g;
            af[mt][0] = Qp[row * KP128 + kb];
            af[mt][1] = Qp[(row + 8) * KP128 + kb];
            af[mt][2] = Qp[row * KP128 + kb + 4];
            af[mt][3] = Qp[(row + 8) * KP128 + kb + 4];
        }
        uint32_t b1f[4][2], b2f[4][2];
#pragma unroll
        for (int nt = 0; nt < 4; nt++) {
            int col = wn * 32 + nt * 8 + g;
            b1f[nt][0] = B1[col * KP128 + kb];
            b1f[nt][1] = B1[col * KP128 + kb + 4];
            b2f[nt][0] = B2[col * KP128 + kb];
            b2f[nt][1] = B2[col * KP128 + kb + 4];
        }
#pragma unroll
        for (int mt = 0; mt < 4; mt++)
#pragma unroll
            for (int nt = 0; nt < 4; nt++) {
                mma16(acc1[mt][nt], af[mt], b1f[nt]);
                mma16(acc2[mt][nt], af[mt], b2f[nt]);
            }
    }

    // ================= Epilogue =================
#pragma unroll
    for (int mt = 0; mt < 4; mt++) {
#pragma unroll
        for (int nt = 0; nt < 4; nt++) {
            int n0  = wm * 64 + mt * 16 + g;
            int d0  = wn * 32 + nt * 8 + tig * 2;
            int posA = c * CHK + n0;
            int posB = posA + 8;
            float s1a = 1.f / (float)(posA + 1);
            float s2a = 1.f / (float)(SEQ - posA);
            float s1b = 1.f / (float)(posB + 1);
            float s2b = 1.f / (float)(SEQ - posB);
            float2 oA, oB;
            oA.x = acc1[mt][nt][0] * s1a + acc2[mt][nt][0] * s2a;
            oA.y = acc1[mt][nt][1] * s1a + acc2[mt][nt][1] * s2a;
            oB.x = acc1[mt][nt][2] * s1b + acc2[mt][nt][2] * s2b;
            oB.y = acc1[mt][nt][3] * s1b + acc2[mt][nt][3] * s2b;
            *(float2*)(out + (size_t)(pos0 + n0) * DD + d0)     = oA;
            *(float2*)(out + (size_t)(pos0 + n0 + 8) * DD + d0) = oB;
        }
    }
}

// ---------------------------------------------------------------------------
extern "C" void kernel_launch(void* const* d_in, const int* in_sizes, int n_in,
                              void* d_out, int out_size)
{
    (void)out_size;
    int big[3] = {0, 1, 2}; int nbig = 0;
    int iw1 = -1, iw2 = -1, ibias[2] = {-1, -1}; int nb = 0;
    for (int i = 0; i < n_in; i++) {
        long long s = in_sizes[i];
        if ((s == 12582912LL || s == 50331648LL) && nbig < 3) big[nbig++] = i;
        else if (s == 32768LL  || s == 131072LL) iw1 = i;
        else if (s == 65536LL  || s == 262144LL) iw2 = i;
        else if ((s == 256LL   || s == 1024LL) && nb < 2) ibias[nb++] = i;
    }
    if (nbig != 3 || iw1 < 0 || iw2 < 0 || nb != 2) {
        big[0] = 0; big[1] = 1; big[2] = 2;
        iw1 = 3; ibias[0] = 4; iw2 = 5; ibias[1] = 6;
    }
    const float *q, *k;
    if (big[0] == 0) {
        q = (const float*)d_in[big[0]];
        k = (const float*)d_in[big[1]];
    } else {
        k = (const float*)d_in[big[0]];
        q = (const float*)d_in[big[1]];
    }
    const float* v  = (const float*)d_in[big[2]];
    const float* w1 = (const float*)d_in[iw1];
    const float* b1 = (const float*)d_in[ibias[0]];
    const float* w2 = (const float*)d_in[iw2];
    const float* b2 = (const float*)d_in[ibias[1]];
    float* out = (float*)d_out;

    uint32_t *hq, *hk, *qphi, *kphi, *P;
    float *w1t, *w2t;
    cudaGetSymbolAddress((void**)&hq,   g_hq);
    cudaGetSymbolAddress((void**)&hk,   g_hk);
    cudaGetSymbolAddress((void**)&qphi, g_qphi);
    cudaGetSymbolAddress((void**)&kphi, g_kphi);
    cudaGetSymbolAddress((void**)&P,    g_P);
    cudaGetSymbolAddress((void**)&w1t,  g_w1t);
    cudaGetSymbolAddress((void**)&w2t,  g_w2t);

    cudaFuncSetAttribute(phiA,
                         cudaFuncAttributeMaxDynamicSharedMemorySize, PA_BYTES);
    cudaFuncSetAttribute(phiB,
                         cudaFuncAttributeMaxDynamicSharedMemorySize, PB_BYTES);
    cudaFuncSetAttribute(chunk_state_fp16,
                         cudaFuncAttributeMaxDynamicSharedMemorySize, CS_BYTES);
    cudaFuncSetAttribute(output_tc,
                         cudaFuncAttributeMaxDynamicSharedMemorySize, OSM_BYTES);

    transpose_kernel<<<(DD*FF + 255)/256, 256>>>(w1, w1t, DD, FF);
    transpose_kernel<<<(FF*FF + 255)/256, 256>>>(w2, w2t, FF, FF);

    phiA<<<2 * NBLK, 256, PA_BYTES>>>(q, k, w1t, b1, hq, hk);
    phiB<<<2 * NBLK, 256, PB_BYTES>>>(hq, hk, w2t, b2, qphi, kphi);

    chunk_state_fp16<<<dim3(BH * NC, 2), 256, CS_BYTES>>>(kphi, v, P);
    prefix_kernel<<<dim3(FDP / 256, BH), 256>>>(P);

    output_tc<<<BH * NC, 256, OSM_BYTES>>>(qphi, kphi, v, P, out);
}

// round 17
// speedup vs baseline: 1.7819x; 1.0029x over previous
#include <cuda_runtime.h>
#include <cuda_fp16.h>
#include <cstdint>

// Problem constants
#define BH   24
#define SEQ  4096
#define DD   128
#define FF   256
#define FP   128   // FF/2 pairs
#define CHK  128
#define NC   32
#define FD   (FF*DD)       // 32768
#define FDP  (FD/2)        // 16384 pairs per slab
#define FPP  128           // pairs per d-row in a slab
#define ROWS (BH*SEQ)      // 98304
#define NBLK (ROWS/128)    // 768

// ---------------- scratch (device globals; no runtime allocation) ----------
__device__ uint32_t g_hq  [(size_t)ROWS * FP];
__device__ uint32_t g_hk  [(size_t)ROWS * FP];
__device__ uint32_t g_qphi[(size_t)ROWS * FP];
__device__ uint32_t g_kphi[(size_t)ROWS * FP];
__device__ uint32_t g_P   [(size_t)BH * (NC+1) * FDP];  // fp16-pair slabs [d][f-pair]
__device__ float    g_w1t [FF * DD];
__device__ float    g_w2t [FF * FF];

#define KP64  68
#define KP128 132

__device__ __forceinline__ uint32_t f2h2(float a, float b) {
    __half2 h = __floats2half2_rn(a, b);
    return *reinterpret_cast<uint32_t*>(&h);
}
__device__ __forceinline__ uint32_t hsub2u(uint32_t a, uint32_t b) {
    __half2 r = __hsub2(*reinterpret_cast<__half2*>(&a),
                        *reinterpret_cast<__half2*>(&b));
    return *reinterpret_cast<uint32_t*>(&r);
}
__device__ __forceinline__ void mma16(float* c, const uint32_t* a, const uint32_t* b) {
    asm volatile(
        "mma.sync.aligned.m16n8k16.row.col.f32.f16.f16.f32 "
        "{%0,%1,%2,%3}, {%4,%5,%6,%7}, {%8,%9}, {%0,%1,%2,%3};"
        : "+f"(c[0]), "+f"(c[1]), "+f"(c[2]), "+f"(c[3])
        : "r"(a[0]), "r"(a[1]), "r"(a[2]), "r"(a[3]), "r"(b[0]), "r"(b[1]));
}
__device__ __forceinline__ uint32_t maskLE(uint32_t v, int m0, int n) {
    uint32_t m = (m0 <= n ? 0xFFFFu : 0u) | (m0 + 1 <= n ? 0xFFFF0000u : 0u);
    return v & m;
}
__device__ __forceinline__ uint32_t maskGE(uint32_t v, int m0, int n) {
    uint32_t m = (m0 >= n ? 0xFFFFu : 0u) | (m0 + 1 >= n ? 0xFFFF0000u : 0u);
    return v & m;
}

// ---------------------------------------------------------------------------
// phiA (verified R16): h = silu(X @ w1t^T + b1), fp16 out. 2 CTAs/SM.
// ---------------------------------------------------------------------------
#define PA_XS    0
#define PA_WS    (128*KP64)
#define PA_BYTES ((128*KP64 + 256*KP64) * 4)   // 104448

__global__ __launch_bounds__(256, 2) void phiA(
    const float* __restrict__ Xq, const float* __restrict__ Xk,
    const float* __restrict__ w1t, const float* __restrict__ b1,
    uint32_t* __restrict__ Hq, uint32_t* __restrict__ Hk)
{
    extern __shared__ uint32_t smx[];
    uint32_t* Xs = smx + PA_XS;
    uint32_t* Ws = smx + PA_WS;

    const int t    = threadIdx.x;
    const int lane = t & 31;
    const int wid  = t >> 5;
    const int wm   = wid >> 2;
    const int wn   = wid & 3;
    const int g    = lane >> 2;
    const int tig  = lane & 3;
    const int bx   = blockIdx.x;
    const bool isK = (bx >= NBLK);
    const int row0 = (isK ? bx - NBLK : bx) * 128;
    const float* X = isK ? Xk : Xq;
    uint32_t* H    = isK ? Hk : Hq;

#pragma unroll
    for (int r = 0; r < 16; r++) {
        int slot = t + r * 256;
        int row  = slot >> 5;
        int p2   = (slot & 31) << 1;
        float4 v = *(const float4*)(X + (size_t)(row0 + row) * DD + (p2 << 1));
        Xs[row * KP64 + p2]     = f2h2(v.x, v.y);
        Xs[row * KP64 + p2 + 1] = f2h2(v.z, v.w);
    }
#pragma unroll
    for (int r = 0; r < 32; r++) {
        int slot = t + r * 256;
        int row  = slot >> 5;
        int p2   = (slot & 31) << 1;
        float4 v = *(const float4*)(w1t + (size_t)row * DD + (p2 << 1));
        Ws[row * KP64 + p2]     = f2h2(v.x, v.y);
        Ws[row * KP64 + p2 + 1] = f2h2(v.z, v.w);
    }
    __syncthreads();

#pragma unroll
    for (int np = 0; np < 2; np++) {
        float acc[4][4][4];
#pragma unroll
        for (int mt = 0; mt < 4; mt++)
#pragma unroll
            for (int nt = 0; nt < 4; nt++)
#pragma unroll
                for (int e = 0; e < 4; e++) acc[mt][nt][e] = 0.f;

#pragma unroll 4
        for (int ks = 0; ks < 8; ks++) {
            int kb = ks * 8 + tig;
            uint32_t af[4][4];
#pragma unroll
            for (int mt = 0; mt < 4; mt++) {
                int row = wm * 64 + mt * 16 + g;
                af[mt][0] = Xs[row * KP64 + kb];
                af[mt][1] = Xs[(row + 8) * KP64 + kb];
                af[mt][2] = Xs[row * KP64 + kb + 4];
                af[mt][3] = Xs[(row + 8) * KP64 + kb + 4];
            }
            uint32_t bf[4][2];
#pragma unroll
            for (int nt = 0; nt < 4; nt++) {
                int col = np * 128 + wn * 32 + nt * 8 + g;
                bf[nt][0] = Ws[col * KP64 + kb];
                bf[nt][1] = Ws[col * KP64 + kb + 4];
            }
#pragma unroll
            for (int mt = 0; mt < 4; mt++)
#pragma unroll
                for (int nt = 0; nt < 4; nt++)
                    mma16(acc[mt][nt], af[mt], bf[nt]);
        }
#pragma unroll
        for (int mt = 0; mt < 4; mt++) {
#pragma unroll
            for (int nt = 0; nt < 4; nt++) {
                int row  = row0 + wm * 64 + mt * 16 + g;
                int col  = np * 128 + wn * 32 + nt * 8 + tig * 2;
                int pcol = col >> 1;
                float b0v = b1[col], b1v = b1[col + 1];
                float x0 = acc[mt][nt][0] + b0v;
                float x1 = acc[mt][nt][1] + b1v;
                float x2 = acc[mt][nt][2] + b0v;
                float x3 = acc[mt][nt][3] + b1v;
                x0 = x0 / (1.f + __expf(-x0));
                x1 = x1 / (1.f + __expf(-x1));
                x2 = x2 / (1.f + __expf(-x2));
                x3 = x3 / (1.f + __expf(-x3));
                H[(size_t)row * FP + pcol]       = f2h2(x0, x1);
                H[(size_t)(row + 8) * FP + pcol] = f2h2(x2, x3);
            }
        }
    }
}

// ---------------------------------------------------------------------------
// phiB (verified R16): phi = h @ w2t^T + b2. 2 CTAs/SM.
// ---------------------------------------------------------------------------
#define PB_H0    0
#define PB_H1    (128*KP64)
#define PB_WS    (2*128*KP64)
#define PB_BYTES (3*128*KP64*4)   // 104448

__global__ __launch_bounds__(256, 2) void phiB(
    const uint32_t* __restrict__ Hq, const uint32_t* __restrict__ Hk,
    const float* __restrict__ w2t, const float* __restrict__ b2,
    uint32_t* __restrict__ Cq, uint32_t* __restrict__ Ck)
{
    extern __shared__ uint32_t smx[];
    uint32_t* Hs0 = smx + PB_H0;
    uint32_t* Hs1 = smx + PB_H1;
    uint32_t* Ws  = smx + PB_WS;

    const int t    = threadIdx.x;
    const int lane = t & 31;
    const int wid  = t >> 5;
    const int wm   = wid >> 2;
    const int wn   = wid & 3;
    const int g    = lane >> 2;
    const int tig  = lane & 3;
    const int bx   = blockIdx.x;
    const bool isK = (bx >= NBLK);
    const int row0 = (isK ? bx - NBLK : bx) * 128;
    const uint32_t* H = isK ? Hk : Hq;
    uint32_t* C       = isK ? Ck : Cq;

#pragma unroll
    for (int r = 0; r < 16; r++) {
        int slot = t + r * 256;
        int row  = slot >> 5;
        int p4   = (slot & 31) << 2;
        uint4 v  = *(const uint4*)(H + (size_t)(row0 + row) * FP + p4);
        uint32_t* dst = ((p4 & 64) ? Hs1 : Hs0) + row * KP64 + (p4 & 63);
        dst[0] = v.x; dst[1] = v.y; dst[2] = v.z; dst[3] = v.w;
    }

#pragma unroll
    for (int np = 0; np < 2; np++) {
        float acc[4][4][4];
#pragma unroll
        for (int mt = 0; mt < 4; mt++)
#pragma unroll
            for (int nt = 0; nt < 4; nt++)
#pragma unroll
                for (int e = 0; e < 4; e++) acc[mt][nt][e] = 0.f;

#pragma unroll
        for (int kp = 0; kp < 2; kp++) {
            __syncthreads();
#pragma unroll
            for (int r = 0; r < 16; r++) {
                int slot = t + r * 256;
                int row  = slot >> 5;
                int p2   = (slot & 31) << 1;
                float4 v = *(const float4*)(
                    w2t + (size_t)(np * 128 + row) * FF + (kp * 64 + p2) * 2);
                Ws[row * KP64 + p2]     = f2h2(v.x, v.y);
                Ws[row * KP64 + p2 + 1] = f2h2(v.z, v.w);
            }
            __syncthreads();

            const uint32_t* Hh = kp ? Hs1 : Hs0;
#pragma unroll 4
            for (int ks = 0; ks < 8; ks++) {
                int kb = ks * 8 + tig;
                uint32_t af[4][4];
#pragma unroll
                for (int mt = 0; mt < 4; mt++) {
                    int row = wm * 64 + mt * 16 + g;
                    af[mt][0] = Hh[row * KP64 + kb];
                    af[mt][1] = Hh[(row + 8) * KP64 + kb];
                    af[mt][2] = Hh[row * KP64 + kb + 4];
                    af[mt][3] = Hh[(row + 8) * KP64 + kb + 4];
                }
                uint32_t bf[4][2];
#pragma unroll
                for (int nt = 0; nt < 4; nt++) {
                    int col = wn * 32 + nt * 8 + g;
                    bf[nt][0] = Ws[col * KP64 + kb];
                    bf[nt][1] = Ws[col * KP64 + kb + 4];
                }
#pragma unroll
                for (int mt = 0; mt < 4; mt++)
#pragma unroll
                    for (int nt = 0; nt < 4; nt++)
                        mma16(acc[mt][nt], af[mt], bf[nt]);
            }
        }
#pragma unroll
        for (int mt = 0; mt < 4; mt++) {
#pragma unroll
            for (int nt = 0; nt < 4; nt++) {
                int row  = row0 + wm * 64 + mt * 16 + g;
                int col  = np * 128 + wn * 32 + nt * 8 + tig * 2;
                int pcol = col >> 1;
                float b0v = b2[col], b1v = b2[col + 1];
                C[(size_t)row * FP + pcol] =
                    f2h2(acc[mt][nt][0] + b0v, acc[mt][nt][1] + b1v);
                C[(size_t)(row + 8) * FP + pcol] =
                    f2h2(acc[mt][nt][2] + b0v, acc[mt][nt][3] + b1v);
            }
        }
    }
}

// ---------------------------------------------------------------------------
__global__ void transpose_kernel(const float* __restrict__ W,
                                 float* __restrict__ Wt, int K, int N)
{
    int idx = blockIdx.x * blockDim.x + threadIdx.x;
    if (idx >= K * N) return;
    int kk = idx / N;
    int n  = idx - kk * N;
    Wt[(size_t)n * K + kk] = W[idx];
}

// ---------------------------------------------------------------------------
// chunk_state (verified R16): fp16 mma, 2 CTAs/SM.
// ---------------------------------------------------------------------------
#define CS_AT    0
#define CS_BT    (128*KP64)
#define CS_BYTES (2*128*KP64*4)   // 69632

__global__ __launch_bounds__(256, 2) void chunk_state_fp16(
    const uint32_t* __restrict__ kphi, const float* __restrict__ vin,
    uint32_t* __restrict__ P)
{
    extern __shared__ uint32_t smx[];
    uint32_t* At = smx + CS_AT;
    uint32_t* Bt = smx + CS_BT;

    const int t    = threadIdx.x;
    const int lane = t & 31;
    const int wid  = t >> 5;
    const int wm   = wid >> 2;
    const int wn   = wid & 3;
    const int g    = lane >> 2;
    const int tig  = lane & 3;
    const int hc   = blockIdx.x;
    const int h    = hc >> 5;
    const int c    = hc & 31;
    const int f0   = blockIdx.y * 128;
    const int fp0p = blockIdx.y * 64;
    const int pos0 = h * SEQ + c * CHK;

#pragma unroll
    for (int r = 0; r < 8; r++) {
        int slot = t + r * 256;
        int mp   = slot >> 5;
        int d4   = (slot & 31) << 2;
        float4 va = *(const float4*)(vin + (size_t)(pos0 + 2 * mp) * DD + d4);
        float4 vb = *(const float4*)(vin + (size_t)(pos0 + 2 * mp + 1) * DD + d4);
        At[(d4+0) * KP64 + mp] = f2h2(va.x, vb.x);
        At[(d4+1) * KP64 + mp] = f2h2(va.y, vb.y);
        At[(d4+2) * KP64 + mp] = f2h2(va.z, vb.z);
        At[(d4+3) * KP64 + mp] = f2h2(va.w, vb.w);
    }
#pragma unroll
    for (int r = 0; r < 16; r++) {
        int slot = t + r * 256;
        int mp   = slot >> 6;
        int fp   = slot & 63;
        uint32_t ua = kphi[(size_t)(pos0 + 2 * mp) * FP + fp0p + fp];
        uint32_t ub = kphi[(size_t)(pos0 + 2 * mp + 1) * FP + fp0p + fp];
        __half2 ha = *reinterpret_cast<__half2*>(&ua);
        __half2 hb = *reinterpret_cast<__half2*>(&ub);
        __half2 lo = __halves2half2(__low2half(ha),  __low2half(hb));
        __half2 hi = __halves2half2(__high2half(ha), __high2half(hb));
        Bt[(2*fp)   * KP64 + mp] = *reinterpret_cast<uint32_t*>(&lo);
        Bt[(2*fp+1) * KP64 + mp] = *reinterpret_cast<uint32_t*>(&hi);
    }
    __syncthreads();

    float acc[4][4][4];
#pragma unroll
    for (int mt = 0; mt < 4; mt++)
#pragma unroll
        for (int nt = 0; nt < 4; nt++)
#pragma unroll
            for (int e = 0; e < 4; e++) acc[mt][nt][e] = 0.f;

#pragma unroll 4
    for (int ks = 0; ks < 8; ks++) {
        int kb = ks * 8 + tig;
        uint32_t af[4][4];
#pragma unroll
        for (int mt = 0; mt < 4; mt++) {
            int row = wm * 64 + mt * 16 + g;
            af[mt][0] = At[row * KP64 + kb];
            af[mt][1] = At[(row + 8) * KP64 + kb];
            af[mt][2] = At[row * KP64 + kb + 4];
            af[mt][3] = At[(row + 8) * KP64 + kb + 4];
        }
        uint32_t bf[4][2];
#pragma unroll
        for (int nt = 0; nt < 4; nt++) {
            int col = wn * 32 + nt * 8 + g;
            bf[nt][0] = Bt[col * KP64 + kb];
            bf[nt][1] = Bt[col * KP64 + kb + 4];
        }
#pragma unroll
        for (int mt = 0; mt < 4; mt++)
#pragma unroll
            for (int nt = 0; nt < 4; nt++)
                mma16(acc[mt][nt], af[mt], bf[nt]);
    }

    uint32_t* S = P + ((size_t)(h * (NC + 1)) + (c + 1)) * FDP;
#pragma unroll
    for (int mt = 0; mt < 4; mt++) {
#pragma unroll
        for (int nt = 0; nt < 4; nt++) {
            int d    = wm * 64 + mt * 16 + g;
            int col  = f0 + wn * 32 + nt * 8 + tig * 2;
            int pcol = col >> 1;
            S[(size_t)d * FPP + pcol]       = f2h2(acc[mt][nt][0], acc[mt][nt][1]);
            S[(size_t)(d + 8) * FPP + pcol] = f2h2(acc[mt][nt][2], acc[mt][nt][3]);
        }
    }
}

// ---------------------------------------------------------------------------
// prefix (x2 vectorized): each thread owns 2 consecutive pairs (uint2).
// ---------------------------------------------------------------------------
__global__ void prefix_kernel(uint32_t* __restrict__ P)
{
    const int h = blockIdx.y;
    const int e2 = blockIdx.x * 256 + threadIdx.x;   // < FDP/2
    uint2* base = reinterpret_cast<uint2*>(P + (size_t)h * (NC + 1) * FDP) + e2;
    const size_t stride2 = FDP / 2;
    base[0] = make_uint2(0u, 0u);
    float a0 = 0.f, a1 = 0.f, a2 = 0.f, a3 = 0.f;
#pragma unroll
    for (int c = 1; c <= NC; c++) {
        uint2 u = base[(size_t)c * stride2];
        __half2 h0 = *reinterpret_cast<__half2*>(&u.x);
        __half2 h1 = *reinterpret_cast<__half2*>(&u.y);
        a0 += __low2float(h0); a1 += __high2float(h0);
        a2 += __low2float(h1); a3 += __high2float(h1);
        uint2 o;
        o.x = f2h2(a0, a1);
        o.y = f2h2(a2, a3);
        base[(size_t)c * stride2] = o;
    }
}

// ---------------------------------------------------------------------------
// output_tc: 512 threads, 16 warps (4m x 4n), warp tile 32x32.
// acc1+acc2 = 64 floats -> regs ~120; 512x128 regs = full RF, 1 CTA.
// ---------------------------------------------------------------------------
#define OR0 0
#define OR1 (128*KP128)
#define OR2 (2*128*KP128)
#define OSM_BYTES (3*128*KP128*4)   // 202752

__global__ __launch_bounds__(512, 1) void output_tc(
    const uint32_t* __restrict__ qphi, const uint32_t* __restrict__ kphi,
    const float* __restrict__ vin,  const uint32_t* __restrict__ P,
    float* __restrict__ out)
{
    extern __shared__ uint32_t smx[];
    uint32_t* Qp   = smx + OR0;
    uint32_t* Kp   = smx + OR1;
    uint32_t* Vt   = smx + OR1;
    uint32_t* B1   = smx + OR1;
    uint32_t* Abuf = smx + OR2;
    uint32_t* B2   = smx + OR2;

    const int t    = threadIdx.x;
    const int lane = t & 31;
    const int wid  = t >> 5;          // 0..15
    const int wm   = wid >> 2;        // 0..3
    const int wn   = wid & 3;         // 0..3
    const int g    = lane >> 2;
    const int tig  = lane & 3;
    const int hc   = blockIdx.x;
    const int h    = hc >> 5;
    const int c    = hc & 31;
    const int pos0 = h * SEQ + c * CHK;

    // ---- stage Qp, Kp: 4096 uint4 slots each ----
#pragma unroll
    for (int r = 0; r < 8; r++) {
        int slot = t + r * 512;
        int row  = slot >> 5;
        int p4   = (slot & 31) << 2;
        uint4 qv = *(const uint4*)(qphi + (size_t)(pos0 + row) * FP + p4);
        Qp[row * KP128 + p4]     = qv.x;
        Qp[row * KP128 + p4 + 1] = qv.y;
        Qp[row * KP128 + p4 + 2] = qv.z;
        Qp[row * KP128 + p4 + 3] = qv.w;
        uint4 kv = *(const uint4*)(kphi + (size_t)(pos0 + row) * FP + p4);
        Kp[row * KP128 + p4]     = kv.x;
        Kp[row * KP128 + p4 + 1] = kv.y;
        Kp[row * KP128 + p4 + 2] = kv.z;
        Kp[row * KP128 + p4 + 3] = kv.w;
    }
    __syncthreads();

    // ================= Stage 1: A = Qphi Kphi^T (K=256) =================
    float accA[2][4][4];
#pragma unroll
    for (int mt = 0; mt < 2; mt++)
#pragma unroll
        for (int nt = 0; nt < 4; nt++)
#pragma unroll
            for (int e = 0; e < 4; e++) accA[mt][nt][e] = 0.f;

#pragma unroll 4
    for (int ks = 0; ks < 16; ks++) {
        int kb = ks * 8 + tig;
        uint32_t af[2][4];
#pragma unroll
        for (int mt = 0; mt < 2; mt++) {
            int row = wm * 32 + mt * 16 + g;
            af[mt][0] = Qp[row * KP128 + kb];
            af[mt][1] = Qp[(row + 8) * KP128 + kb];
            af[mt][2] = Qp[row * KP128 + kb + 4];
            af[mt][3] = Qp[(row + 8) * KP128 + kb + 4];
        }
        uint32_t bf[4][2];
#pragma unroll
        for (int nt = 0; nt < 4; nt++) {
            int col = wn * 32 + nt * 8 + g;
            bf[nt][0] = Kp[col * KP128 + kb];
            bf[nt][1] = Kp[col * KP128 + kb + 4];
        }
#pragma unroll
        for (int mt = 0; mt < 2; mt++)
#pragma unroll
            for (int nt = 0; nt < 4; nt++)
                mma16(accA[mt][nt], af[mt], bf[nt]);
    }
    __syncthreads();

    // ---- write A as fp16 pairs [n][m-pair]; pack V^T [d][m-pair] ----
#pragma unroll
    for (int mt = 0; mt < 2; mt++) {
#pragma unroll
        for (int nt = 0; nt < 4; nt++) {
            int n0 = wm * 32 + mt * 16 + g;
            int mp = wn * 16 + nt * 4 + tig;
            Abuf[n0 * KP64 + mp]       = f2h2(accA[mt][nt][0], accA[mt][nt][1]);
            Abuf[(n0 + 8) * KP64 + mp] = f2h2(accA[mt][nt][2], accA[mt][nt][3]);
        }
    }
#pragma unroll
    for (int r = 0; r < 4; r++) {
        int slot = t + r * 512;
        int mp   = slot >> 5;
        int d4   = (slot & 31) << 2;
        float4 va = *(const float4*)(vin + (size_t)(pos0 + 2 * mp) * DD + d4);
        float4 vb = *(const float4*)(vin + (size_t)(pos0 + 2 * mp + 1) * DD + d4);
        Vt[(d4+0) * KP64 + mp] = f2h2(va.x, vb.x);
        Vt[(d4+1) * KP64 + mp] = f2h2(va.y, vb.y);
        Vt[(d4+2) * KP64 + mp] = f2h2(va.z, vb.z);
        Vt[(d4+3) * KP64 + mp] = f2h2(va.w, vb.w);
    }
    __syncthreads();

    // ================= Stage 2: masked A @ V =================
    float acc1[2][4][4], acc2[2][4][4];
#pragma unroll
    for (int mt = 0; mt < 2; mt++)
#pragma unroll
        for (int nt = 0; nt < 4; nt++)
#pragma unroll
            for (int e = 0; e < 4; e++) { acc1[mt][nt][e] = 0.f; acc2[mt][nt][e] = 0.f; }

#pragma unroll 4
    for (int ks = 0; ks < 8; ks++) {
        int kb = ks * 8 + tig;
        int m0 = kb * 2;
        int m2 = (kb + 4) * 2;
        uint32_t lo[2][4], up[2][4];
#pragma unroll
        for (int mt = 0; mt < 2; mt++) {
            int nA = wm * 32 + mt * 16 + g;
            int nB = nA + 8;
            uint32_t a0 = Abuf[nA * KP64 + kb];
            uint32_t a1 = Abuf[nB * KP64 + kb];
            uint32_t a2 = Abuf[nA * KP64 + kb + 4];
            uint32_t a3 = Abuf[nB * KP64 + kb + 4];
            lo[mt][0] = maskLE(a0, m0, nA);
            lo[mt][1] = maskLE(a1, m0, nB);
            lo[mt][2] = maskLE(a2, m2, nA);
            lo[mt][3] = maskLE(a3, m2, nB);
            up[mt][0] = maskGE(a0, m0, nA);
            up[mt][1] = maskGE(a1, m0, nB);
            up[mt][2] = maskGE(a2, m2, nA);
            up[mt][3] = maskGE(a3, m2, nB);
        }
        uint32_t bf[4][2];
#pragma unroll
        for (int nt = 0; nt < 4; nt++) {
            int col = wn * 32 + nt * 8 + g;
            bf[nt][0] = Vt[col * KP64 + kb];
            bf[nt][1] = Vt[col * KP64 + kb + 4];
        }
#pragma unroll
        for (int mt = 0; mt < 2; mt++)
#pragma unroll
            for (int nt = 0; nt < 4; nt++) {
                mma16(acc1[mt][nt], lo[mt], bf[nt]);
                mma16(acc2[mt][nt], up[mt], bf[nt]);
            }
    }
    __syncthreads();

    // ---- stage B1 = Wexc, B2 = Wtot - Winc (fp16 pairs, direct) ----
    const uint32_t* Pbase = P + (size_t)h * (NC + 1) * FDP;
    const uint32_t* Pexc  = Pbase + (size_t)c * FDP;
    const uint32_t* Pinc  = Pbase + (size_t)(c + 1) * FDP;
    const uint32_t* Ptot  = Pbase + (size_t)NC * FDP;

#pragma unroll
    for (int r = 0; r < 8; r++) {
        int slot = t + r * 512;
        int row  = slot >> 5;
        int p4   = (slot & 31) << 2;
        size_t go = (size_t)row * FPP + p4;
        uint4 ev = *(const uint4*)(Pexc + go);
        B1[row * KP128 + p4]     = ev.x;
        B1[row * KP128 + p4 + 1] = ev.y;
        B1[row * KP128 + p4 + 2] = ev.z;
        B1[row * KP128 + p4 + 3] = ev.w;
        uint4 iv = *(const uint4*)(Pinc + go);
        uint4 tv = *(const uint4*)(Ptot + go);
        B2[row * KP128 + p4]     = hsub2u(tv.x, iv.x);
        B2[row * KP128 + p4 + 1] = hsub2u(tv.y, iv.y);
        B2[row * KP128 + p4 + 2] = hsub2u(tv.z, iv.z);
        B2[row * KP128 + p4 + 3] = hsub2u(tv.w, iv.w);
    }
    __syncthreads();

    // ================= Stage 3: Q @ Wexc / Q @ Wsuf (K=256) =================
#pragma unroll 4
    for (int ks = 0; ks < 16; ks++) {
        int kb = ks * 8 + tig;
        uint32_t af[2][4];
#pragma unroll
        for (int mt = 0; mt < 2; mt++) {
            int row = wm * 32 + mt * 16 + g;
            af[mt][0] = Qp[row * KP128 + kb];
            af[mt][1] = Qp[(row + 8) * KP128 + kb];
            af[mt][2] = Qp[row * KP128 + kb + 4];
            af[mt][3] = Qp[(row + 8) * KP128 + kb + 4];
        }
        uint32_t b1f[4][2], b2f[4][2];
#pragma unroll
        for (int nt = 0; nt < 4; nt++) {
            int col = wn * 32 + nt * 8 + g;
            b1f[nt][0] = B1[col * KP128 + kb];
            b1f[nt][1] = B1[col * KP128 + kb + 4];
            b2f[nt][0] = B2[col * KP128 + kb];
            b2f[nt][1] = B2[col * KP128 + kb + 4];
        }
#pragma unroll
        for (int mt = 0; mt < 2; mt++)
#pragma unroll
            for (int nt = 0; nt < 4; nt++) {
                mma16(acc1[mt][nt], af[mt], b1f[nt]);
                mma16(acc2[mt][nt], af[mt], b2f[nt]);
            }
    }

    // ================= Epilogue =================
#pragma unroll
    for (int mt = 0; mt < 2; mt++) {
#pragma unroll
        for (int nt = 0; nt < 4; nt++) {
            int n0  = wm * 32 + mt * 16 + g;
            int d0  = wn * 32 + nt * 8 + tig * 2;
            int posA = c * CHK + n0;
            int posB = posA + 8;
            float s1a = 1.f / (float)(posA + 1);
            float s2a = 1.f / (float)(SEQ - posA);
            float s1b = 1.f / (float)(posB + 1);
            float s2b = 1.f / (float)(SEQ - posB);
            float2 oA, oB;
            oA.x = acc1[mt][nt][0] * s1a + acc2[mt][nt][0] * s2a;
            oA.y = acc1[mt][nt][1] * s1a + acc2[mt][nt][1] * s2a;
            oB.x = acc1[mt][nt][2] * s1b + acc2[mt][nt][2] * s2b;
            oB.y = acc1[mt][nt][3] * s1b + acc2[mt][nt][3] * s2b;
            *(float2*)(out + (size_t)(pos0 + n0) * DD + d0)     = oA;
            *(float2*)(out + (size_t)(pos0 + n0 + 8) * DD + d0) = oB;
        }
    }
}

// ---------------------------------------------------------------------------
extern "C" void kernel_launch(void* const* d_in, const int* in_sizes, int n_in,
                              void* d_out, int out_size)
{
    (void)out_size;
    int big[3] = {0, 1, 2}; int nbig = 0;
    int iw1 = -1, iw2 = -1, ibias[2] = {-1, -1}; int nb = 0;
    for (int i = 0; i < n_in; i++) {
        long long s = in_sizes[i];
        if ((s == 12582912LL || s == 50331648LL) && nbig < 3) big[nbig++] = i;
        else if (s == 32768LL  || s == 131072LL) iw1 = i;
        else if (s == 65536LL  || s == 262144LL) iw2 = i;
        else if ((s == 256LL   || s == 1024LL) && nb < 2) ibias[nb++] = i;
    }
    if (nbig != 3 || iw1 < 0 || iw2 < 0 || nb != 2) {
        big[0] = 0; big[1] = 1; big[2] = 2;
        iw1 = 3; ibias[0] = 4; iw2 = 5; ibias[1] = 6;
    }
    const float *q, *k;
    if (big[0] == 0) {
        q = (const float*)d_in[big[0]];
        k = (const float*)d_in[big[1]];
    } else {
        k = (const float*)d_in[big[0]];
        q = (const float*)d_in[big[1]];
    }
    const float* v  = (const float*)d_in[big[2]];
    const float* w1 = (const float*)d_in[iw1];
    const float* b1 = (const float*)d_in[ibias[0]];
    const float* w2 = (const float*)d_in[iw2];
    const float* b2 = (const float*)d_in[ibias[1]];
    float* out = (float*)d_out;

    uint32_t *hq, *hk, *qphi, *kphi, *P;
    float *w1t, *w2t;
    cudaGetSymbolAddress((void**)&hq,   g_hq);
    cudaGetSymbolAddress((void**)&hk,   g_hk);
    cudaGetSymbolAddress((void**)&qphi, g_qphi);
    cudaGetSymbolAddress((void**)&kphi, g_kphi);
    cudaGetSymbolAddress((void**)&P,    g_P);
    cudaGetSymbolAddress((void**)&w1t,  g_w1t);
    cudaGetSymbolAddress((void**)&w2t,  g_w2t);

    cudaFuncSetAttribute(phiA,
                         cudaFuncAttributeMaxDynamicSharedMemorySize, PA_BYTES);
    cudaFuncSetAttribute(phiB,
                         cudaFuncAttributeMaxDynamicSharedMemorySize, PB_BYTES);
    cudaFuncSetAttribute(chunk_state_fp16,
                         cudaFuncAttributeMaxDynamicSharedMemorySize, CS_BYTES);
    cudaFuncSetAttribute(output_tc,
                         cudaFuncAttributeMaxDynamicSharedMemorySize, OSM_BYTES);

    transpose_kernel<<<(DD*FF + 255)/256, 256>>>(w1, w1t, DD, FF);
    transpose_kernel<<<(FF*FF + 255)/256, 256>>>(w2, w2t, FF, FF);

    phiA<<<2 * NBLK, 256, PA_BYTES>>>(q, k, w1t, b1, hq, hk);
    phiB<<<2 * NBLK, 256, PB_BYTES>>>(hq, hk, w2t, b2, qphi, kphi);

    chunk_state_fp16<<<dim3(BH * NC, 2), 256, CS_BYTES>>>(kphi, v, P);
    prefix_kernel<<<dim3(FDP / 512, BH), 256>>>(P);

    output_tc<<<BH * NC, 512, OSM_BYTES>>>(qphi, kphi, v, P, out);
}